// round 1
// baseline (speedup 1.0000x reference)
#include <cuda_runtime.h>
#include <math.h>

#define BB  2
#define SS  2048
#define HH  32
#define DHH 128
#define NQ  4096   // H*DH
#define BSZ 4096   // B*S
#define TQ  128
#define TK  64

// Scratch (sanctioned __device__ globals; ~136 MB total)
__device__ float g_qproj[BB*SS*NQ];    // [B][Srow][4096]
__device__ float g_kproj[BB*SS*DHH];   // [B][S][128]
__device__ float g_vproj[BB*SS*DHH];
__device__ float g_attn [BB*SS*NQ];    // o2 layout: [B][S][h*128+d]

// ---------------------------------------------------------------------------
// Generic tiled GEMM + bias: C[M,N] = A[M,K] @ W[K,N] + bias[N]
// BM=64, BN=64, BK=32, 256 threads, 4x4 micro-tile. M%64==0, N%64==0, K%32==0.
// ---------------------------------------------------------------------------
__global__ __launch_bounds__(256) void gemm_bias(
    const float* __restrict__ A, const float* __restrict__ W,
    const float* __restrict__ bias, float* __restrict__ C,
    int M, int N, int K)
{
    __shared__ float Ast[32][65];   // [kk][r]  (transposed A tile)
    __shared__ float Ws [32][65];   // [kk][c]

    const int tx = threadIdx.x & 15;
    const int ty = threadIdx.x >> 4;
    const int n0 = blockIdx.x * 64;
    const int m0 = blockIdx.y * 64;

    float acc[4][4] = {};

    for (int k0 = 0; k0 < K; k0 += 32) {
        for (int idx = threadIdx.x; idx < 64 * 32; idx += 256) {
            int r = idx >> 5, kk = idx & 31;
            Ast[kk][r] = A[(size_t)(m0 + r) * K + k0 + kk];
        }
        for (int idx = threadIdx.x; idx < 32 * 64; idx += 256) {
            int kk = idx >> 6, c = idx & 63;
            Ws[kk][c] = W[(size_t)(k0 + kk) * N + n0 + c];
        }
        __syncthreads();

        #pragma unroll
        for (int kk = 0; kk < 32; ++kk) {
            float a[4], w[4];
            #pragma unroll
            for (int i = 0; i < 4; ++i) a[i] = Ast[kk][ty * 4 + i];
            #pragma unroll
            for (int j = 0; j < 4; ++j) w[j] = Ws[kk][tx * 4 + j];
            #pragma unroll
            for (int i = 0; i < 4; ++i)
                #pragma unroll
                for (int j = 0; j < 4; ++j)
                    acc[i][j] += a[i] * w[j];
        }
        __syncthreads();
    }

    #pragma unroll
    for (int i = 0; i < 4; ++i) {
        int r = m0 + ty * 4 + i;
        #pragma unroll
        for (int j = 0; j < 4; ++j) {
            int c = n0 + tx * 4 + j;
            C[(size_t)r * N + c] = acc[i][j] + bias[c];
        }
    }
}

// ---------------------------------------------------------------------------
// Flash attention, fp32. Block = (qtile of 128 queries) x (head) x (batch).
// 256 threads as 16x16; scores micro 8x4, AV micro 8x8.
// q[b,h,i,d] = qproj[b][h*64 + i/32][(i%32)*128 + d]  -> a 128-query tile is
// 16384 CONTIGUOUS floats at qproj + (b*S + h*64 + 4*qt)*4096, linear l*128+d.
// ---------------------------------------------------------------------------
struct AttnSmem {
    float Qs[DHH][TQ + 4];   // [128][132] k-major (d, then query)
    float Ks[DHH][TK + 4];   // [128][68]  k-major (d, then key)
    float Vs[TK][DHH];       // [64][128]  row-major
    float Ps[TQ][TK + 4];    // [128][68]  probabilities
};

__global__ __launch_bounds__(256) void attn_kernel(
    const float* __restrict__ qproj, const float* __restrict__ kproj,
    const float* __restrict__ vproj, float* __restrict__ o2)
{
    extern __shared__ char smraw[];
    AttnSmem* sm = reinterpret_cast<AttnSmem*>(smraw);

    const int qt = blockIdx.x;
    const int h  = blockIdx.y;
    const int b  = blockIdx.z;
    const int tid = threadIdx.x;
    const int tx = tid & 15;        // 16 cols of threads
    const int ty = tid >> 4;        // 16 rows of threads
    const float scale = 0.08838834764831845f;  // 1/sqrt(128)

    // Load Q tile (contiguous!), pre-scaled, stored d-major.
    const float* qsrc = qproj + ((size_t)b * SS + (size_t)h * 64 + (size_t)qt * 4) * NQ;
    for (int idx = tid; idx < TQ * DHH; idx += 256) {
        int l = idx >> 7, d = idx & 127;
        sm->Qs[d][l] = qsrc[idx] * scale;
    }

    float m[8], lsum[8], o[8][8];
    #pragma unroll
    for (int i = 0; i < 8; ++i) {
        m[i] = -1e30f; lsum[i] = 0.f;
        #pragma unroll
        for (int j = 0; j < 8; ++j) o[i][j] = 0.f;
    }

    const float* kbase = kproj + (size_t)b * SS * DHH;
    const float* vbase = vproj + (size_t)b * SS * DHH;

    for (int kt = 0; kt < SS / TK; ++kt) {
        const float* ksrc = kbase + (size_t)kt * TK * DHH;
        const float* vsrc = vbase + (size_t)kt * TK * DHH;
        for (int idx = tid; idx < TK * DHH; idx += 256) {
            int c = idx >> 7, d = idx & 127;
            sm->Ks[d][c] = ksrc[idx];
            sm->Vs[c][d] = vsrc[idx];
        }
        __syncthreads();   // Ks/Vs (and, on kt==0, Qs) ready

        // --- scores: s[8][4] = Q(8 rows) . K^T(4 cols) ---
        float s[8][4] = {};
        #pragma unroll 4
        for (int k = 0; k < DHH; ++k) {
            float4 qa = *reinterpret_cast<const float4*>(&sm->Qs[k][ty * 8]);
            float4 qb = *reinterpret_cast<const float4*>(&sm->Qs[k][ty * 8 + 4]);
            float4 kf = *reinterpret_cast<const float4*>(&sm->Ks[k][tx * 4]);
            float qv[8] = {qa.x, qa.y, qa.z, qa.w, qb.x, qb.y, qb.z, qb.w};
            float kv[4] = {kf.x, kf.y, kf.z, kf.w};
            #pragma unroll
            for (int i = 0; i < 8; ++i)
                #pragma unroll
                for (int j = 0; j < 4; ++j)
                    s[i][j] += qv[i] * kv[j];
        }

        // --- online softmax update (row = ty*8+i, owned by 16 tx lanes) ---
        #pragma unroll
        for (int i = 0; i < 8; ++i) {
            float mt = fmaxf(fmaxf(s[i][0], s[i][1]), fmaxf(s[i][2], s[i][3]));
            #pragma unroll
            for (int off = 1; off < 16; off <<= 1)
                mt = fmaxf(mt, __shfl_xor_sync(0xffffffffu, mt, off));
            float mnew  = fmaxf(m[i], mt);
            float alpha = __expf(m[i] - mnew);
            m[i] = mnew;
            float rs = 0.f;
            #pragma unroll
            for (int j = 0; j < 4; ++j) {
                float p = __expf(s[i][j] - mnew);
                s[i][j] = p;
                rs += p;
            }
            #pragma unroll
            for (int off = 1; off < 16; off <<= 1)
                rs += __shfl_xor_sync(0xffffffffu, rs, off);
            lsum[i] = lsum[i] * alpha + rs;
            #pragma unroll
            for (int j = 0; j < 8; ++j) o[i][j] *= alpha;
            *reinterpret_cast<float4*>(&sm->Ps[ty * 8 + i][tx * 4]) =
                make_float4(s[i][0], s[i][1], s[i][2], s[i][3]);
        }
        __syncwarp();   // P rows are produced & consumed within the same warp

        // --- AV: o[i][j] += sum_c P[row][c] * V[c][tx*8+j] ---
        #pragma unroll 2
        for (int c = 0; c < TK; ++c) {
            float pr[8];
            #pragma unroll
            for (int i = 0; i < 8; ++i) pr[i] = sm->Ps[ty * 8 + i][c];
            float4 va = *reinterpret_cast<const float4*>(&sm->Vs[c][tx * 8]);
            float4 vb = *reinterpret_cast<const float4*>(&sm->Vs[c][tx * 8 + 4]);
            float vv[8] = {va.x, va.y, va.z, va.w, vb.x, vb.y, vb.z, vb.w};
            #pragma unroll
            for (int i = 0; i < 8; ++i)
                #pragma unroll
                for (int j = 0; j < 8; ++j)
                    o[i][j] += pr[i] * vv[j];
        }
        __syncthreads();  // protect Ks/Vs before next tile's load
    }

    // Write o2[b][s][h*128+d] = out/l  (transposed-merge layout for O proj)
    #pragma unroll
    for (int i = 0; i < 8; ++i) {
        float inv = 1.0f / lsum[i];
        size_t row = (size_t)b * SS + (size_t)qt * TQ + ty * 8 + i;
        float* dst = o2 + row * NQ + h * DHH + tx * 8;
        *reinterpret_cast<float4*>(dst) =
            make_float4(o[i][0] * inv, o[i][1] * inv, o[i][2] * inv, o[i][3] * inv);
        *reinterpret_cast<float4*>(dst + 4) =
            make_float4(o[i][4] * inv, o[i][5] * inv, o[i][6] * inv, o[i][7] * inv);
    }
}

// ---------------------------------------------------------------------------
extern "C" void kernel_launch(void* const* d_in, const int* in_sizes, int n_in,
                              void* d_out, int out_size)
{
    const float* query  = (const float*)d_in[0];
    const float* key    = (const float*)d_in[1];
    const float* values = (const float*)d_in[2];
    const float* W_q = (const float*)d_in[3];
    const float* b_q = (const float*)d_in[4];
    const float* W_k = (const float*)d_in[5];
    const float* b_k = (const float*)d_in[6];
    const float* W_v = (const float*)d_in[7];
    const float* b_v = (const float*)d_in[8];
    const float* W_o = (const float*)d_in[9];
    const float* b_o = (const float*)d_in[10];
    float* out = (float*)d_out;

    float *qp, *kp, *vp, *ap;
    cudaGetSymbolAddress((void**)&qp, g_qproj);
    cudaGetSymbolAddress((void**)&kp, g_kproj);
    cudaGetSymbolAddress((void**)&vp, g_vproj);
    cudaGetSymbolAddress((void**)&ap, g_attn);

    cudaFuncSetAttribute(attn_kernel, cudaFuncAttributeMaxDynamicSharedMemorySize,
                         (int)sizeof(AttnSmem));

    dim3 blk(256);
    // Projections
    gemm_bias<<<dim3(NQ / 64,  BSZ / 64), blk>>>(query,  W_q, b_q, qp, BSZ, NQ,  DHH);
    gemm_bias<<<dim3(DHH / 64, BSZ / 64), blk>>>(key,    W_k, b_k, kp, BSZ, DHH, DHH);
    gemm_bias<<<dim3(DHH / 64, BSZ / 64), blk>>>(values, W_v, b_v, vp, BSZ, DHH, DHH);
    // Attention
    attn_kernel<<<dim3(SS / TQ, HH, BB), blk, sizeof(AttnSmem)>>>(qp, kp, vp, ap);
    // Output projection
    gemm_bias<<<dim3(DHH / 64, BSZ / 64), blk>>>(ap, W_o, b_o, out, BSZ, DHH, NQ);
}

// round 2
// speedup vs baseline: 1.0538x; 1.0538x over previous
#include <cuda_runtime.h>
#include <math.h>

#define BB  2
#define SS  2048
#define HH  32
#define DHH 128
#define NQ  4096   // H*DH
#define BSZ 4096   // B*S
#define TQ  128
#define TK  64

// Scratch (sanctioned __device__ globals; ~136 MB total)
__device__ float g_qproj[BB*SS*NQ];    // [B][Srow][4096]
__device__ float g_kproj[BB*SS*DHH];   // [B][S][128]
__device__ float g_vproj[BB*SS*DHH];
__device__ float g_attn [BB*SS*NQ];    // o2 layout: [B][S][h*128+d]

// ---------------------------------------------------------------------------
// Generic tiled GEMM + bias: C[M,N] = A[M,K] @ W[K,N] + bias[N]
// BM=64, BN=64, BK=32, 256 threads, 4x4 micro-tile. M%64==0, N%64==0, K%32==0.
// ---------------------------------------------------------------------------
__global__ __launch_bounds__(256) void gemm_bias(
    const float* __restrict__ A, const float* __restrict__ W,
    const float* __restrict__ bias, float* __restrict__ C,
    int M, int N, int K)
{
    __shared__ float Ast[32][65];   // [kk][r]  (transposed A tile)
    __shared__ float Ws [32][65];   // [kk][c]

    const int tx = threadIdx.x & 15;
    const int ty = threadIdx.x >> 4;
    const int n0 = blockIdx.x * 64;
    const int m0 = blockIdx.y * 64;

    float acc[4][4] = {};

    for (int k0 = 0; k0 < K; k0 += 32) {
        for (int idx = threadIdx.x; idx < 64 * 32; idx += 256) {
            int r = idx >> 5, kk = idx & 31;
            Ast[kk][r] = A[(size_t)(m0 + r) * K + k0 + kk];
        }
        for (int idx = threadIdx.x; idx < 32 * 64; idx += 256) {
            int kk = idx >> 6, c = idx & 63;
            Ws[kk][c] = W[(size_t)(k0 + kk) * N + n0 + c];
        }
        __syncthreads();

        #pragma unroll
        for (int kk = 0; kk < 32; ++kk) {
            float a[4], w[4];
            #pragma unroll
            for (int i = 0; i < 4; ++i) a[i] = Ast[kk][ty * 4 + i];
            #pragma unroll
            for (int j = 0; j < 4; ++j) w[j] = Ws[kk][tx * 4 + j];
            #pragma unroll
            for (int i = 0; i < 4; ++i)
                #pragma unroll
                for (int j = 0; j < 4; ++j)
                    acc[i][j] += a[i] * w[j];
        }
        __syncthreads();
    }

    #pragma unroll
    for (int i = 0; i < 4; ++i) {
        int r = m0 + ty * 4 + i;
        #pragma unroll
        for (int j = 0; j < 4; ++j) {
            int c = n0 + tx * 4 + j;
            C[(size_t)r * N + c] = acc[i][j] + bias[c];
        }
    }
}

// ---------------------------------------------------------------------------
// Flash attention, fp32. Block = (qtile of 128 queries) x (head) x (batch).
// 256 threads as 16x16; scores micro 8x4, AV micro 8x8.
// q[b,h,i,d] = qproj[b][h*64 + i/32][(i%32)*128 + d]  -> a 128-query tile is
// 16384 CONTIGUOUS floats at qproj + (b*S + h*64 + 4*qt)*4096, linear l*128+d.
// ---------------------------------------------------------------------------
struct AttnSmem {
    float Qs[DHH][TQ + 4];   // [128][132] k-major (d, then query)
    float Ks[DHH][TK + 4];   // [128][68]  k-major (d, then key)
    float Vs[TK][DHH];       // [64][128]  row-major
    float Ps[TQ][TK + 4];    // [128][68]  probabilities
};

__global__ __launch_bounds__(256) void attn_kernel(
    const float* __restrict__ qproj, const float* __restrict__ kproj,
    const float* __restrict__ vproj, float* __restrict__ o2)
{
    extern __shared__ char smraw[];
    AttnSmem* sm = reinterpret_cast<AttnSmem*>(smraw);

    const int qt = blockIdx.x;
    const int h  = blockIdx.y;
    const int b  = blockIdx.z;
    const int tid = threadIdx.x;
    const int tx = tid & 15;        // 16 cols of threads
    const int ty = tid >> 4;        // 16 rows of threads
    const float scale = 0.08838834764831845f;  // 1/sqrt(128)

    // Load Q tile (contiguous!), pre-scaled, stored d-major.
    const float* qsrc = qproj + ((size_t)b * SS + (size_t)h * 64 + (size_t)qt * 4) * NQ;
    for (int idx = tid; idx < TQ * DHH; idx += 256) {
        int l = idx >> 7, d = idx & 127;
        sm->Qs[d][l] = qsrc[idx] * scale;
    }

    float m[8], lsum[8], o[8][8];
    #pragma unroll
    for (int i = 0; i < 8; ++i) {
        m[i] = -1e30f; lsum[i] = 0.f;
        #pragma unroll
        for (int j = 0; j < 8; ++j) o[i][j] = 0.f;
    }

    const float* kbase = kproj + (size_t)b * SS * DHH;
    const float* vbase = vproj + (size_t)b * SS * DHH;

    for (int kt = 0; kt < SS / TK; ++kt) {
        const float* ksrc = kbase + (size_t)kt * TK * DHH;
        const float* vsrc = vbase + (size_t)kt * TK * DHH;
        for (int idx = tid; idx < TK * DHH; idx += 256) {
            int c = idx >> 7, d = idx & 127;
            sm->Ks[d][c] = ksrc[idx];
            sm->Vs[c][d] = vsrc[idx];
        }
        __syncthreads();   // Ks/Vs (and, on kt==0, Qs) ready

        // --- scores: s[8][4] = Q(8 rows) . K^T(4 cols) ---
        float s[8][4] = {};
        #pragma unroll 4
        for (int k = 0; k < DHH; ++k) {
            float4 qa = *reinterpret_cast<const float4*>(&sm->Qs[k][ty * 8]);
            float4 qb = *reinterpret_cast<const float4*>(&sm->Qs[k][ty * 8 + 4]);
            float4 kf = *reinterpret_cast<const float4*>(&sm->Ks[k][tx * 4]);
            float qv[8] = {qa.x, qa.y, qa.z, qa.w, qb.x, qb.y, qb.z, qb.w};
            float kv[4] = {kf.x, kf.y, kf.z, kf.w};
            #pragma unroll
            for (int i = 0; i < 8; ++i)
                #pragma unroll
                for (int j = 0; j < 4; ++j)
                    s[i][j] += qv[i] * kv[j];
        }

        // --- online softmax update (row = ty*8+i, owned by 16 tx lanes) ---
        #pragma unroll
        for (int i = 0; i < 8; ++i) {
            float mt = fmaxf(fmaxf(s[i][0], s[i][1]), fmaxf(s[i][2], s[i][3]));
            #pragma unroll
            for (int off = 1; off < 16; off <<= 1)
                mt = fmaxf(mt, __shfl_xor_sync(0xffffffffu, mt, off));
            float mnew  = fmaxf(m[i], mt);
            float alpha = __expf(m[i] - mnew);
            m[i] = mnew;
            float rs = 0.f;
            #pragma unroll
            for (int j = 0; j < 4; ++j) {
                float p = __expf(s[i][j] - mnew);
                s[i][j] = p;
                rs += p;
            }
            #pragma unroll
            for (int off = 1; off < 16; off <<= 1)
                rs += __shfl_xor_sync(0xffffffffu, rs, off);
            lsum[i] = lsum[i] * alpha + rs;
            #pragma unroll
            for (int j = 0; j < 8; ++j) o[i][j] *= alpha;
            *reinterpret_cast<float4*>(&sm->Ps[ty * 8 + i][tx * 4]) =
                make_float4(s[i][0], s[i][1], s[i][2], s[i][3]);
        }
        __syncwarp();   // P rows are produced & consumed within the same warp

        // --- AV: o[i][j] += sum_c P[row][c] * V[c][tx*8+j] ---
        #pragma unroll 2
        for (int c = 0; c < TK; ++c) {
            float pr[8];
            #pragma unroll
            for (int i = 0; i < 8; ++i) pr[i] = sm->Ps[ty * 8 + i][c];
            float4 va = *reinterpret_cast<const float4*>(&sm->Vs[c][tx * 8]);
            float4 vb = *reinterpret_cast<const float4*>(&sm->Vs[c][tx * 8 + 4]);
            float vv[8] = {va.x, va.y, va.z, va.w, vb.x, vb.y, vb.z, vb.w};
            #pragma unroll
            for (int i = 0; i < 8; ++i)
                #pragma unroll
                for (int j = 0; j < 8; ++j)
                    o[i][j] += pr[i] * vv[j];
        }
        __syncthreads();  // protect Ks/Vs before next tile's load
    }

    // Write o2[b][s][h*128+d] = out/l  (transposed-merge layout for O proj)
    #pragma unroll
    for (int i = 0; i < 8; ++i) {
        float inv = 1.0f / lsum[i];
        size_t row = (size_t)b * SS + (size_t)qt * TQ + ty * 8 + i;
        float* dst = o2 + row * NQ + h * DHH + tx * 8;
        *reinterpret_cast<float4*>(dst) =
            make_float4(o[i][0] * inv, o[i][1] * inv, o[i][2] * inv, o[i][3] * inv);
        *reinterpret_cast<float4*>(dst + 4) =
            make_float4(o[i][4] * inv, o[i][5] * inv, o[i][6] * inv, o[i][7] * inv);
    }
}

// ---------------------------------------------------------------------------
extern "C" void kernel_launch(void* const* d_in, const int* in_sizes, int n_in,
                              void* d_out, int out_size)
{
    const float* query  = (const float*)d_in[0];
    const float* key    = (const float*)d_in[1];
    const float* values = (const float*)d_in[2];
    const float* W_q = (const float*)d_in[3];
    const float* b_q = (const float*)d_in[4];
    const float* W_k = (const float*)d_in[5];
    const float* b_k = (const float*)d_in[6];
    const float* W_v = (const float*)d_in[7];
    const float* b_v = (const float*)d_in[8];
    const float* W_o = (const float*)d_in[9];
    const float* b_o = (const float*)d_in[10];
    float* out = (float*)d_out;

    float *qp, *kp, *vp, *ap;
    cudaGetSymbolAddress((void**)&qp, g_qproj);
    cudaGetSymbolAddress((void**)&kp, g_kproj);
    cudaGetSymbolAddress((void**)&vp, g_vproj);
    cudaGetSymbolAddress((void**)&ap, g_attn);

    cudaFuncSetAttribute(attn_kernel, cudaFuncAttributeMaxDynamicSharedMemorySize,
                         (int)sizeof(AttnSmem));

    dim3 blk(256);
    // Projections
    gemm_bias<<<dim3(NQ / 64,  BSZ / 64), blk>>>(query,  W_q, b_q, qp, BSZ, NQ,  DHH);
    gemm_bias<<<dim3(DHH / 64, BSZ / 64), blk>>>(key,    W_k, b_k, kp, BSZ, DHH, DHH);
    gemm_bias<<<dim3(DHH / 64, BSZ / 64), blk>>>(values, W_v, b_v, vp, BSZ, DHH, DHH);
    // Attention
    attn_kernel<<<dim3(SS / TQ, HH, BB), blk, sizeof(AttnSmem)>>>(qp, kp, vp, ap);
    // Output projection
    gemm_bias<<<dim3(DHH / 64, BSZ / 64), blk>>>(ap, W_o, b_o, out, BSZ, DHH, NQ);
}

// round 3
// speedup vs baseline: 1.0544x; 1.0006x over previous
#include <cuda_runtime.h>
#include <math.h>

#define BB  2
#define SS  2048
#define HH  32
#define DHH 128
#define NQ  4096   // H*DH
#define BSZ 4096   // B*S
#define TQ  128
#define TK  64

// Scratch (sanctioned __device__ globals; ~136 MB total)
__device__ float g_qproj[BB*SS*NQ];    // [B][Srow][4096]
__device__ float g_kproj[BB*SS*DHH];   // [B][S][128]
__device__ float g_vproj[BB*SS*DHH];
__device__ float g_attn [BB*SS*NQ];    // o2 layout: [B][S][h*128+d]

// ---------------------------------------------------------------------------
// Generic tiled GEMM + bias: C[M,N] = A[M,K] @ W[K,N] + bias[N]
// BM=64, BN=64, BK=32, 256 threads, 4x4 micro-tile. M%64==0, N%64==0, K%32==0.
// ---------------------------------------------------------------------------
__global__ __launch_bounds__(256) void gemm_bias(
    const float* __restrict__ A, const float* __restrict__ W,
    const float* __restrict__ bias, float* __restrict__ C,
    int M, int N, int K)
{
    __shared__ float Ast[32][65];   // [kk][r]  (transposed A tile)
    __shared__ float Ws [32][65];   // [kk][c]

    const int tx = threadIdx.x & 15;
    const int ty = threadIdx.x >> 4;
    const int n0 = blockIdx.x * 64;
    const int m0 = blockIdx.y * 64;

    float acc[4][4] = {};

    for (int k0 = 0; k0 < K; k0 += 32) {
        for (int idx = threadIdx.x; idx < 64 * 32; idx += 256) {
            int r = idx >> 5, kk = idx & 31;
            Ast[kk][r] = A[(size_t)(m0 + r) * K + k0 + kk];
        }
        for (int idx = threadIdx.x; idx < 32 * 64; idx += 256) {
            int kk = idx >> 6, c = idx & 63;
            Ws[kk][c] = W[(size_t)(k0 + kk) * N + n0 + c];
        }
        __syncthreads();

        #pragma unroll
        for (int kk = 0; kk < 32; ++kk) {
            float a[4], w[4];
            #pragma unroll
            for (int i = 0; i < 4; ++i) a[i] = Ast[kk][ty * 4 + i];
            #pragma unroll
            for (int j = 0; j < 4; ++j) w[j] = Ws[kk][tx * 4 + j];
            #pragma unroll
            for (int i = 0; i < 4; ++i)
                #pragma unroll
                for (int j = 0; j < 4; ++j)
                    acc[i][j] += a[i] * w[j];
        }
        __syncthreads();
    }

    #pragma unroll
    for (int i = 0; i < 4; ++i) {
        int r = m0 + ty * 4 + i;
        #pragma unroll
        for (int j = 0; j < 4; ++j) {
            int c = n0 + tx * 4 + j;
            C[(size_t)r * N + c] = acc[i][j] + bias[c];
        }
    }
}

// ---------------------------------------------------------------------------
// Flash attention, fp32. Block = (qtile of 128 queries) x (head) x (batch).
// 256 threads as 16x16; scores micro 8x4, AV micro 8x8.
// q[b,h,i,d] = qproj[b][h*64 + i/32][(i%32)*128 + d]  -> a 128-query tile is
// 16384 CONTIGUOUS floats at qproj + (b*S + h*64 + 4*qt)*4096, linear l*128+d.
// ---------------------------------------------------------------------------
struct AttnSmem {
    float Qs[DHH][TQ + 4];   // [128][132] k-major (d, then query)
    float Ks[DHH][TK + 4];   // [128][68]  k-major (d, then key)
    float Vs[TK][DHH];       // [64][128]  row-major
    float Ps[TQ][TK + 4];    // [128][68]  probabilities
};

__global__ __launch_bounds__(256) void attn_kernel(
    const float* __restrict__ qproj, const float* __restrict__ kproj,
    const float* __restrict__ vproj, float* __restrict__ o2)
{
    extern __shared__ char smraw[];
    AttnSmem* sm = reinterpret_cast<AttnSmem*>(smraw);

    const int qt = blockIdx.x;
    const int h  = blockIdx.y;
    const int b  = blockIdx.z;
    const int tid = threadIdx.x;
    const int tx = tid & 15;        // 16 cols of threads
    const int ty = tid >> 4;        // 16 rows of threads
    const float scale = 0.08838834764831845f;  // 1/sqrt(128)

    // Load Q tile (contiguous!), pre-scaled, stored d-major.
    const float* qsrc = qproj + ((size_t)b * SS + (size_t)h * 64 + (size_t)qt * 4) * NQ;
    for (int idx = tid; idx < TQ * DHH; idx += 256) {
        int l = idx >> 7, d = idx & 127;
        sm->Qs[d][l] = qsrc[idx] * scale;
    }

    float m[8], lsum[8], o[8][8];
    #pragma unroll
    for (int i = 0; i < 8; ++i) {
        m[i] = -1e30f; lsum[i] = 0.f;
        #pragma unroll
        for (int j = 0; j < 8; ++j) o[i][j] = 0.f;
    }

    const float* kbase = kproj + (size_t)b * SS * DHH;
    const float* vbase = vproj + (size_t)b * SS * DHH;

    for (int kt = 0; kt < SS / TK; ++kt) {
        const float* ksrc = kbase + (size_t)kt * TK * DHH;
        const float* vsrc = vbase + (size_t)kt * TK * DHH;
        for (int idx = tid; idx < TK * DHH; idx += 256) {
            int c = idx >> 7, d = idx & 127;
            sm->Ks[d][c] = ksrc[idx];
            sm->Vs[c][d] = vsrc[idx];
        }
        __syncthreads();   // Ks/Vs (and, on kt==0, Qs) ready

        // --- scores: s[8][4] = Q(8 rows) . K^T(4 cols) ---
        float s[8][4] = {};
        #pragma unroll 4
        for (int k = 0; k < DHH; ++k) {
            float4 qa = *reinterpret_cast<const float4*>(&sm->Qs[k][ty * 8]);
            float4 qb = *reinterpret_cast<const float4*>(&sm->Qs[k][ty * 8 + 4]);
            float4 kf = *reinterpret_cast<const float4*>(&sm->Ks[k][tx * 4]);
            float qv[8] = {qa.x, qa.y, qa.z, qa.w, qb.x, qb.y, qb.z, qb.w};
            float kv[4] = {kf.x, kf.y, kf.z, kf.w};
            #pragma unroll
            for (int i = 0; i < 8; ++i)
                #pragma unroll
                for (int j = 0; j < 4; ++j)
                    s[i][j] += qv[i] * kv[j];
        }

        // --- online softmax update (row = ty*8+i, owned by 16 tx lanes) ---
        #pragma unroll
        for (int i = 0; i < 8; ++i) {
            float mt = fmaxf(fmaxf(s[i][0], s[i][1]), fmaxf(s[i][2], s[i][3]));
            #pragma unroll
            for (int off = 1; off < 16; off <<= 1)
                mt = fmaxf(mt, __shfl_xor_sync(0xffffffffu, mt, off));
            float mnew  = fmaxf(m[i], mt);
            float alpha = __expf(m[i] - mnew);
            m[i] = mnew;
            float rs = 0.f;
            #pragma unroll
            for (int j = 0; j < 4; ++j) {
                float p = __expf(s[i][j] - mnew);
                s[i][j] = p;
                rs += p;
            }
            #pragma unroll
            for (int off = 1; off < 16; off <<= 1)
                rs += __shfl_xor_sync(0xffffffffu, rs, off);
            lsum[i] = lsum[i] * alpha + rs;
            #pragma unroll
            for (int j = 0; j < 8; ++j) o[i][j] *= alpha;
            *reinterpret_cast<float4*>(&sm->Ps[ty * 8 + i][tx * 4]) =
                make_float4(s[i][0], s[i][1], s[i][2], s[i][3]);
        }
        __syncwarp();   // P rows are produced & consumed within the same warp

        // --- AV: o[i][j] += sum_c P[row][c] * V[c][tx*8+j] ---
        #pragma unroll 2
        for (int c = 0; c < TK; ++c) {
            float pr[8];
            #pragma unroll
            for (int i = 0; i < 8; ++i) pr[i] = sm->Ps[ty * 8 + i][c];
            float4 va = *reinterpret_cast<const float4*>(&sm->Vs[c][tx * 8]);
            float4 vb = *reinterpret_cast<const float4*>(&sm->Vs[c][tx * 8 + 4]);
            float vv[8] = {va.x, va.y, va.z, va.w, vb.x, vb.y, vb.z, vb.w};
            #pragma unroll
            for (int i = 0; i < 8; ++i)
                #pragma unroll
                for (int j = 0; j < 8; ++j)
                    o[i][j] += pr[i] * vv[j];
        }
        __syncthreads();  // protect Ks/Vs before next tile's load
    }

    // Write o2[b][s][h*128+d] = out/l  (transposed-merge layout for O proj)
    #pragma unroll
    for (int i = 0; i < 8; ++i) {
        float inv = 1.0f / lsum[i];
        size_t row = (size_t)b * SS + (size_t)qt * TQ + ty * 8 + i;
        float* dst = o2 + row * NQ + h * DHH + tx * 8;
        *reinterpret_cast<float4*>(dst) =
            make_float4(o[i][0] * inv, o[i][1] * inv, o[i][2] * inv, o[i][3] * inv);
        *reinterpret_cast<float4*>(dst + 4) =
            make_float4(o[i][4] * inv, o[i][5] * inv, o[i][6] * inv, o[i][7] * inv);
    }
}

// ---------------------------------------------------------------------------
extern "C" void kernel_launch(void* const* d_in, const int* in_sizes, int n_in,
                              void* d_out, int out_size)
{
    const float* query  = (const float*)d_in[0];
    const float* key    = (const float*)d_in[1];
    const float* values = (const float*)d_in[2];
    const float* W_q = (const float*)d_in[3];
    const float* b_q = (const float*)d_in[4];
    const float* W_k = (const float*)d_in[5];
    const float* b_k = (const float*)d_in[6];
    const float* W_v = (const float*)d_in[7];
    const float* b_v = (const float*)d_in[8];
    const float* W_o = (const float*)d_in[9];
    const float* b_o = (const float*)d_in[10];
    float* out = (float*)d_out;

    float *qp, *kp, *vp, *ap;
    cudaGetSymbolAddress((void**)&qp, g_qproj);
    cudaGetSymbolAddress((void**)&kp, g_kproj);
    cudaGetSymbolAddress((void**)&vp, g_vproj);
    cudaGetSymbolAddress((void**)&ap, g_attn);

    cudaFuncSetAttribute(attn_kernel, cudaFuncAttributeMaxDynamicSharedMemorySize,
                         (int)sizeof(AttnSmem));

    dim3 blk(256);
    // Projections
    gemm_bias<<<dim3(NQ / 64,  BSZ / 64), blk>>>(query,  W_q, b_q, qp, BSZ, NQ,  DHH);
    gemm_bias<<<dim3(DHH / 64, BSZ / 64), blk>>>(key,    W_k, b_k, kp, BSZ, DHH, DHH);
    gemm_bias<<<dim3(DHH / 64, BSZ / 64), blk>>>(values, W_v, b_v, vp, BSZ, DHH, DHH);
    // Attention
    attn_kernel<<<dim3(SS / TQ, HH, BB), blk, sizeof(AttnSmem)>>>(qp, kp, vp, ap);
    // Output projection
    gemm_bias<<<dim3(DHH / 64, BSZ / 64), blk>>>(ap, W_o, b_o, out, BSZ, DHH, NQ);
}

// round 5
// speedup vs baseline: 4.2025x; 3.9855x over previous
#include <cuda_runtime.h>
#include <cuda_fp16.h>
#include <math.h>
#include <stdint.h>

#define BB 2
#define SS 2048
#define HH 32
#define DHH 128
#define NQ 4096
#define BSZ 4096
#define TQ 128
#define TK 64
#define NT 32

// -------- scratch (device globals; sanctioned) --------
__device__ float g_qproj[BSZ*NQ];
__device__ float g_kproj[BSZ*DHH];
__device__ float g_vproj[BSZ*DHH];
__device__ float g_attn [BSZ*NQ];
__device__ __half g_kh[BSZ*DHH];        // [b][s][d] fp16
__device__ __half g_vt[BB*DHH*SS];      // [b][d][s] fp16 (transposed)

// -------- async copy helpers --------
__device__ __forceinline__ uint32_t smem_u32(const void* p){
    uint32_t a;
    asm("{ .reg .u64 t; cvta.to.shared.u64 t, %1; cvt.u32.u64 %0, t; }" : "=r"(a) : "l"(p));
    return a;
}
__device__ __forceinline__ void cp16(uint32_t dst, const void* src){
    asm volatile("cp.async.cg.shared.global [%0], [%1], 16;" :: "r"(dst), "l"(src));
}
#define CP_COMMIT() asm volatile("cp.async.commit_group;" ::: "memory")
#define CP_WAIT1()  asm volatile("cp.async.wait_group 1;" ::: "memory")
#define CP_WAIT0()  asm volatile("cp.async.wait_group 0;" ::: "memory")

// -------- mma.sync m16n8k16 fp16 -> fp32 --------
__device__ __forceinline__ void mma16816(float* c, const uint32_t* a, const uint32_t* b){
    asm volatile("mma.sync.aligned.m16n8k16.row.col.f32.f16.f16.f32 "
        "{%0,%1,%2,%3}, {%4,%5,%6,%7}, {%8,%9}, {%0,%1,%2,%3};"
        : "+f"(c[0]), "+f"(c[1]), "+f"(c[2]), "+f"(c[3])
        : "r"(a[0]), "r"(a[1]), "r"(a[2]), "r"(a[3]), "r"(b[0]), "r"(b[1]));
}
__device__ __forceinline__ uint32_t packh2(float x, float y){
    __half2 h = __floats2half2_rn(x, y);
    return *reinterpret_cast<uint32_t*>(&h);
}

// smem tile geometry (bytes)
#define KROWB 272              // 64 rows  [key][d]: 128 halves + 8 pad
#define VROWB 144              // 128 rows [d][key]: 64 halves + 8 pad
#define KBYTES (64*KROWB)      // 17408
#define VBYTES (128*VROWB)     // 18432
#define BUF    (KBYTES+VBYTES) // 35840
#define SMEM_DYN (2*BUF)       // 71680

// -------- generic fp32 GEMM + bias (unchanged, proven) --------
__global__ __launch_bounds__(256) void gemm_bias(
    const float* __restrict__ A, const float* __restrict__ W,
    const float* __restrict__ bias, float* __restrict__ C,
    int M, int N, int K)
{
    __shared__ float Ast[32][65];
    __shared__ float Ws [32][65];
    const int tx = threadIdx.x & 15, ty = threadIdx.x >> 4;
    const int n0 = blockIdx.x * 64, m0 = blockIdx.y * 64;
    float acc[4][4] = {};
    for (int k0 = 0; k0 < K; k0 += 32) {
        for (int idx = threadIdx.x; idx < 64*32; idx += 256) {
            int r = idx >> 5, kk = idx & 31;
            Ast[kk][r] = A[(size_t)(m0 + r) * K + k0 + kk];
        }
        for (int idx = threadIdx.x; idx < 32*64; idx += 256) {
            int kk = idx >> 6, c = idx & 63;
            Ws[kk][c] = W[(size_t)(k0 + kk) * N + n0 + c];
        }
        __syncthreads();
        #pragma unroll
        for (int kk = 0; kk < 32; ++kk) {
            float a[4], w[4];
            #pragma unroll
            for (int i = 0; i < 4; ++i) a[i] = Ast[kk][ty*4+i];
            #pragma unroll
            for (int j = 0; j < 4; ++j) w[j] = Ws[kk][tx*4+j];
            #pragma unroll
            for (int i = 0; i < 4; ++i)
                #pragma unroll
                for (int j = 0; j < 4; ++j) acc[i][j] += a[i]*w[j];
        }
        __syncthreads();
    }
    #pragma unroll
    for (int i = 0; i < 4; ++i)
        #pragma unroll
        for (int j = 0; j < 4; ++j)
            C[(size_t)(m0+ty*4+i)*N + n0+tx*4+j] = acc[i][j] + bias[n0+tx*4+j];
}

// -------- converts --------
__global__ void conv_k(const float* __restrict__ in, __half* __restrict__ out, int n){
    int i = blockIdx.x * 256 + threadIdx.x;
    if (i < n) out[i] = __float2half_rn(in[i]);
}
__global__ void conv_vt(const float* __restrict__ v, __half* __restrict__ ot){
    int s = blockIdx.x * 64 + (threadIdx.x & 63);
    int d = blockIdx.y * 4 + (threadIdx.x >> 6);
    int b = blockIdx.z;
    float f = v[((size_t)b*SS + s)*DHH + d];
    ot[((size_t)b*DHH + d)*SS + s] = __float2half_rn(f);
}

// -------- tile loader: K[64x128] row-major + V^T[128x64] into smem --------
__device__ __forceinline__ void load_tile(uint32_t buf, int b, int kt,
    const __half* kh, const __half* vt, int tid)
{
    const __half* ks = kh + ((size_t)b*SS + (size_t)kt*TK) * DHH;
    #pragma unroll
    for (int t = 0; t < 4; ++t) {            // K: 1024 x 16B chunks
        int e = tid + t*256;
        int r = e >> 4, c = e & 15;
        cp16(buf + r*KROWB + c*16, ks + (size_t)r*DHH + c*8);
    }
    const __half* vs = vt + (size_t)b*DHH*SS + (size_t)kt*TK;
    #pragma unroll
    for (int t = 0; t < 4; ++t) {            // V: 1024 x 16B chunks
        int e = tid + t*256;
        int d = e >> 3, c = e & 7;
        cp16(buf + KBYTES + d*VROWB + c*16, vs + (size_t)d*SS + c*8);
    }
}

// -------- HMMA flash attention --------
__global__ __launch_bounds__(256) void attn_hmma(
    const float* __restrict__ qproj, const __half* __restrict__ kh,
    const __half* __restrict__ vt, float* __restrict__ o2)
{
    extern __shared__ __align__(16) char smraw[];
    const uint32_t smb = smem_u32(smraw);
    const int qt = blockIdx.x, h = blockIdx.y, b = blockIdx.z;
    const int tid = threadIdx.x, w = tid >> 5, lane = tid & 31;
    const int g = lane >> 2, q4 = lane & 3;

    // prologue: prefetch tile 0
    load_tile(smb, b, 0, kh, vt, tid);
    CP_COMMIT();

    // Q fragments (held in regs for the whole CTA lifetime), pre-scaled
    const float scl = 0.08838834764831845f;
    const float* qsrc = qproj + ((size_t)b*SS + (size_t)h*64 + (size_t)qt*4) * NQ;
    const int r0 = w*16 + g, r1 = r0 + 8;
    uint32_t aQ[8][4];
    #pragma unroll
    for (int ks = 0; ks < 8; ++ks) {
        int d0 = 16*ks + 2*q4;
        float2 f;
        f = *reinterpret_cast<const float2*>(qsrc + (size_t)r0*DHH + d0);
        aQ[ks][0] = packh2(f.x*scl, f.y*scl);
        f = *reinterpret_cast<const float2*>(qsrc + (size_t)r1*DHH + d0);
        aQ[ks][1] = packh2(f.x*scl, f.y*scl);
        f = *reinterpret_cast<const float2*>(qsrc + (size_t)r0*DHH + d0 + 8);
        aQ[ks][2] = packh2(f.x*scl, f.y*scl);
        f = *reinterpret_cast<const float2*>(qsrc + (size_t)r1*DHH + d0 + 8);
        aQ[ks][3] = packh2(f.x*scl, f.y*scl);
    }

    float o[16][4];
    #pragma unroll
    for (int n = 0; n < 16; ++n)
        #pragma unroll
        for (int i = 0; i < 4; ++i) o[n][i] = 0.f;
    float rs0 = 0.f, rs1 = 0.f;

    for (int kt = 0; kt < NT; ++kt) {
        if (kt + 1 < NT) {
            load_tile(smb + ((kt+1)&1)*BUF, b, kt+1, kh, vt, tid);
            CP_COMMIT();
            CP_WAIT1();
        } else {
            CP_WAIT0();
        }
        __syncthreads();

        const uint32_t Kb = smb + (kt&1)*BUF;
        const uint32_t Vb = Kb + KBYTES;

        // S = Q K^T  (8 n-tiles of 8 keys)
        float s[8][4];
        #pragma unroll
        for (int j = 0; j < 8; ++j)
            #pragma unroll
            for (int i = 0; i < 4; ++i) s[j][i] = 0.f;
        #pragma unroll
        for (int ks = 0; ks < 8; ++ks) {
            #pragma unroll
            for (int j = 0; j < 8; ++j) {
                uint32_t bb[2];
                uint32_t p = Kb + (8*j + g)*KROWB + (16*ks + 2*q4)*2;
                asm volatile("ld.shared.b32 %0, [%1];" : "=r"(bb[0]) : "r"(p));
                asm volatile("ld.shared.b32 %0, [%1];" : "=r"(bb[1]) : "r"(p + 16));
                mma16816(s[j], aQ[ks], bb);
            }
        }

        // exp + pack P fragments (register-only)
        uint32_t ph[4][4];
        #pragma unroll
        for (int j = 0; j < 8; ++j) {
            float p0 = __expf(s[j][0]);
            float p1 = __expf(s[j][1]);
            float p2 = __expf(s[j][2]);
            float p3 = __expf(s[j][3]);
            rs0 += p0 + p1;
            rs1 += p2 + p3;
            ph[j>>1][(j&1)*2]     = packh2(p0, p1);
            ph[j>>1][(j&1)*2 + 1] = packh2(p2, p3);
        }

        // O += P V  (16 n-tiles of 8 dims, 4 k-steps of 16 keys)
        #pragma unroll
        for (int ks = 0; ks < 4; ++ks) {
            #pragma unroll
            for (int n = 0; n < 16; ++n) {
                uint32_t bb[2];
                uint32_t p = Vb + (8*n + g)*VROWB + (16*ks + 2*q4)*2;
                asm volatile("ld.shared.b32 %0, [%1];" : "=r"(bb[0]) : "r"(p));
                asm volatile("ld.shared.b32 %0, [%1];" : "=r"(bb[1]) : "r"(p + 16));
                mma16816(o[n], ph[ks], bb);
            }
        }
        __syncthreads();
    }

    // row-sum reduction across the 4 lanes sharing a row
    rs0 += __shfl_xor_sync(0xffffffffu, rs0, 1);
    rs0 += __shfl_xor_sync(0xffffffffu, rs0, 2);
    rs1 += __shfl_xor_sync(0xffffffffu, rs1, 1);
    rs1 += __shfl_xor_sync(0xffffffffu, rs1, 2);
    const float inv0 = 1.0f / rs0, inv1 = 1.0f / rs1;

    // write o2[b][qt*128 + row][h*128 + d]
    float* dst0 = o2 + ((size_t)b*SS + (size_t)qt*TQ + r0) * NQ + (size_t)h * DHH;
    float* dst1 = o2 + ((size_t)b*SS + (size_t)qt*TQ + r1) * NQ + (size_t)h * DHH;
    #pragma unroll
    for (int n = 0; n < 16; ++n) {
        int c = 8*n + 2*q4;
        *reinterpret_cast<float2*>(dst0 + c) = make_float2(o[n][0]*inv0, o[n][1]*inv0);
        *reinterpret_cast<float2*>(dst1 + c) = make_float2(o[n][2]*inv1, o[n][3]*inv1);
    }
}

// ---------------------------------------------------------------------------
extern "C" void kernel_launch(void* const* d_in, const int* in_sizes, int n_in,
                              void* d_out, int out_size)
{
    const float* query  = (const float*)d_in[0];
    const float* key    = (const float*)d_in[1];
    const float* values = (const float*)d_in[2];
    const float* W_q = (const float*)d_in[3];
    const float* b_q = (const float*)d_in[4];
    const float* W_k = (const float*)d_in[5];
    const float* b_k = (const float*)d_in[6];
    const float* W_v = (const float*)d_in[7];
    const float* b_v = (const float*)d_in[8];
    const float* W_o = (const float*)d_in[9];
    const float* b_o = (const float*)d_in[10];
    float* out = (float*)d_out;

    float *qp, *kp, *vp, *ap;
    __half *khp, *vtp;
    cudaGetSymbolAddress((void**)&qp, g_qproj);
    cudaGetSymbolAddress((void**)&kp, g_kproj);
    cudaGetSymbolAddress((void**)&vp, g_vproj);
    cudaGetSymbolAddress((void**)&ap, g_attn);
    cudaGetSymbolAddress((void**)&khp, g_kh);
    cudaGetSymbolAddress((void**)&vtp, g_vt);

    cudaFuncSetAttribute(attn_hmma, cudaFuncAttributeMaxDynamicSharedMemorySize, SMEM_DYN);

    dim3 blk(256);
    gemm_bias<<<dim3(NQ/64,  BSZ/64), blk>>>(query,  W_q, b_q, qp, BSZ, NQ,  DHH);
    gemm_bias<<<dim3(DHH/64, BSZ/64), blk>>>(key,    W_k, b_k, kp, BSZ, DHH, DHH);
    gemm_bias<<<dim3(DHH/64, BSZ/64), blk>>>(values, W_v, b_v, vp, BSZ, DHH, DHH);

    conv_k <<<(BSZ*DHH + 255)/256, 256>>>(kp, khp, BSZ*DHH);
    conv_vt<<<dim3(SS/64, DHH/4, BB), 256>>>(vp, vtp);

    attn_hmma<<<dim3(SS/TQ, HH, BB), 256, SMEM_DYN>>>(qp, khp, vtp, ap);

    gemm_bias<<<dim3(DHH/64, BSZ/64), blk>>>(ap, W_o, b_o, out, BSZ, DHH, NQ);
}

// round 6
// speedup vs baseline: 7.7536x; 1.8450x over previous
#include <cuda_runtime.h>
#include <cuda_fp16.h>
#include <math.h>
#include <stdint.h>

#define BB 2
#define SS 2048
#define HH 32
#define DHH 128
#define NQ 4096
#define BSZ 4096
#define TQ 128
#define TK 64
#define NT 32

// -------- scratch --------
__device__ float  g_kproj[BSZ*DHH];
__device__ float  g_vproj[BSZ*DHH];
__device__ __half g_xh   [BSZ*DHH];      // query fp16
__device__ __half g_wqT  [NQ*DHH];       // W_q^T fp16 [4096][128]
__device__ __half g_woT  [DHH*NQ];       // W_o^T fp16 [128][4096]
__device__ __half g_qh   [BSZ*NQ];       // Q proj, pre-scaled fp16
__device__ __half g_kh   [BSZ*DHH];      // K fp16 [b][s][d]
__device__ __half g_vt   [BB*DHH*SS];    // V^T fp16 [b][d][s]
__device__ __half g_attnh[BSZ*NQ];       // attention out fp16

// -------- helpers --------
__device__ __forceinline__ uint32_t smem_u32(const void* p){
    uint32_t a;
    asm("{ .reg .u64 t; cvta.to.shared.u64 t, %1; cvt.u32.u64 %0, t; }" : "=r"(a) : "l"(p));
    return a;
}
__device__ __forceinline__ void cp16(uint32_t dst, const void* src){
    asm volatile("cp.async.cg.shared.global [%0], [%1], 16;" :: "r"(dst), "l"(src));
}
#define CP_COMMIT() asm volatile("cp.async.commit_group;" ::: "memory")
#define CP_WAIT1()  asm volatile("cp.async.wait_group 1;" ::: "memory")
#define CP_WAIT0()  asm volatile("cp.async.wait_group 0;" ::: "memory")

__device__ __forceinline__ void mma16816(float* c, const uint32_t* a, const uint32_t* b){
    asm volatile("mma.sync.aligned.m16n8k16.row.col.f32.f16.f16.f32 "
        "{%0,%1,%2,%3}, {%4,%5,%6,%7}, {%8,%9}, {%0,%1,%2,%3};"
        : "+f"(c[0]), "+f"(c[1]), "+f"(c[2]), "+f"(c[3])
        : "r"(a[0]), "r"(a[1]), "r"(a[2]), "r"(a[3]), "r"(b[0]), "r"(b[1]));
}
__device__ __forceinline__ void ldsm4(uint32_t* r, uint32_t a){
    asm volatile("ldmatrix.sync.aligned.m8n8.x4.shared.b16 {%0,%1,%2,%3}, [%4];"
        : "=r"(r[0]), "=r"(r[1]), "=r"(r[2]), "=r"(r[3]) : "r"(a));
}
__device__ __forceinline__ uint32_t packh2(float x, float y){
    __half2 h = __floats2half2_rn(x, y);
    return *reinterpret_cast<uint32_t*>(&h);
}

// =======================================================================
// fp16 HMMA GEMM: C[M,N] = (A[M,K] @ Bt[N,K]^T + bias)*scale
// BM=128, BN=128, BK=32, 256 thr (warps 2m x 4n). dims % {128,128,32} == 0.
// =======================================================================
template<int OUT_HALF>
__global__ __launch_bounds__(256) void hgemm(
    const __half* __restrict__ A, const __half* __restrict__ Bt,
    const float* __restrict__ bias, void* __restrict__ Cv,
    int M, int N, int K, float scale)
{
    __shared__ __align__(16) __half As[2][128*40];
    __shared__ __align__(16) __half Bs[2][128*40];
    const int tid = threadIdx.x, lane = tid & 31, w = tid >> 5;
    const int wm = (w >> 2) * 64, wn = (w & 3) * 32;
    const int m0 = blockIdx.y * 128, n0 = blockIdx.x * 128;
    const int g = lane >> 2, q4 = lane & 3;
    const int arow = ((lane >> 3) & 1) * 8 + (lane & 7);
    const int akse = (lane >> 4) * 8;
    const int brow = ((lane >> 4) & 1) * 8 + (lane & 7);
    const int bkse = ((lane >> 3) & 1) * 8;

    float acc[4][4][4] = {};
    const int nk = K / 32;

    auto load = [&](int kb, int st){
        #pragma unroll
        for (int i = 0; i < 2; ++i) {
            int e = tid + 256*i, r = e >> 2, c = e & 3;
            cp16(smem_u32(&As[st][r*40 + c*8]), A  + (size_t)(m0 + r)*K + kb*32 + c*8);
            cp16(smem_u32(&Bs[st][r*40 + c*8]), Bt + (size_t)(n0 + r)*K + kb*32 + c*8);
        }
    };
    load(0, 0); CP_COMMIT();

    for (int kb = 0; kb < nk; ++kb) {
        if (kb + 1 < nk) { load(kb+1, (kb+1)&1); CP_COMMIT(); CP_WAIT1(); }
        else             { CP_WAIT0(); }
        __syncthreads();
        const int st = kb & 1;
        const uint32_t aB = smem_u32(&As[st][0]) + (wm + arow)*80 + akse*2;
        const uint32_t bB = smem_u32(&Bs[st][0]) + (wn + brow)*80 + bkse*2;
        #pragma unroll
        for (int ks = 0; ks < 2; ++ks) {
            uint32_t aF[4][4], bF[2][4];
            #pragma unroll
            for (int mi = 0; mi < 4; ++mi) ldsm4(aF[mi], aB + mi*16*80 + ks*32);
            #pragma unroll
            for (int np = 0; np < 2; ++np) ldsm4(bF[np], bB + np*16*80 + ks*32);
            #pragma unroll
            for (int mi = 0; mi < 4; ++mi)
                #pragma unroll
                for (int ni = 0; ni < 4; ++ni)
                    mma16816(acc[mi][ni], aF[mi], bF[ni>>1] + (ni&1)*2);
        }
        __syncthreads();
    }

    #pragma unroll
    for (int mi = 0; mi < 4; ++mi) {
        #pragma unroll
        for (int ni = 0; ni < 4; ++ni) {
            int row = m0 + wm + mi*16 + g;
            int col = n0 + wn + ni*8 + 2*q4;
            float b0 = bias[col], b1 = bias[col+1];
            float c0 = (acc[mi][ni][0] + b0)*scale, c1 = (acc[mi][ni][1] + b1)*scale;
            float c2 = (acc[mi][ni][2] + b0)*scale, c3 = (acc[mi][ni][3] + b1)*scale;
            if (OUT_HALF) {
                __half* C = (__half*)Cv;
                *reinterpret_cast<__half2*>(C + (size_t)row*N + col)     = __floats2half2_rn(c0, c1);
                *reinterpret_cast<__half2*>(C + (size_t)(row+8)*N + col) = __floats2half2_rn(c2, c3);
            } else {
                float* C = (float*)Cv;
                *reinterpret_cast<float2*>(C + (size_t)row*N + col)     = make_float2(c0, c1);
                *reinterpret_cast<float2*>(C + (size_t)(row+8)*N + col) = make_float2(c2, c3);
            }
        }
    }
}

// -------- fp32 GEMM + bias (K/V projections; proven) --------
__global__ __launch_bounds__(256) void gemm_bias(
    const float* __restrict__ A, const float* __restrict__ W,
    const float* __restrict__ bias, float* __restrict__ C,
    int M, int N, int K)
{
    __shared__ float Ast[32][65];
    __shared__ float Ws [32][65];
    const int tx = threadIdx.x & 15, ty = threadIdx.x >> 4;
    const int n0 = blockIdx.x * 64, m0 = blockIdx.y * 64;
    float acc[4][4] = {};
    for (int k0 = 0; k0 < K; k0 += 32) {
        for (int idx = threadIdx.x; idx < 64*32; idx += 256) {
            int r = idx >> 5, kk = idx & 31;
            Ast[kk][r] = A[(size_t)(m0 + r)*K + k0 + kk];
        }
        for (int idx = threadIdx.x; idx < 32*64; idx += 256) {
            int kk = idx >> 6, c = idx & 63;
            Ws[kk][c] = W[(size_t)(k0 + kk)*N + n0 + c];
        }
        __syncthreads();
        #pragma unroll
        for (int kk = 0; kk < 32; ++kk) {
            float a[4], wv[4];
            #pragma unroll
            for (int i = 0; i < 4; ++i) a[i] = Ast[kk][ty*4+i];
            #pragma unroll
            for (int j = 0; j < 4; ++j) wv[j] = Ws[kk][tx*4+j];
            #pragma unroll
            for (int i = 0; i < 4; ++i)
                #pragma unroll
                for (int j = 0; j < 4; ++j) acc[i][j] += a[i]*wv[j];
        }
        __syncthreads();
    }
    #pragma unroll
    for (int i = 0; i < 4; ++i)
        #pragma unroll
        for (int j = 0; j < 4; ++j)
            C[(size_t)(m0+ty*4+i)*N + n0+tx*4+j] = acc[i][j] + bias[n0+tx*4+j];
}

// -------- converts / transposes --------
__global__ void conv_h(const float* __restrict__ in, __half* __restrict__ out, int n){
    int i = blockIdx.x * 256 + threadIdx.x;
    if (i < n) out[i] = __float2half_rn(in[i]);
}
__global__ void conv_vt(const float* __restrict__ v, __half* __restrict__ ot){
    int s = blockIdx.x * 64 + (threadIdx.x & 63);
    int d = blockIdx.y * 4 + (threadIdx.x >> 6);
    int b = blockIdx.z;
    float f = v[((size_t)b*SS + s)*DHH + d];
    ot[((size_t)b*DHH + d)*SS + s] = __float2half_rn(f);
}
// W [K][N] fp32 -> Wt [N][K] fp16 ; grid (N/32, K/32), block 256
__global__ void transpose_w(const float* __restrict__ in, __half* __restrict__ out, int K, int N){
    __shared__ float t[32][33];
    int bx = blockIdx.x*32, by = blockIdx.y*32;
    int x = threadIdx.x & 31, y = threadIdx.x >> 5;
    #pragma unroll
    for (int i = 0; i < 4; ++i)
        t[y + 8*i][x] = in[(size_t)(by + y + 8*i)*N + bx + x];
    __syncthreads();
    #pragma unroll
    for (int i = 0; i < 4; ++i)
        out[(size_t)(bx + y + 8*i)*K + by + x] = __float2half_rn(t[x][y + 8*i]);
}

// =======================================================================
// HMMA flash attention
// =======================================================================
#define KROWB 272
#define VROWB 144
#define KBYTES (64*KROWB)
#define VBYTES (128*VROWB)
#define BUF    (KBYTES+VBYTES)
#define SMEM_DYN (2*BUF)

__device__ __forceinline__ void load_tile(uint32_t buf, int b, int kt,
    const __half* kh, const __half* vt, int tid)
{
    const __half* ks = kh + ((size_t)b*SS + (size_t)kt*TK) * DHH;
    #pragma unroll
    for (int t = 0; t < 4; ++t) {
        int e = tid + t*256, r = e >> 4, c = e & 15;
        cp16(buf + r*KROWB + c*16, ks + (size_t)r*DHH + c*8);
    }
    const __half* vs = vt + (size_t)b*DHH*SS + (size_t)kt*TK;
    #pragma unroll
    for (int t = 0; t < 4; ++t) {
        int e = tid + t*256, d = e >> 3, c = e & 7;
        cp16(buf + KBYTES + d*VROWB + c*16, vs + (size_t)d*SS + c*8);
    }
}

__global__ __launch_bounds__(256) void attn_hmma(
    const __half* __restrict__ qh, const __half* __restrict__ kh,
    const __half* __restrict__ vt, __half* __restrict__ o2h)
{
    extern __shared__ __align__(16) char smraw[];
    const uint32_t smb = smem_u32(smraw);
    const int qt = blockIdx.x, h = blockIdx.y, b = blockIdx.z;
    const int tid = threadIdx.x, w = tid >> 5, lane = tid & 31;
    const int g = lane >> 2, q4 = lane & 3;
    const int jrow = ((lane >> 4) & 1) * 8 + (lane & 7);
    const int ksel = ((lane >> 3) & 1) * 8;

    load_tile(smb, b, 0, kh, vt, tid);
    CP_COMMIT();

    // Q fragments straight from pre-scaled fp16 (no cvt)
    const __half* qsrc = qh + ((size_t)b*SS + (size_t)h*64 + (size_t)qt*4) * NQ;
    const int r0 = w*16 + g, r1 = r0 + 8;
    uint32_t aQ[8][4];
    #pragma unroll
    for (int ks = 0; ks < 8; ++ks) {
        int d0 = 16*ks + 2*q4;
        aQ[ks][0] = *reinterpret_cast<const uint32_t*>(qsrc + (size_t)r0*DHH + d0);
        aQ[ks][1] = *reinterpret_cast<const uint32_t*>(qsrc + (size_t)r1*DHH + d0);
        aQ[ks][2] = *reinterpret_cast<const uint32_t*>(qsrc + (size_t)r0*DHH + d0 + 8);
        aQ[ks][3] = *reinterpret_cast<const uint32_t*>(qsrc + (size_t)r1*DHH + d0 + 8);
    }

    float o[16][4];
    #pragma unroll
    for (int n = 0; n < 16; ++n)
        #pragma unroll
        for (int i = 0; i < 4; ++i) o[n][i] = 0.f;
    float rs0 = 0.f, rs1 = 0.f;

    for (int kt = 0; kt < NT; ++kt) {
        if (kt + 1 < NT) {
            load_tile(smb + ((kt+1)&1)*BUF, b, kt+1, kh, vt, tid);
            CP_COMMIT();
            CP_WAIT1();
        } else {
            CP_WAIT0();
        }
        __syncthreads();

        const uint32_t Kb = smb + (kt&1)*BUF + jrow*KROWB + ksel*2;
        const uint32_t Vb = smb + (kt&1)*BUF + KBYTES + jrow*VROWB + ksel*2;

        // S = Q K^T : 8 k-steps x 4 j-pairs, ldsm.x4 ping-pong
        float s[8][4];
        #pragma unroll
        for (int j = 0; j < 8; ++j)
            #pragma unroll
            for (int i = 0; i < 4; ++i) s[j][i] = 0.f;
        #pragma unroll
        for (int ks = 0; ks < 8; ++ks) {
            uint32_t bb[2][4];
            ldsm4(bb[0], Kb + 32*ks);
            #pragma unroll
            for (int jp = 0; jp < 4; ++jp) {
                if (jp < 3) ldsm4(bb[(jp+1)&1], Kb + (jp+1)*16*KROWB + 32*ks);
                mma16816(s[2*jp],   aQ[ks], bb[jp&1]);
                mma16816(s[2*jp+1], aQ[ks], bb[jp&1] + 2);
            }
        }

        // exp + pack P (register-only)
        uint32_t ph[4][4];
        #pragma unroll
        for (int j = 0; j < 8; ++j) {
            float p0 = __expf(s[j][0]);
            float p1 = __expf(s[j][1]);
            float p2 = __expf(s[j][2]);
            float p3 = __expf(s[j][3]);
            rs0 += p0 + p1;
            rs1 += p2 + p3;
            ph[j>>1][(j&1)*2]     = packh2(p0, p1);
            ph[j>>1][(j&1)*2 + 1] = packh2(p2, p3);
        }

        // O += P V : 4 k-steps x 8 n-pairs
        #pragma unroll
        for (int ks = 0; ks < 4; ++ks) {
            uint32_t bb[2][4];
            ldsm4(bb[0], Vb + 32*ks);
            #pragma unroll
            for (int np = 0; np < 8; ++np) {
                if (np < 7) ldsm4(bb[(np+1)&1], Vb + (np+1)*16*VROWB + 32*ks);
                mma16816(o[2*np],   ph[ks], bb[np&1]);
                mma16816(o[2*np+1], ph[ks], bb[np&1] + 2);
            }
        }
        __syncthreads();
    }

    rs0 += __shfl_xor_sync(0xffffffffu, rs0, 1);
    rs0 += __shfl_xor_sync(0xffffffffu, rs0, 2);
    rs1 += __shfl_xor_sync(0xffffffffu, rs1, 1);
    rs1 += __shfl_xor_sync(0xffffffffu, rs1, 2);
    const float inv0 = 1.0f / rs0, inv1 = 1.0f / rs1;

    __half* dst0 = o2h + ((size_t)b*SS + (size_t)qt*TQ + r0) * NQ + (size_t)h * DHH;
    __half* dst1 = o2h + ((size_t)b*SS + (size_t)qt*TQ + r1) * NQ + (size_t)h * DHH;
    #pragma unroll
    for (int n = 0; n < 16; ++n) {
        int c = 8*n + 2*q4;
        *reinterpret_cast<__half2*>(dst0 + c) = __floats2half2_rn(o[n][0]*inv0, o[n][1]*inv0);
        *reinterpret_cast<__half2*>(dst1 + c) = __floats2half2_rn(o[n][2]*inv1, o[n][3]*inv1);
    }
}

// ---------------------------------------------------------------------------
extern "C" void kernel_launch(void* const* d_in, const int* in_sizes, int n_in,
                              void* d_out, int out_size)
{
    const float* query  = (const float*)d_in[0];
    const float* key    = (const float*)d_in[1];
    const float* values = (const float*)d_in[2];
    const float* W_q = (const float*)d_in[3];
    const float* b_q = (const float*)d_in[4];
    const float* W_k = (const float*)d_in[5];
    const float* b_k = (const float*)d_in[6];
    const float* W_v = (const float*)d_in[7];
    const float* b_v = (const float*)d_in[8];
    const float* W_o = (const float*)d_in[9];
    const float* b_o = (const float*)d_in[10];
    float* out = (float*)d_out;

    float *kp, *vp;
    __half *xh, *wqT, *woT, *qhp, *khp, *vtp, *ah;
    cudaGetSymbolAddress((void**)&kp,  g_kproj);
    cudaGetSymbolAddress((void**)&vp,  g_vproj);
    cudaGetSymbolAddress((void**)&xh,  g_xh);
    cudaGetSymbolAddress((void**)&wqT, g_wqT);
    cudaGetSymbolAddress((void**)&woT, g_woT);
    cudaGetSymbolAddress((void**)&qhp, g_qh);
    cudaGetSymbolAddress((void**)&khp, g_kh);
    cudaGetSymbolAddress((void**)&vtp, g_vt);
    cudaGetSymbolAddress((void**)&ah,  g_attnh);

    cudaFuncSetAttribute(attn_hmma, cudaFuncAttributeMaxDynamicSharedMemorySize, SMEM_DYN);

    const float scl = 0.08838834764831845f;   // 1/sqrt(128)

    // prep: fp16 inputs + transposed fp16 weights
    conv_h<<<(BSZ*DHH + 255)/256, 256>>>(query, xh, BSZ*DHH);
    transpose_w<<<dim3(NQ/32,  DHH/32), 256>>>(W_q, wqT, DHH, NQ);
    transpose_w<<<dim3(DHH/32, NQ/32),  256>>>(W_o, woT, NQ, DHH);

    // K/V projections (fp32, error-sensitive path) + converts
    dim3 blk(256);
    gemm_bias<<<dim3(DHH/64, BSZ/64), blk>>>(key,    W_k, b_k, kp, BSZ, DHH, DHH);
    gemm_bias<<<dim3(DHH/64, BSZ/64), blk>>>(values, W_v, b_v, vp, BSZ, DHH, DHH);
    conv_h <<<(BSZ*DHH + 255)/256, 256>>>(kp, khp, BSZ*DHH);
    conv_vt<<<dim3(SS/64, DHH/4, BB), 256>>>(vp, vtp);

    // Q projection (HMMA, fp16 out, scale baked in)
    hgemm<1><<<dim3(NQ/128, BSZ/128), 256>>>(xh, wqT, b_q, qhp, BSZ, NQ, DHH, scl);

    // attention
    attn_hmma<<<dim3(SS/TQ, HH, BB), 256, SMEM_DYN>>>(qhp, khp, vtp, ah);

    // O projection (HMMA, fp32 out)
    hgemm<0><<<dim3(DHH/128, BSZ/128), 256>>>(ah, woT, b_o, out, BSZ, DHH, NQ, 1.0f);
}

// round 7
// speedup vs baseline: 8.7339x; 1.1264x over previous
#include <cuda_runtime.h>
#include <cuda_fp16.h>
#include <math.h>
#include <stdint.h>

#define BB 2
#define SS 2048
#define HH 32
#define DHH 128
#define NQ 4096
#define BSZ 4096
#define TQ 128
#define TK 64
#define NT 32
#define OSPLIT 8

// -------- scratch --------
__device__ float  g_kproj[BSZ*DHH];
__device__ float  g_vproj[BSZ*DHH];
__device__ float  g_part [OSPLIT*BSZ*DHH];   // O-proj split-K partials
__device__ __half g_xh   [BSZ*DHH];
__device__ __half g_wqT  [NQ*DHH];
__device__ __half g_woT  [DHH*NQ];
__device__ __half g_qh   [BSZ*NQ];           // Q proj, log2e/sqrt(d) pre-scaled fp16
__device__ __half g_kh   [BSZ*DHH];
__device__ __half g_vt   [BB*DHH*SS];
__device__ __half g_attnh[BSZ*NQ];

// -------- helpers --------
__device__ __forceinline__ uint32_t smem_u32(const void* p){
    uint32_t a;
    asm("{ .reg .u64 t; cvta.to.shared.u64 t, %1; cvt.u32.u64 %0, t; }" : "=r"(a) : "l"(p));
    return a;
}
__device__ __forceinline__ void cp16(uint32_t dst, const void* src){
    asm volatile("cp.async.cg.shared.global [%0], [%1], 16;" :: "r"(dst), "l"(src));
}
#define CP_COMMIT() asm volatile("cp.async.commit_group;" ::: "memory")
#define CP_WAIT1()  asm volatile("cp.async.wait_group 1;" ::: "memory")
#define CP_WAIT0()  asm volatile("cp.async.wait_group 0;" ::: "memory")

__device__ __forceinline__ void mma16816(float* c, const uint32_t* a, const uint32_t* b){
    asm volatile("mma.sync.aligned.m16n8k16.row.col.f32.f16.f16.f32 "
        "{%0,%1,%2,%3}, {%4,%5,%6,%7}, {%8,%9}, {%0,%1,%2,%3};"
        : "+f"(c[0]), "+f"(c[1]), "+f"(c[2]), "+f"(c[3])
        : "r"(a[0]), "r"(a[1]), "r"(a[2]), "r"(a[3]), "r"(b[0]), "r"(b[1]));
}
__device__ __forceinline__ void ldsm4(uint32_t* r, uint32_t a){
    asm volatile("ldmatrix.sync.aligned.m8n8.x4.shared.b16 {%0,%1,%2,%3}, [%4];"
        : "=r"(r[0]), "=r"(r[1]), "=r"(r[2]), "=r"(r[3]) : "r"(a));
}
__device__ __forceinline__ float ex2f(float x){
    float r;
    asm("ex2.approx.f32 %0, %1;" : "=f"(r) : "f"(x));
    return r;
}
__device__ __forceinline__ uint32_t packh2(float x, float y){
    __half2 h = __floats2half2_rn(x, y);
    return *reinterpret_cast<uint32_t*>(&h);
}

// =======================================================================
// fp16 HMMA GEMM (full-K): C = (A @ Bt^T + bias) * scale
// =======================================================================
template<int OUT_HALF>
__global__ __launch_bounds__(256) void hgemm(
    const __half* __restrict__ A, const __half* __restrict__ Bt,
    const float* __restrict__ bias, void* __restrict__ Cv,
    int M, int N, int K, float scale)
{
    __shared__ __align__(16) __half As[2][128*40];
    __shared__ __align__(16) __half Bs[2][128*40];
    const int tid = threadIdx.x, lane = tid & 31, w = tid >> 5;
    const int wm = (w >> 2) * 64, wn = (w & 3) * 32;
    const int m0 = blockIdx.y * 128, n0 = blockIdx.x * 128;
    const int g = lane >> 2, q4 = lane & 3;
    const int arow = ((lane >> 3) & 1) * 8 + (lane & 7);
    const int akse = (lane >> 4) * 8;
    const int brow = ((lane >> 4) & 1) * 8 + (lane & 7);
    const int bkse = ((lane >> 3) & 1) * 8;

    float acc[4][4][4] = {};
    const int nk = K / 32;

    auto load = [&](int kb, int st){
        #pragma unroll
        for (int i = 0; i < 2; ++i) {
            int e = tid + 256*i, r = e >> 2, c = e & 3;
            cp16(smem_u32(&As[st][r*40 + c*8]), A  + (size_t)(m0 + r)*K + kb*32 + c*8);
            cp16(smem_u32(&Bs[st][r*40 + c*8]), Bt + (size_t)(n0 + r)*K + kb*32 + c*8);
        }
    };
    load(0, 0); CP_COMMIT();

    for (int kb = 0; kb < nk; ++kb) {
        if (kb + 1 < nk) { load(kb+1, (kb+1)&1); CP_COMMIT(); CP_WAIT1(); }
        else             { CP_WAIT0(); }
        __syncthreads();
        const int st = kb & 1;
        const uint32_t aB = smem_u32(&As[st][0]) + (wm + arow)*80 + akse*2;
        const uint32_t bB = smem_u32(&Bs[st][0]) + (wn + brow)*80 + bkse*2;
        #pragma unroll
        for (int ks = 0; ks < 2; ++ks) {
            uint32_t aF[4][4], bF[2][4];
            #pragma unroll
            for (int mi = 0; mi < 4; ++mi) ldsm4(aF[mi], aB + mi*16*80 + ks*32);
            #pragma unroll
            for (int np = 0; np < 2; ++np) ldsm4(bF[np], bB + np*16*80 + ks*32);
            #pragma unroll
            for (int mi = 0; mi < 4; ++mi)
                #pragma unroll
                for (int ni = 0; ni < 4; ++ni)
                    mma16816(acc[mi][ni], aF[mi], bF[ni>>1] + (ni&1)*2);
        }
        __syncthreads();
    }

    #pragma unroll
    for (int mi = 0; mi < 4; ++mi) {
        #pragma unroll
        for (int ni = 0; ni < 4; ++ni) {
            int row = m0 + wm + mi*16 + g;
            int col = n0 + wn + ni*8 + 2*q4;
            float b0 = bias[col], b1 = bias[col+1];
            float c0 = (acc[mi][ni][0] + b0)*scale, c1 = (acc[mi][ni][1] + b1)*scale;
            float c2 = (acc[mi][ni][2] + b0)*scale, c3 = (acc[mi][ni][3] + b1)*scale;
            if (OUT_HALF) {
                __half* C = (__half*)Cv;
                *reinterpret_cast<__half2*>(C + (size_t)row*N + col)     = __floats2half2_rn(c0, c1);
                *reinterpret_cast<__half2*>(C + (size_t)(row+8)*N + col) = __floats2half2_rn(c2, c3);
            } else {
                float* C = (float*)Cv;
                *reinterpret_cast<float2*>(C + (size_t)row*N + col)     = make_float2(c0, c1);
                *reinterpret_cast<float2*>(C + (size_t)(row+8)*N + col) = make_float2(c2, c3);
            }
        }
    }
}

// ---- split-K hgemm: partial[kc] = A @ Bt^T over K-chunk kc (no bias) ----
__global__ __launch_bounds__(256) void hgemm_splitk(
    const __half* __restrict__ A, const __half* __restrict__ Bt,
    float* __restrict__ part, int M, int N, int K)
{
    __shared__ __align__(16) __half As[2][128*40];
    __shared__ __align__(16) __half Bs[2][128*40];
    const int tid = threadIdx.x, lane = tid & 31, w = tid >> 5;
    const int wm = (w >> 2) * 64, wn = (w & 3) * 32;
    const int m0 = blockIdx.y * 128, n0 = blockIdx.x * 128;
    const int kc = blockIdx.z;
    const int g = lane >> 2, q4 = lane & 3;
    const int arow = ((lane >> 3) & 1) * 8 + (lane & 7);
    const int akse = (lane >> 4) * 8;
    const int brow = ((lane >> 4) & 1) * 8 + (lane & 7);
    const int bkse = ((lane >> 3) & 1) * 8;

    float acc[4][4][4] = {};
    const int nkpc = K / 32 / OSPLIT;
    const int kb0 = kc * nkpc;

    auto load = [&](int kb, int st){
        #pragma unroll
        for (int i = 0; i < 2; ++i) {
            int e = tid + 256*i, r = e >> 2, c = e & 3;
            cp16(smem_u32(&As[st][r*40 + c*8]), A  + (size_t)(m0 + r)*K + kb*32 + c*8);
            cp16(smem_u32(&Bs[st][r*40 + c*8]), Bt + (size_t)(n0 + r)*K + kb*32 + c*8);
        }
    };
    load(kb0, 0); CP_COMMIT();

    for (int i = 0; i < nkpc; ++i) {
        if (i + 1 < nkpc) { load(kb0+i+1, (i+1)&1); CP_COMMIT(); CP_WAIT1(); }
        else              { CP_WAIT0(); }
        __syncthreads();
        const int st = i & 1;
        const uint32_t aB = smem_u32(&As[st][0]) + (wm + arow)*80 + akse*2;
        const uint32_t bB = smem_u32(&Bs[st][0]) + (wn + brow)*80 + bkse*2;
        #pragma unroll
        for (int ks = 0; ks < 2; ++ks) {
            uint32_t aF[4][4], bF[2][4];
            #pragma unroll
            for (int mi = 0; mi < 4; ++mi) ldsm4(aF[mi], aB + mi*16*80 + ks*32);
            #pragma unroll
            for (int np = 0; np < 2; ++np) ldsm4(bF[np], bB + np*16*80 + ks*32);
            #pragma unroll
            for (int mi = 0; mi < 4; ++mi)
                #pragma unroll
                for (int ni = 0; ni < 4; ++ni)
                    mma16816(acc[mi][ni], aF[mi], bF[ni>>1] + (ni&1)*2);
        }
        __syncthreads();
    }

    float* P = part + (size_t)kc * M * N;
    #pragma unroll
    for (int mi = 0; mi < 4; ++mi)
        #pragma unroll
        for (int ni = 0; ni < 4; ++ni) {
            int row = m0 + wm + mi*16 + g;
            int col = n0 + wn + ni*8 + 2*q4;
            *reinterpret_cast<float2*>(P + (size_t)row*N + col)     = make_float2(acc[mi][ni][0], acc[mi][ni][1]);
            *reinterpret_cast<float2*>(P + (size_t)(row+8)*N + col) = make_float2(acc[mi][ni][2], acc[mi][ni][3]);
        }
}

__global__ void reduce_bias(const float* __restrict__ part, const float* __restrict__ bias,
                            float* __restrict__ out, int MN, int N)
{
    int i = (blockIdx.x * 256 + threadIdx.x) * 4;
    if (i >= MN) return;
    float4 s = *reinterpret_cast<const float4*>(part + i);
    #pragma unroll
    for (int kc = 1; kc < OSPLIT; ++kc) {
        float4 p = *reinterpret_cast<const float4*>(part + (size_t)kc*MN + i);
        s.x += p.x; s.y += p.y; s.z += p.z; s.w += p.w;
    }
    int c = i & (N - 1);
    s.x += bias[c]; s.y += bias[c+1]; s.z += bias[c+2]; s.w += bias[c+3];
    *reinterpret_cast<float4*>(out + i) = s;
}

// -------- fp32 GEMM + bias (K/V projections) --------
__global__ __launch_bounds__(256) void gemm_bias(
    const float* __restrict__ A, const float* __restrict__ W,
    const float* __restrict__ bias, float* __restrict__ C,
    int M, int N, int K)
{
    __shared__ float Ast[32][65];
    __shared__ float Ws [32][65];
    const int tx = threadIdx.x & 15, ty = threadIdx.x >> 4;
    const int n0 = blockIdx.x * 64, m0 = blockIdx.y * 64;
    float acc[4][4] = {};
    for (int k0 = 0; k0 < K; k0 += 32) {
        for (int idx = threadIdx.x; idx < 64*32; idx += 256) {
            int r = idx >> 5, kk = idx & 31;
            Ast[kk][r] = A[(size_t)(m0 + r)*K + k0 + kk];
        }
        for (int idx = threadIdx.x; idx < 32*64; idx += 256) {
            int kk = idx >> 6, c = idx & 63;
            Ws[kk][c] = W[(size_t)(k0 + kk)*N + n0 + c];
        }
        __syncthreads();
        #pragma unroll
        for (int kk = 0; kk < 32; ++kk) {
            float a[4], wv[4];
            #pragma unroll
            for (int i = 0; i < 4; ++i) a[i] = Ast[kk][ty*4+i];
            #pragma unroll
            for (int j = 0; j < 4; ++j) wv[j] = Ws[kk][tx*4+j];
            #pragma unroll
            for (int i = 0; i < 4; ++i)
                #pragma unroll
                for (int j = 0; j < 4; ++j) acc[i][j] += a[i]*wv[j];
        }
        __syncthreads();
    }
    #pragma unroll
    for (int i = 0; i < 4; ++i)
        #pragma unroll
        for (int j = 0; j < 4; ++j)
            C[(size_t)(m0+ty*4+i)*N + n0+tx*4+j] = acc[i][j] + bias[n0+tx*4+j];
}

// -------- converts / transposes --------
__global__ void conv_h(const float* __restrict__ in, __half* __restrict__ out, int n){
    int i = blockIdx.x * 256 + threadIdx.x;
    if (i < n) out[i] = __float2half_rn(in[i]);
}
__global__ void conv_vt(const float* __restrict__ v, __half* __restrict__ ot){
    int s = blockIdx.x * 64 + (threadIdx.x & 63);
    int d = blockIdx.y * 4 + (threadIdx.x >> 6);
    int b = blockIdx.z;
    float f = v[((size_t)b*SS + s)*DHH + d];
    ot[((size_t)b*DHH + d)*SS + s] = __float2half_rn(f);
}
__global__ void transpose_w(const float* __restrict__ in, __half* __restrict__ out, int K, int N){
    __shared__ float t[32][33];
    int bx = blockIdx.x*32, by = blockIdx.y*32;
    int x = threadIdx.x & 31, y = threadIdx.x >> 5;
    #pragma unroll
    for (int i = 0; i < 4; ++i)
        t[y + 8*i][x] = in[(size_t)(by + y + 8*i)*N + bx + x];
    __syncthreads();
    #pragma unroll
    for (int i = 0; i < 4; ++i)
        out[(size_t)(bx + y + 8*i)*K + by + x] = __float2half_rn(t[x][y + 8*i]);
}

// =======================================================================
// HMMA flash attention (log2-domain softmax, rowsum-by-MMA, 3-stage/1-sync)
// =======================================================================
#define KROWB 272
#define VROWB 144
#define KBYTES (64*KROWB)
#define VBYTES (128*VROWB)
#define BUF    (KBYTES+VBYTES)
#define SMEM_DYN (3*BUF)

__device__ __forceinline__ void load_tile(uint32_t buf, int b, int kt,
    const __half* kh, const __half* vt, int tid)
{
    const __half* ks = kh + ((size_t)b*SS + (size_t)kt*TK) * DHH;
    #pragma unroll
    for (int t = 0; t < 4; ++t) {
        int e = tid + t*256, r = e >> 4, c = e & 15;
        cp16(buf + r*KROWB + c*16, ks + (size_t)r*DHH + c*8);
    }
    const __half* vs = vt + (size_t)b*DHH*SS + (size_t)kt*TK;
    #pragma unroll
    for (int t = 0; t < 4; ++t) {
        int e = tid + t*256, d = e >> 3, c = e & 7;
        cp16(buf + KBYTES + d*VROWB + c*16, vs + (size_t)d*SS + c*8);
    }
}

__global__ __launch_bounds__(256) void attn_hmma(
    const __half* __restrict__ qh, const __half* __restrict__ kh,
    const __half* __restrict__ vt, __half* __restrict__ o2h)
{
    extern __shared__ __align__(16) char smraw[];
    const uint32_t smb = smem_u32(smraw);
    const int qt = blockIdx.x, h = blockIdx.y, b = blockIdx.z;
    const int tid = threadIdx.x, w = tid >> 5, lane = tid & 31;
    const int g = lane >> 2, q4 = lane & 3;
    const int jrow = ((lane >> 4) & 1) * 8 + (lane & 7);
    const int ksel = ((lane >> 3) & 1) * 8;

    load_tile(smb,       b, 0, kh, vt, tid); CP_COMMIT();
    load_tile(smb + BUF, b, 1, kh, vt, tid); CP_COMMIT();

    const __half* qsrc = qh + ((size_t)b*SS + (size_t)h*64 + (size_t)qt*4) * NQ;
    const int r0 = w*16 + g, r1 = r0 + 8;
    uint32_t aQ[8][4];
    #pragma unroll
    for (int ks = 0; ks < 8; ++ks) {
        int d0 = 16*ks + 2*q4;
        aQ[ks][0] = *reinterpret_cast<const uint32_t*>(qsrc + (size_t)r0*DHH + d0);
        aQ[ks][1] = *reinterpret_cast<const uint32_t*>(qsrc + (size_t)r1*DHH + d0);
        aQ[ks][2] = *reinterpret_cast<const uint32_t*>(qsrc + (size_t)r0*DHH + d0 + 8);
        aQ[ks][3] = *reinterpret_cast<const uint32_t*>(qsrc + (size_t)r1*DHH + d0 + 8);
    }

    float o[16][4];
    #pragma unroll
    for (int n = 0; n < 16; ++n)
        #pragma unroll
        for (int i = 0; i < 4; ++i) o[n][i] = 0.f;
    float rsum[4] = {0.f, 0.f, 0.f, 0.f};
    const uint32_t onesB[2] = {0x3C003C00u, 0x3C003C00u};

    for (int kt = 0; kt < NT; ++kt) {
        if (kt + 1 < NT) { CP_WAIT1(); } else { CP_WAIT0(); }
        __syncthreads();                                 // single barrier per tile
        if (kt + 2 < NT) {
            load_tile(smb + (uint32_t)((kt+2)%3)*BUF, b, kt+2, kh, vt, tid);
            CP_COMMIT();
        }

        const uint32_t Kb = smb + (uint32_t)(kt%3)*BUF + jrow*KROWB + ksel*2;
        const uint32_t Vb = smb + (uint32_t)(kt%3)*BUF + KBYTES + jrow*VROWB + ksel*2;

        // S = Q K^T (log2 domain; scale baked into Q)
        float s[8][4];
        #pragma unroll
        for (int j = 0; j < 8; ++j)
            #pragma unroll
            for (int i = 0; i < 4; ++i) s[j][i] = 0.f;
        #pragma unroll
        for (int ks = 0; ks < 8; ++ks) {
            uint32_t bb[2][4];
            ldsm4(bb[0], Kb + 32*ks);
            #pragma unroll
            for (int jp = 0; jp < 4; ++jp) {
                if (jp < 3) ldsm4(bb[(jp+1)&1], Kb + (jp+1)*16*KROWB + 32*ks);
                mma16816(s[2*jp],   aQ[ks], bb[jp&1]);
                mma16816(s[2*jp+1], aQ[ks], bb[jp&1] + 2);
            }
        }

        // p = 2^s, pack to fp16 fragments (register-only)
        uint32_t ph[4][4];
        #pragma unroll
        for (int j = 0; j < 8; ++j) {
            float p0 = ex2f(s[j][0]);
            float p1 = ex2f(s[j][1]);
            float p2 = ex2f(s[j][2]);
            float p3 = ex2f(s[j][3]);
            ph[j>>1][(j&1)*2]     = packh2(p0, p1);
            ph[j>>1][(j&1)*2 + 1] = packh2(p2, p3);
        }

        // O += P V ; rowsum += P @ ones (exactly consistent with fp16 P)
        #pragma unroll
        for (int ks = 0; ks < 4; ++ks) {
            uint32_t bb[2][4];
            ldsm4(bb[0], Vb + 32*ks);
            #pragma unroll
            for (int np = 0; np < 8; ++np) {
                if (np < 7) ldsm4(bb[(np+1)&1], Vb + (np+1)*16*VROWB + 32*ks);
                mma16816(o[2*np],   ph[ks], bb[np&1]);
                mma16816(o[2*np+1], ph[ks], bb[np&1] + 2);
            }
            mma16816(rsum, ph[ks], onesB);
        }
    }

    const float inv0 = 1.0f / rsum[0], inv1 = 1.0f / rsum[2];

    __half* dst0 = o2h + ((size_t)b*SS + (size_t)qt*TQ + r0) * NQ + (size_t)h * DHH;
    __half* dst1 = o2h + ((size_t)b*SS + (size_t)qt*TQ + r1) * NQ + (size_t)h * DHH;
    #pragma unroll
    for (int n = 0; n < 16; ++n) {
        int c = 8*n + 2*q4;
        *reinterpret_cast<__half2*>(dst0 + c) = __floats2half2_rn(o[n][0]*inv0, o[n][1]*inv0);
        *reinterpret_cast<__half2*>(dst1 + c) = __floats2half2_rn(o[n][2]*inv1, o[n][3]*inv1);
    }
}

// ---------------------------------------------------------------------------
extern "C" void kernel_launch(void* const* d_in, const int* in_sizes, int n_in,
                              void* d_out, int out_size)
{
    const float* query  = (const float*)d_in[0];
    const float* key    = (const float*)d_in[1];
    const float* values = (const float*)d_in[2];
    const float* W_q = (const float*)d_in[3];
    const float* b_q = (const float*)d_in[4];
    const float* W_k = (const float*)d_in[5];
    const float* b_k = (const float*)d_in[6];
    const float* W_v = (const float*)d_in[7];
    const float* b_v = (const float*)d_in[8];
    const float* W_o = (const float*)d_in[9];
    const float* b_o = (const float*)d_in[10];
    float* out = (float*)d_out;

    float *kp, *vp, *pp;
    __half *xh, *wqT, *woT, *qhp, *khp, *vtp, *ah;
    cudaGetSymbolAddress((void**)&kp,  g_kproj);
    cudaGetSymbolAddress((void**)&vp,  g_vproj);
    cudaGetSymbolAddress((void**)&pp,  g_part);
    cudaGetSymbolAddress((void**)&xh,  g_xh);
    cudaGetSymbolAddress((void**)&wqT, g_wqT);
    cudaGetSymbolAddress((void**)&woT, g_woT);
    cudaGetSymbolAddress((void**)&qhp, g_qh);
    cudaGetSymbolAddress((void**)&khp, g_kh);
    cudaGetSymbolAddress((void**)&vtp, g_vt);
    cudaGetSymbolAddress((void**)&ah,  g_attnh);

    cudaFuncSetAttribute(attn_hmma, cudaFuncAttributeMaxDynamicSharedMemorySize, SMEM_DYN);

    const float scl2 = 0.12753102189093095f;   // log2(e)/sqrt(128)

    conv_h<<<(BSZ*DHH + 255)/256, 256>>>(query, xh, BSZ*DHH);
    transpose_w<<<dim3(NQ/32,  DHH/32), 256>>>(W_q, wqT, DHH, NQ);
    transpose_w<<<dim3(DHH/32, NQ/32),  256>>>(W_o, woT, NQ, DHH);

    dim3 blk(256);
    gemm_bias<<<dim3(DHH/64, BSZ/64), blk>>>(key,    W_k, b_k, kp, BSZ, DHH, DHH);
    gemm_bias<<<dim3(DHH/64, BSZ/64), blk>>>(values, W_v, b_v, vp, BSZ, DHH, DHH);
    conv_h <<<(BSZ*DHH + 255)/256, 256>>>(kp, khp, BSZ*DHH);
    conv_vt<<<dim3(SS/64, DHH/4, BB), 256>>>(vp, vtp);

    // Q projection (HMMA, fp16 out, log2-domain scale baked in)
    hgemm<1><<<dim3(NQ/128, BSZ/128), 256>>>(xh, wqT, b_q, qhp, BSZ, NQ, DHH, scl2);

    // attention
    attn_hmma<<<dim3(SS/TQ, HH, BB), 256, SMEM_DYN>>>(qhp, khp, vtp, ah);

    // O projection: split-K HMMA + reduce
    hgemm_splitk<<<dim3(DHH/128, BSZ/128, OSPLIT), 256>>>(ah, woT, pp, BSZ, DHH, NQ);
    reduce_bias<<<(BSZ*DHH/4 + 255)/256, 256>>>(pp, b_o, out, BSZ*DHH, DHH);
}

// round 8
// speedup vs baseline: 9.2168x; 1.0553x over previous
#include <cuda_runtime.h>
#include <cuda_fp16.h>
#include <math.h>
#include <stdint.h>

#define BB 2
#define SS 2048
#define HH 32
#define DHH 128
#define NQ 4096
#define BSZ 4096
#define TQ 128
#define TK 64
#define NT 32
#define OSPLIT 8

// -------- scratch --------
__device__ float  g_part [OSPLIT*BSZ*DHH];
__device__ __half g_xh   [BSZ*DHH];          // query fp16
__device__ __half g_xkh  [BSZ*DHH];          // key input fp16
__device__ __half g_xvh  [BSZ*DHH];          // values input fp16
__device__ __half g_wqT  [NQ*DHH];
__device__ __half g_wkT  [DHH*DHH];
__device__ __half g_wvT  [DHH*DHH];
__device__ __half g_woT  [DHH*NQ];
__device__ __half g_qh   [BSZ*NQ];           // Q proj, log2e/sqrt(d) pre-scaled
__device__ __half g_kh   [BSZ*DHH];          // K proj fp16 [b][s][d]
__device__ __half g_vh   [BSZ*DHH];          // V proj fp16 [b][s][d]
__device__ __half g_vt   [BB*DHH*SS];        // V^T fp16 [b][d][s]
__device__ __half g_attnh[BSZ*NQ];

// -------- helpers --------
__device__ __forceinline__ uint32_t smem_u32(const void* p){
    uint32_t a;
    asm("{ .reg .u64 t; cvta.to.shared.u64 t, %1; cvt.u32.u64 %0, t; }" : "=r"(a) : "l"(p));
    return a;
}
__device__ __forceinline__ void cp16(uint32_t dst, const void* src){
    asm volatile("cp.async.cg.shared.global [%0], [%1], 16;" :: "r"(dst), "l"(src));
}
#define CP_COMMIT() asm volatile("cp.async.commit_group;" ::: "memory")
#define CP_WAIT1()  asm volatile("cp.async.wait_group 1;" ::: "memory")
#define CP_WAIT0()  asm volatile("cp.async.wait_group 0;" ::: "memory")

__device__ __forceinline__ void mma16816(float* c, const uint32_t* a, const uint32_t* b){
    asm volatile("mma.sync.aligned.m16n8k16.row.col.f32.f16.f16.f32 "
        "{%0,%1,%2,%3}, {%4,%5,%6,%7}, {%8,%9}, {%0,%1,%2,%3};"
        : "+f"(c[0]), "+f"(c[1]), "+f"(c[2]), "+f"(c[3])
        : "r"(a[0]), "r"(a[1]), "r"(a[2]), "r"(a[3]), "r"(b[0]), "r"(b[1]));
}
__device__ __forceinline__ void ldsm4(uint32_t* r, uint32_t a){
    asm volatile("ldmatrix.sync.aligned.m8n8.x4.shared.b16 {%0,%1,%2,%3}, [%4];"
        : "=r"(r[0]), "=r"(r[1]), "=r"(r[2]), "=r"(r[3]) : "r"(a));
}
__device__ __forceinline__ float ex2f(float x){
    float r;
    asm("ex2.approx.f32 %0, %1;" : "=f"(r) : "f"(x));
    return r;
}
__device__ __forceinline__ uint32_t packh2(float x, float y){
    __half2 h = __floats2half2_rn(x, y);
    return *reinterpret_cast<uint32_t*>(&h);
}

// =======================================================================
// fp16 HMMA GEMM (full-K): C = (A @ Bt^T + bias) * scale
// =======================================================================
template<int OUT_HALF>
__global__ __launch_bounds__(256) void hgemm(
    const __half* __restrict__ A, const __half* __restrict__ Bt,
    const float* __restrict__ bias, void* __restrict__ Cv,
    int M, int N, int K, float scale)
{
    __shared__ __align__(16) __half As[2][128*40];
    __shared__ __align__(16) __half Bs[2][128*40];
    const int tid = threadIdx.x, lane = tid & 31, w = tid >> 5;
    const int wm = (w >> 2) * 64, wn = (w & 3) * 32;
    const int m0 = blockIdx.y * 128, n0 = blockIdx.x * 128;
    const int g = lane >> 2, q4 = lane & 3;
    const int arow = ((lane >> 3) & 1) * 8 + (lane & 7);
    const int akse = (lane >> 4) * 8;
    const int brow = ((lane >> 4) & 1) * 8 + (lane & 7);
    const int bkse = ((lane >> 3) & 1) * 8;

    float acc[4][4][4] = {};
    const int nk = K / 32;

    auto load = [&](int kb, int st){
        #pragma unroll
        for (int i = 0; i < 2; ++i) {
            int e = tid + 256*i, r = e >> 2, c = e & 3;
            cp16(smem_u32(&As[st][r*40 + c*8]), A  + (size_t)(m0 + r)*K + kb*32 + c*8);
            cp16(smem_u32(&Bs[st][r*40 + c*8]), Bt + (size_t)(n0 + r)*K + kb*32 + c*8);
        }
    };
    load(0, 0); CP_COMMIT();

    for (int kb = 0; kb < nk; ++kb) {
        if (kb + 1 < nk) { load(kb+1, (kb+1)&1); CP_COMMIT(); CP_WAIT1(); }
        else             { CP_WAIT0(); }
        __syncthreads();
        const int st = kb & 1;
        const uint32_t aB = smem_u32(&As[st][0]) + (wm + arow)*80 + akse*2;
        const uint32_t bB = smem_u32(&Bs[st][0]) + (wn + brow)*80 + bkse*2;
        #pragma unroll
        for (int ks = 0; ks < 2; ++ks) {
            uint32_t aF[4][4], bF[2][4];
            #pragma unroll
            for (int mi = 0; mi < 4; ++mi) ldsm4(aF[mi], aB + mi*16*80 + ks*32);
            #pragma unroll
            for (int np = 0; np < 2; ++np) ldsm4(bF[np], bB + np*16*80 + ks*32);
            #pragma unroll
            for (int mi = 0; mi < 4; ++mi)
                #pragma unroll
                for (int ni = 0; ni < 4; ++ni)
                    mma16816(acc[mi][ni], aF[mi], bF[ni>>1] + (ni&1)*2);
        }
        __syncthreads();
    }

    #pragma unroll
    for (int mi = 0; mi < 4; ++mi) {
        #pragma unroll
        for (int ni = 0; ni < 4; ++ni) {
            int row = m0 + wm + mi*16 + g;
            int col = n0 + wn + ni*8 + 2*q4;
            float b0 = bias[col], b1 = bias[col+1];
            float c0 = (acc[mi][ni][0] + b0)*scale, c1 = (acc[mi][ni][1] + b1)*scale;
            float c2 = (acc[mi][ni][2] + b0)*scale, c3 = (acc[mi][ni][3] + b1)*scale;
            if (OUT_HALF) {
                __half* C = (__half*)Cv;
                *reinterpret_cast<__half2*>(C + (size_t)row*N + col)     = __floats2half2_rn(c0, c1);
                *reinterpret_cast<__half2*>(C + (size_t)(row+8)*N + col) = __floats2half2_rn(c2, c3);
            } else {
                float* C = (float*)Cv;
                *reinterpret_cast<float2*>(C + (size_t)row*N + col)     = make_float2(c0, c1);
                *reinterpret_cast<float2*>(C + (size_t)(row+8)*N + col) = make_float2(c2, c3);
            }
        }
    }
}

// ---- split-K hgemm + reduce (O projection) ----
__global__ __launch_bounds__(256) void hgemm_splitk(
    const __half* __restrict__ A, const __half* __restrict__ Bt,
    float* __restrict__ part, int M, int N, int K)
{
    __shared__ __align__(16) __half As[2][128*40];
    __shared__ __align__(16) __half Bs[2][128*40];
    const int tid = threadIdx.x, lane = tid & 31, w = tid >> 5;
    const int wm = (w >> 2) * 64, wn = (w & 3) * 32;
    const int m0 = blockIdx.y * 128, n0 = blockIdx.x * 128;
    const int kc = blockIdx.z;
    const int g = lane >> 2, q4 = lane & 3;
    const int arow = ((lane >> 3) & 1) * 8 + (lane & 7);
    const int akse = (lane >> 4) * 8;
    const int brow = ((lane >> 4) & 1) * 8 + (lane & 7);
    const int bkse = ((lane >> 3) & 1) * 8;

    float acc[4][4][4] = {};
    const int nkpc = K / 32 / OSPLIT;
    const int kb0 = kc * nkpc;

    auto load = [&](int kb, int st){
        #pragma unroll
        for (int i = 0; i < 2; ++i) {
            int e = tid + 256*i, r = e >> 2, c = e & 3;
            cp16(smem_u32(&As[st][r*40 + c*8]), A  + (size_t)(m0 + r)*K + kb*32 + c*8);
            cp16(smem_u32(&Bs[st][r*40 + c*8]), Bt + (size_t)(n0 + r)*K + kb*32 + c*8);
        }
    };
    load(kb0, 0); CP_COMMIT();

    for (int i = 0; i < nkpc; ++i) {
        if (i + 1 < nkpc) { load(kb0+i+1, (i+1)&1); CP_COMMIT(); CP_WAIT1(); }
        else              { CP_WAIT0(); }
        __syncthreads();
        const int st = i & 1;
        const uint32_t aB = smem_u32(&As[st][0]) + (wm + arow)*80 + akse*2;
        const uint32_t bB = smem_u32(&Bs[st][0]) + (wn + brow)*80 + bkse*2;
        #pragma unroll
        for (int ks = 0; ks < 2; ++ks) {
            uint32_t aF[4][4], bF[2][4];
            #pragma unroll
            for (int mi = 0; mi < 4; ++mi) ldsm4(aF[mi], aB + mi*16*80 + ks*32);
            #pragma unroll
            for (int np = 0; np < 2; ++np) ldsm4(bF[np], bB + np*16*80 + ks*32);
            #pragma unroll
            for (int mi = 0; mi < 4; ++mi)
                #pragma unroll
                for (int ni = 0; ni < 4; ++ni)
                    mma16816(acc[mi][ni], aF[mi], bF[ni>>1] + (ni&1)*2);
        }
        __syncthreads();
    }

    float* P = part + (size_t)kc * M * N;
    #pragma unroll
    for (int mi = 0; mi < 4; ++mi)
        #pragma unroll
        for (int ni = 0; ni < 4; ++ni) {
            int row = m0 + wm + mi*16 + g;
            int col = n0 + wn + ni*8 + 2*q4;
            *reinterpret_cast<float2*>(P + (size_t)row*N + col)     = make_float2(acc[mi][ni][0], acc[mi][ni][1]);
            *reinterpret_cast<float2*>(P + (size_t)(row+8)*N + col) = make_float2(acc[mi][ni][2], acc[mi][ni][3]);
        }
}

__global__ void reduce_bias(const float* __restrict__ part, const float* __restrict__ bias,
                            float* __restrict__ out, int MN, int N)
{
    int i = (blockIdx.x * 256 + threadIdx.x) * 4;
    if (i >= MN) return;
    float4 s = *reinterpret_cast<const float4*>(part + i);
    #pragma unroll
    for (int kc = 1; kc < OSPLIT; ++kc) {
        float4 p = *reinterpret_cast<const float4*>(part + (size_t)kc*MN + i);
        s.x += p.x; s.y += p.y; s.z += p.z; s.w += p.w;
    }
    int c = i & (N - 1);
    s.x += bias[c]; s.y += bias[c+1]; s.z += bias[c+2]; s.w += bias[c+3];
    *reinterpret_cast<float4*>(out + i) = s;
}

// -------- converts / transposes --------
__global__ void conv_h(const float* __restrict__ in, __half* __restrict__ out, int n){
    int i = blockIdx.x * 256 + threadIdx.x;
    if (i < n) out[i] = __float2half_rn(in[i]);
}
__global__ void conv_vt_h(const __half* __restrict__ v, __half* __restrict__ ot){
    int s = blockIdx.x * 64 + (threadIdx.x & 63);
    int d = blockIdx.y * 4 + (threadIdx.x >> 6);
    int b = blockIdx.z;
    ot[((size_t)b*DHH + d)*SS + s] = v[((size_t)b*SS + s)*DHH + d];
}
__global__ void transpose_w(const float* __restrict__ in, __half* __restrict__ out, int K, int N){
    __shared__ float t[32][33];
    int bx = blockIdx.x*32, by = blockIdx.y*32;
    int x = threadIdx.x & 31, y = threadIdx.x >> 5;
    #pragma unroll
    for (int i = 0; i < 4; ++i)
        t[y + 8*i][x] = in[(size_t)(by + y + 8*i)*N + bx + x];
    __syncthreads();
    #pragma unroll
    for (int i = 0; i < 4; ++i)
        out[(size_t)(bx + y + 8*i)*K + by + x] = __float2half_rn(t[x][y + 8*i]);
}

// =======================================================================
// HMMA flash attention — 2 heads per CTA (halves K/V L2 traffic)
// =======================================================================
#define KROWB 272
#define VROWB 144
#define KBYTES (64*KROWB)
#define VBYTES (128*VROWB)
#define BUF    (KBYTES+VBYTES)
#define QROWB  272
#define QBYTES (128*QROWB)
#define SMEM_DYN (2*QBYTES + 3*BUF)   // 69632 + 107520 = 177152

__device__ __forceinline__ void load_tile(uint32_t buf, int b, int kt,
    const __half* kh, const __half* vt, int tid)
{
    const __half* ks = kh + ((size_t)b*SS + (size_t)kt*TK) * DHH;
    #pragma unroll
    for (int t = 0; t < 4; ++t) {
        int e = tid + t*256, r = e >> 4, c = e & 15;
        cp16(buf + r*KROWB + c*16, ks + (size_t)r*DHH + c*8);
    }
    const __half* vs = vt + (size_t)b*DHH*SS + (size_t)kt*TK;
    #pragma unroll
    for (int t = 0; t < 4; ++t) {
        int e = tid + t*256, d = e >> 3, c = e & 7;
        cp16(buf + KBYTES + d*VROWB + c*16, vs + (size_t)d*SS + c*8);
    }
}

__global__ __launch_bounds__(256, 1) void attn_hmma(
    const __half* __restrict__ qh, const __half* __restrict__ kh,
    const __half* __restrict__ vt, __half* __restrict__ o2h)
{
    extern __shared__ __align__(16) char smraw[];
    const uint32_t smb = smem_u32(smraw);
    const uint32_t kvb = smb + 2*QBYTES;
    const int qt = blockIdx.x, hp = blockIdx.y, b = blockIdx.z;
    const int h0 = hp * 2;
    const int tid = threadIdx.x, w = tid >> 5, lane = tid & 31;
    const int g = lane >> 2, q4 = lane & 3;
    const int jrow = ((lane >> 4) & 1) * 8 + (lane & 7);
    const int ksel = ((lane >> 3) & 1) * 8;
    const int arow = ((lane >> 3) & 1) * 8 + (lane & 7);
    const int akse = (lane >> 4) * 8;

    // stage Q for both heads + K/V tile 0 (one cp.async group)
    #pragma unroll
    for (int p = 0; p < 2; ++p) {
        const __half* qsrc = qh + ((size_t)b*SS + (size_t)(h0+p)*64 + (size_t)qt*4) * NQ;
        #pragma unroll
        for (int t = 0; t < 8; ++t) {
            int e = tid + t*256, r = e >> 4, c = e & 15;
            cp16(smb + p*QBYTES + r*QROWB + c*16, qsrc + (size_t)r*DHH + c*8);
        }
    }
    load_tile(kvb, b, 0, kh, vt, tid);
    CP_COMMIT();
    load_tile(kvb + BUF, b, 1, kh, vt, tid);
    CP_COMMIT();

    float o[2][16][4];
    #pragma unroll
    for (int p = 0; p < 2; ++p)
        #pragma unroll
        for (int n = 0; n < 16; ++n)
            #pragma unroll
            for (int i = 0; i < 4; ++i) o[p][n][i] = 0.f;
    float rsum[2][4] = {};
    const uint32_t onesB[2] = {0x3C003C00u, 0x3C003C00u};

    for (int kt = 0; kt < NT; ++kt) {
        if (kt + 1 < NT) { CP_WAIT1(); } else { CP_WAIT0(); }
        __syncthreads();
        if (kt + 2 < NT) {
            load_tile(kvb + (uint32_t)((kt+2)%3)*BUF, b, kt+2, kh, vt, tid);
            CP_COMMIT();
        }

        const uint32_t Kb = kvb + (uint32_t)(kt%3)*BUF + jrow*KROWB + ksel*2;
        const uint32_t Vb = kvb + (uint32_t)(kt%3)*BUF + KBYTES + jrow*VROWB + ksel*2;

        #pragma unroll
        for (int p = 0; p < 2; ++p) {
            const uint32_t Qb = smb + p*QBYTES + (w*16 + arow)*QROWB + akse*2;

            // S = Q K^T (log2 domain; scale baked into Q)
            float s[8][4];
            #pragma unroll
            for (int j = 0; j < 8; ++j)
                #pragma unroll
                for (int i = 0; i < 4; ++i) s[j][i] = 0.f;
            #pragma unroll
            for (int ks = 0; ks < 8; ++ks) {
                uint32_t aF[4];
                ldsm4(aF, Qb + 32*ks);
                uint32_t bb[2][4];
                ldsm4(bb[0], Kb + 32*ks);
                #pragma unroll
                for (int jp = 0; jp < 4; ++jp) {
                    if (jp < 3) ldsm4(bb[(jp+1)&1], Kb + (jp+1)*16*KROWB + 32*ks);
                    mma16816(s[2*jp],   aF, bb[jp&1]);
                    mma16816(s[2*jp+1], aF, bb[jp&1] + 2);
                }
            }

            // p = 2^s, pack fp16 fragments
            uint32_t ph[4][4];
            #pragma unroll
            for (int j = 0; j < 8; ++j) {
                float p0 = ex2f(s[j][0]);
                float p1 = ex2f(s[j][1]);
                float p2 = ex2f(s[j][2]);
                float p3 = ex2f(s[j][3]);
                ph[j>>1][(j&1)*2]     = packh2(p0, p1);
                ph[j>>1][(j&1)*2 + 1] = packh2(p2, p3);
            }

            // O += P V ; rowsum += P @ ones
            #pragma unroll
            for (int ks = 0; ks < 4; ++ks) {
                uint32_t bb[2][4];
                ldsm4(bb[0], Vb + 32*ks);
                #pragma unroll
                for (int np = 0; np < 8; ++np) {
                    if (np < 7) ldsm4(bb[(np+1)&1], Vb + (np+1)*16*VROWB + 32*ks);
                    mma16816(o[p][2*np],   ph[ks], bb[np&1]);
                    mma16816(o[p][2*np+1], ph[ks], bb[np&1] + 2);
                }
                mma16816(rsum[p], ph[ks], onesB);
            }
        }
    }

    const int r0 = w*16 + g, r1 = r0 + 8;
    #pragma unroll
    for (int p = 0; p < 2; ++p) {
        const float inv0 = 1.0f / rsum[p][0], inv1 = 1.0f / rsum[p][2];
        __half* dst0 = o2h + ((size_t)b*SS + (size_t)qt*TQ + r0) * NQ + (size_t)(h0+p) * DHH;
        __half* dst1 = o2h + ((size_t)b*SS + (size_t)qt*TQ + r1) * NQ + (size_t)(h0+p) * DHH;
        #pragma unroll
        for (int n = 0; n < 16; ++n) {
            int c = 8*n + 2*q4;
            *reinterpret_cast<__half2*>(dst0 + c) = __floats2half2_rn(o[p][n][0]*inv0, o[p][n][1]*inv0);
            *reinterpret_cast<__half2*>(dst1 + c) = __floats2half2_rn(o[p][n][2]*inv1, o[p][n][3]*inv1);
        }
    }
}

// ---------------------------------------------------------------------------
extern "C" void kernel_launch(void* const* d_in, const int* in_sizes, int n_in,
                              void* d_out, int out_size)
{
    const float* query  = (const float*)d_in[0];
    const float* key    = (const float*)d_in[1];
    const float* values = (const float*)d_in[2];
    const float* W_q = (const float*)d_in[3];
    const float* b_q = (const float*)d_in[4];
    const float* W_k = (const float*)d_in[5];
    const float* b_k = (const float*)d_in[6];
    const float* W_v = (const float*)d_in[7];
    const float* b_v = (const float*)d_in[8];
    const float* W_o = (const float*)d_in[9];
    const float* b_o = (const float*)d_in[10];
    float* out = (float*)d_out;

    float *pp;
    __half *xh, *xkh, *xvh, *wqT, *wkT, *wvT, *woT, *qhp, *khp, *vhp, *vtp, *ah;
    cudaGetSymbolAddress((void**)&pp,  g_part);
    cudaGetSymbolAddress((void**)&xh,  g_xh);
    cudaGetSymbolAddress((void**)&xkh, g_xkh);
    cudaGetSymbolAddress((void**)&xvh, g_xvh);
    cudaGetSymbolAddress((void**)&wqT, g_wqT);
    cudaGetSymbolAddress((void**)&wkT, g_wkT);
    cudaGetSymbolAddress((void**)&wvT, g_wvT);
    cudaGetSymbolAddress((void**)&woT, g_woT);
    cudaGetSymbolAddress((void**)&qhp, g_qh);
    cudaGetSymbolAddress((void**)&khp, g_kh);
    cudaGetSymbolAddress((void**)&vhp, g_vh);
    cudaGetSymbolAddress((void**)&vtp, g_vt);
    cudaGetSymbolAddress((void**)&ah,  g_attnh);

    cudaFuncSetAttribute(attn_hmma, cudaFuncAttributeMaxDynamicSharedMemorySize, SMEM_DYN);

    const float scl2 = 0.12753102189093095f;   // log2(e)/sqrt(128)

    // fp16 inputs + transposed fp16 weights
    conv_h<<<(BSZ*DHH + 255)/256, 256>>>(query,  xh,  BSZ*DHH);
    conv_h<<<(BSZ*DHH + 255)/256, 256>>>(key,    xkh, BSZ*DHH);
    conv_h<<<(BSZ*DHH + 255)/256, 256>>>(values, xvh, BSZ*DHH);
    transpose_w<<<dim3(NQ/32,  DHH/32), 256>>>(W_q, wqT, DHH, NQ);
    transpose_w<<<dim3(DHH/32, DHH/32), 256>>>(W_k, wkT, DHH, DHH);
    transpose_w<<<dim3(DHH/32, DHH/32), 256>>>(W_v, wvT, DHH, DHH);
    transpose_w<<<dim3(DHH/32, NQ/32),  256>>>(W_o, woT, NQ, DHH);

    // projections (all HMMA fp16)
    hgemm<1><<<dim3(NQ/128,  BSZ/128), 256>>>(xh,  wqT, b_q, qhp, BSZ, NQ,  DHH, scl2);
    hgemm<1><<<dim3(DHH/128, BSZ/128), 256>>>(xkh, wkT, b_k, khp, BSZ, DHH, DHH, 1.0f);
    hgemm<1><<<dim3(DHH/128, BSZ/128), 256>>>(xvh, wvT, b_v, vhp, BSZ, DHH, DHH, 1.0f);
    conv_vt_h<<<dim3(SS/64, DHH/4, BB), 256>>>(vhp, vtp);

    // attention (2 heads per CTA)
    attn_hmma<<<dim3(SS/TQ, HH/2, BB), 256, SMEM_DYN>>>(qhp, khp, vtp, ah);

    // O projection: split-K HMMA + reduce
    hgemm_splitk<<<dim3(DHH/128, BSZ/128, OSPLIT), 256>>>(ah, woT, pp, BSZ, DHH, NQ);
    reduce_bias<<<(BSZ*DHH/4 + 255)/256, 256>>>(pp, b_o, out, BSZ*DHH, DHH);
}

// round 9
// speedup vs baseline: 9.3665x; 1.0162x over previous
#include <cuda_runtime.h>
#include <cuda_fp16.h>
#include <math.h>
#include <stdint.h>

#define BB 2
#define SS 2048
#define HH 32
#define DHH 128
#define NQ 4096
#define BSZ 4096
#define TK 64
#define NT 32
#define OSPLIT 8

// -------- scratch --------
__device__ float  g_part [OSPLIT*BSZ*DHH];
__device__ __half g_xh   [BSZ*DHH];
__device__ __half g_xkh  [BSZ*DHH];
__device__ __half g_xvh  [BSZ*DHH];
__device__ __half g_wqT  [NQ*DHH];
__device__ __half g_wkT  [DHH*DHH];
__device__ __half g_wvT  [DHH*DHH];
__device__ __half g_woT  [DHH*NQ];
__device__ __half g_qh   [BSZ*NQ];           // Q proj, log2e/sqrt(d) pre-scaled
__device__ __half g_kh   [BSZ*DHH];
__device__ __half g_vh   [BSZ*DHH];
__device__ __half g_vt   [BB*DHH*SS];
__device__ __half g_attnh[BSZ*NQ];

// -------- helpers --------
__device__ __forceinline__ uint32_t smem_u32(const void* p){
    uint32_t a;
    asm("{ .reg .u64 t; cvta.to.shared.u64 t, %1; cvt.u32.u64 %0, t; }" : "=r"(a) : "l"(p));
    return a;
}
__device__ __forceinline__ void cp16(uint32_t dst, const void* src){
    asm volatile("cp.async.cg.shared.global [%0], [%1], 16;" :: "r"(dst), "l"(src));
}
#define CP_COMMIT() asm volatile("cp.async.commit_group;" ::: "memory")
#define CP_WAIT1()  asm volatile("cp.async.wait_group 1;" ::: "memory")
#define CP_WAIT0()  asm volatile("cp.async.wait_group 0;" ::: "memory")

__device__ __forceinline__ void mma16816(float* c, const uint32_t* a, const uint32_t* b){
    asm volatile("mma.sync.aligned.m16n8k16.row.col.f32.f16.f16.f32 "
        "{%0,%1,%2,%3}, {%4,%5,%6,%7}, {%8,%9}, {%0,%1,%2,%3};"
        : "+f"(c[0]), "+f"(c[1]), "+f"(c[2]), "+f"(c[3])
        : "r"(a[0]), "r"(a[1]), "r"(a[2]), "r"(a[3]), "r"(b[0]), "r"(b[1]));
}
__device__ __forceinline__ void ldsm4(uint32_t* r, uint32_t a){
    asm volatile("ldmatrix.sync.aligned.m8n8.x4.shared.b16 {%0,%1,%2,%3}, [%4];"
        : "=r"(r[0]), "=r"(r[1]), "=r"(r[2]), "=r"(r[3]) : "r"(a));
}
__device__ __forceinline__ float ex2f(float x){
    float r;
    asm("ex2.approx.f32 %0, %1;" : "=f"(r) : "f"(x));
    return r;
}
__device__ __forceinline__ uint32_t packh2(float x, float y){
    __half2 h = __floats2half2_rn(x, y);
    return *reinterpret_cast<uint32_t*>(&h);
}

// =======================================================================
// fp16 HMMA GEMM (full-K): C = (A @ Bt^T + bias) * scale
// =======================================================================
template<int OUT_HALF>
__global__ __launch_bounds__(256) void hgemm(
    const __half* __restrict__ A, const __half* __restrict__ Bt,
    const float* __restrict__ bias, void* __restrict__ Cv,
    int M, int N, int K, float scale)
{
    __shared__ __align__(16) __half As[2][128*40];
    __shared__ __align__(16) __half Bs[2][128*40];
    const int tid = threadIdx.x, lane = tid & 31, w = tid >> 5;
    const int wm = (w >> 2) * 64, wn = (w & 3) * 32;
    const int m0 = blockIdx.y * 128, n0 = blockIdx.x * 128;
    const int g = lane >> 2, q4 = lane & 3;
    const int arow = ((lane >> 3) & 1) * 8 + (lane & 7);
    const int akse = (lane >> 4) * 8;
    const int brow = ((lane >> 4) & 1) * 8 + (lane & 7);
    const int bkse = ((lane >> 3) & 1) * 8;

    float acc[4][4][4] = {};
    const int nk = K / 32;

    auto load = [&](int kb, int st){
        #pragma unroll
        for (int i = 0; i < 2; ++i) {
            int e = tid + 256*i, r = e >> 2, c = e & 3;
            cp16(smem_u32(&As[st][r*40 + c*8]), A  + (size_t)(m0 + r)*K + kb*32 + c*8);
            cp16(smem_u32(&Bs[st][r*40 + c*8]), Bt + (size_t)(n0 + r)*K + kb*32 + c*8);
        }
    };
    load(0, 0); CP_COMMIT();

    for (int kb = 0; kb < nk; ++kb) {
        if (kb + 1 < nk) { load(kb+1, (kb+1)&1); CP_COMMIT(); CP_WAIT1(); }
        else             { CP_WAIT0(); }
        __syncthreads();
        const int st = kb & 1;
        const uint32_t aB = smem_u32(&As[st][0]) + (wm + arow)*80 + akse*2;
        const uint32_t bB = smem_u32(&Bs[st][0]) + (wn + brow)*80 + bkse*2;
        #pragma unroll
        for (int ks = 0; ks < 2; ++ks) {
            uint32_t aF[4][4], bF[2][4];
            #pragma unroll
            for (int mi = 0; mi < 4; ++mi) ldsm4(aF[mi], aB + mi*16*80 + ks*32);
            #pragma unroll
            for (int np = 0; np < 2; ++np) ldsm4(bF[np], bB + np*16*80 + ks*32);
            #pragma unroll
            for (int mi = 0; mi < 4; ++mi)
                #pragma unroll
                for (int ni = 0; ni < 4; ++ni)
                    mma16816(acc[mi][ni], aF[mi], bF[ni>>1] + (ni&1)*2);
        }
        __syncthreads();
    }

    #pragma unroll
    for (int mi = 0; mi < 4; ++mi) {
        #pragma unroll
        for (int ni = 0; ni < 4; ++ni) {
            int row = m0 + wm + mi*16 + g;
            int col = n0 + wn + ni*8 + 2*q4;
            float b0 = bias[col], b1 = bias[col+1];
            float c0 = (acc[mi][ni][0] + b0)*scale, c1 = (acc[mi][ni][1] + b1)*scale;
            float c2 = (acc[mi][ni][2] + b0)*scale, c3 = (acc[mi][ni][3] + b1)*scale;
            if (OUT_HALF) {
                __half* C = (__half*)Cv;
                *reinterpret_cast<__half2*>(C + (size_t)row*N + col)     = __floats2half2_rn(c0, c1);
                *reinterpret_cast<__half2*>(C + (size_t)(row+8)*N + col) = __floats2half2_rn(c2, c3);
            } else {
                float* C = (float*)Cv;
                *reinterpret_cast<float2*>(C + (size_t)row*N + col)     = make_float2(c0, c1);
                *reinterpret_cast<float2*>(C + (size_t)(row+8)*N + col) = make_float2(c2, c3);
            }
        }
    }
}

// ---- split-K hgemm + reduce (O projection) ----
__global__ __launch_bounds__(256) void hgemm_splitk(
    const __half* __restrict__ A, const __half* __restrict__ Bt,
    float* __restrict__ part, int M, int N, int K)
{
    __shared__ __align__(16) __half As[2][128*40];
    __shared__ __align__(16) __half Bs[2][128*40];
    const int tid = threadIdx.x, lane = tid & 31, w = tid >> 5;
    const int wm = (w >> 2) * 64, wn = (w & 3) * 32;
    const int m0 = blockIdx.y * 128, n0 = blockIdx.x * 128;
    const int kc = blockIdx.z;
    const int g = lane >> 2, q4 = lane & 3;
    const int arow = ((lane >> 3) & 1) * 8 + (lane & 7);
    const int akse = (lane >> 4) * 8;
    const int brow = ((lane >> 4) & 1) * 8 + (lane & 7);
    const int bkse = ((lane >> 3) & 1) * 8;

    float acc[4][4][4] = {};
    const int nkpc = K / 32 / OSPLIT;
    const int kb0 = kc * nkpc;

    auto load = [&](int kb, int st){
        #pragma unroll
        for (int i = 0; i < 2; ++i) {
            int e = tid + 256*i, r = e >> 2, c = e & 3;
            cp16(smem_u32(&As[st][r*40 + c*8]), A  + (size_t)(m0 + r)*K + kb*32 + c*8);
            cp16(smem_u32(&Bs[st][r*40 + c*8]), Bt + (size_t)(n0 + r)*K + kb*32 + c*8);
        }
    };
    load(kb0, 0); CP_COMMIT();

    for (int i = 0; i < nkpc; ++i) {
        if (i + 1 < nkpc) { load(kb0+i+1, (i+1)&1); CP_COMMIT(); CP_WAIT1(); }
        else              { CP_WAIT0(); }
        __syncthreads();
        const int st = i & 1;
        const uint32_t aB = smem_u32(&As[st][0]) + (wm + arow)*80 + akse*2;
        const uint32_t bB = smem_u32(&Bs[st][0]) + (wn + brow)*80 + bkse*2;
        #pragma unroll
        for (int ks = 0; ks < 2; ++ks) {
            uint32_t aF[4][4], bF[2][4];
            #pragma unroll
            for (int mi = 0; mi < 4; ++mi) ldsm4(aF[mi], aB + mi*16*80 + ks*32);
            #pragma unroll
            for (int np = 0; np < 2; ++np) ldsm4(bF[np], bB + np*16*80 + ks*32);
            #pragma unroll
            for (int mi = 0; mi < 4; ++mi)
                #pragma unroll
                for (int ni = 0; ni < 4; ++ni)
                    mma16816(acc[mi][ni], aF[mi], bF[ni>>1] + (ni&1)*2);
        }
        __syncthreads();
    }

    float* P = part + (size_t)kc * M * N;
    #pragma unroll
    for (int mi = 0; mi < 4; ++mi)
        #pragma unroll
        for (int ni = 0; ni < 4; ++ni) {
            int row = m0 + wm + mi*16 + g;
            int col = n0 + wn + ni*8 + 2*q4;
            *reinterpret_cast<float2*>(P + (size_t)row*N + col)     = make_float2(acc[mi][ni][0], acc[mi][ni][1]);
            *reinterpret_cast<float2*>(P + (size_t)(row+8)*N + col) = make_float2(acc[mi][ni][2], acc[mi][ni][3]);
        }
}

__global__ void reduce_bias(const float* __restrict__ part, const float* __restrict__ bias,
                            float* __restrict__ out, int MN, int N)
{
    int i = (blockIdx.x * 256 + threadIdx.x) * 4;
    if (i >= MN) return;
    float4 s = *reinterpret_cast<const float4*>(part + i);
    #pragma unroll
    for (int kc = 1; kc < OSPLIT; ++kc) {
        float4 p = *reinterpret_cast<const float4*>(part + (size_t)kc*MN + i);
        s.x += p.x; s.y += p.y; s.z += p.z; s.w += p.w;
    }
    int c = i & (N - 1);
    s.x += bias[c]; s.y += bias[c+1]; s.z += bias[c+2]; s.w += bias[c+3];
    *reinterpret_cast<float4*>(out + i) = s;
}

// -------- converts / transposes --------
__global__ void conv_h(const float* __restrict__ in, __half* __restrict__ out, int n){
    int i = blockIdx.x * 256 + threadIdx.x;
    if (i < n) out[i] = __float2half_rn(in[i]);
}
__global__ void conv_vt_h(const __half* __restrict__ v, __half* __restrict__ ot){
    int s = blockIdx.x * 64 + (threadIdx.x & 63);
    int d = blockIdx.y * 4 + (threadIdx.x >> 6);
    int b = blockIdx.z;
    ot[((size_t)b*DHH + d)*SS + s] = v[((size_t)b*SS + s)*DHH + d];
}
__global__ void transpose_w(const float* __restrict__ in, __half* __restrict__ out, int K, int N){
    __shared__ float t[32][33];
    int bx = blockIdx.x*32, by = blockIdx.y*32;
    int x = threadIdx.x & 31, y = threadIdx.x >> 5;
    #pragma unroll
    for (int i = 0; i < 4; ++i)
        t[y + 8*i][x] = in[(size_t)(by + y + 8*i)*N + bx + x];
    __syncthreads();
    #pragma unroll
    for (int i = 0; i < 4; ++i)
        out[(size_t)(bx + y + 8*i)*K + by + x] = __float2half_rn(t[x][y + 8*i]);
}

// =======================================================================
// HMMA flash attention — M=32 per warp (256 q-rows/CTA) to halve LDS/work
// =======================================================================
#define KROWB 272
#define VROWB 144
#define KBYTES (64*KROWB)
#define VBYTES (128*VROWB)
#define BUF    (KBYTES+VBYTES)
#define QROWB  272
#define QROWS  256
#define QBYTES (QROWS*QROWB)          // 69632
#define SMEM_DYN (QBYTES + 3*BUF)     // 177152

__device__ __forceinline__ void load_tile(uint32_t buf, int b, int kt,
    const __half* kh, const __half* vt, int tid)
{
    const __half* ks = kh + ((size_t)b*SS + (size_t)kt*TK) * DHH;
    #pragma unroll
    for (int t = 0; t < 4; ++t) {
        int e = tid + t*256, r = e >> 4, c = e & 15;
        cp16(buf + r*KROWB + c*16, ks + (size_t)r*DHH + c*8);
    }
    const __half* vs = vt + (size_t)b*DHH*SS + (size_t)kt*TK;
    #pragma unroll
    for (int t = 0; t < 4; ++t) {
        int e = tid + t*256, d = e >> 3, c = e & 7;
        cp16(buf + KBYTES + d*VROWB + c*16, vs + (size_t)d*SS + c*8);
    }
}

__global__ __launch_bounds__(256, 1) void attn_hmma(
    const __half* __restrict__ qh, const __half* __restrict__ kh,
    const __half* __restrict__ vt, __half* __restrict__ o2h)
{
    extern __shared__ __align__(16) char smraw[];
    const uint32_t smb = smem_u32(smraw);        // Q block
    const uint32_t kvb = smb + QBYTES;           // K/V stages
    const int qb = blockIdx.x, h = blockIdx.y, b = blockIdx.z;
    const int tid = threadIdx.x, w = tid >> 5, lane = tid & 31;
    const int g = lane >> 2, q4 = lane & 3;
    const int jrow = ((lane >> 4) & 1) * 8 + (lane & 7);
    const int ksel = ((lane >> 3) & 1) * 8;
    const int arow = ((lane >> 3) & 1) * 8 + (lane & 7);
    const int akse = (lane >> 4) * 8;

    // stage Q (256 rows, contiguous in qh) + K/V tile 0 into group0
    {
        const __half* qsrc = qh + ((size_t)b*SS + (size_t)h*64 + (size_t)qb*8) * NQ;
        #pragma unroll
        for (int t = 0; t < 16; ++t) {
            int e = tid + t*256, r = e >> 4, c = e & 15;
            cp16(smb + r*QROWB + c*16, qsrc + (size_t)r*DHH + c*8);
        }
    }
    load_tile(kvb, b, 0, kh, vt, tid);
    CP_COMMIT();
    load_tile(kvb + BUF, b, 1, kh, vt, tid);
    CP_COMMIT();

    float o[2][16][4];
    #pragma unroll
    for (int m = 0; m < 2; ++m)
        #pragma unroll
        for (int n = 0; n < 16; ++n)
            #pragma unroll
            for (int i = 0; i < 4; ++i) o[m][n][i] = 0.f;
    float rsum[2][4] = {};
    const uint32_t onesB[2] = {0x3C003C00u, 0x3C003C00u};
    const uint32_t Qb = smb + (w*32 + arow)*QROWB + akse*2;

    for (int kt = 0; kt < NT; ++kt) {
        if (kt + 1 < NT) { CP_WAIT1(); } else { CP_WAIT0(); }
        __syncthreads();
        if (kt + 2 < NT) {
            load_tile(kvb + (uint32_t)((kt+2)%3)*BUF, b, kt+2, kh, vt, tid);
            CP_COMMIT();
        }

        const uint32_t Kb = kvb + (uint32_t)(kt%3)*BUF + jrow*KROWB + ksel*2;
        const uint32_t Vb = kvb + (uint32_t)(kt%3)*BUF + KBYTES + jrow*VROWB + ksel*2;

        // S = Q K^T for both m-tiles (K fragments shared)
        float s[2][8][4];
        #pragma unroll
        for (int m = 0; m < 2; ++m)
            #pragma unroll
            for (int j = 0; j < 8; ++j)
                #pragma unroll
                for (int i = 0; i < 4; ++i) s[m][j][i] = 0.f;
        #pragma unroll
        for (int ks = 0; ks < 8; ++ks) {
            uint32_t aF0[4], aF1[4];
            ldsm4(aF0, Qb + 32*ks);
            ldsm4(aF1, Qb + 16*QROWB + 32*ks);
            uint32_t bb[2][4];
            ldsm4(bb[0], Kb + 32*ks);
            #pragma unroll
            for (int jp = 0; jp < 4; ++jp) {
                if (jp < 3) ldsm4(bb[(jp+1)&1], Kb + (jp+1)*16*KROWB + 32*ks);
                mma16816(s[0][2*jp],   aF0, bb[jp&1]);
                mma16816(s[0][2*jp+1], aF0, bb[jp&1] + 2);
                mma16816(s[1][2*jp],   aF1, bb[jp&1]);
                mma16816(s[1][2*jp+1], aF1, bb[jp&1] + 2);
            }
        }

        // p = 2^s, pack fp16 fragments (s dies here)
        uint32_t P[2][4][4];
        #pragma unroll
        for (int m = 0; m < 2; ++m)
            #pragma unroll
            for (int j = 0; j < 8; ++j) {
                float p0 = ex2f(s[m][j][0]);
                float p1 = ex2f(s[m][j][1]);
                float p2 = ex2f(s[m][j][2]);
                float p3 = ex2f(s[m][j][3]);
                P[m][j>>1][(j&1)*2]     = packh2(p0, p1);
                P[m][j>>1][(j&1)*2 + 1] = packh2(p2, p3);
            }

        // O += P V (V fragments shared across m-tiles); rowsum += P @ ones
        #pragma unroll
        for (int ks = 0; ks < 4; ++ks) {
            uint32_t bb[2][4];
            ldsm4(bb[0], Vb + 32*ks);
            #pragma unroll
            for (int np = 0; np < 8; ++np) {
                if (np < 7) ldsm4(bb[(np+1)&1], Vb + (np+1)*16*VROWB + 32*ks);
                mma16816(o[0][2*np],   P[0][ks], bb[np&1]);
                mma16816(o[0][2*np+1], P[0][ks], bb[np&1] + 2);
                mma16816(o[1][2*np],   P[1][ks], bb[np&1]);
                mma16816(o[1][2*np+1], P[1][ks], bb[np&1] + 2);
            }
            mma16816(rsum[0], P[0][ks], onesB);
            mma16816(rsum[1], P[1][ks], onesB);
        }
    }

    // epilogue: rows = qb*256 + w*32 + m*16 + {g, g+8}
    #pragma unroll
    for (int m = 0; m < 2; ++m) {
        const float inv0 = 1.0f / rsum[m][0], inv1 = 1.0f / rsum[m][2];
        const int lr = w*32 + m*16 + g;
        __half* dst0 = o2h + ((size_t)b*SS + (size_t)qb*QROWS + lr)     * NQ + (size_t)h * DHH;
        __half* dst1 = o2h + ((size_t)b*SS + (size_t)qb*QROWS + lr + 8) * NQ + (size_t)h * DHH;
        #pragma unroll
        for (int n = 0; n < 16; ++n) {
            int c = 8*n + 2*q4;
            *reinterpret_cast<__half2*>(dst0 + c) = __floats2half2_rn(o[m][n][0]*inv0, o[m][n][1]*inv0);
            *reinterpret_cast<__half2*>(dst1 + c) = __floats2half2_rn(o[m][n][2]*inv1, o[m][n][3]*inv1);
        }
    }
}

// ---------------------------------------------------------------------------
extern "C" void kernel_launch(void* const* d_in, const int* in_sizes, int n_in,
                              void* d_out, int out_size)
{
    const float* query  = (const float*)d_in[0];
    const float* key    = (const float*)d_in[1];
    const float* values = (const float*)d_in[2];
    const float* W_q = (const float*)d_in[3];
    const float* b_q = (const float*)d_in[4];
    const float* W_k = (const float*)d_in[5];
    const float* b_k = (const float*)d_in[6];
    const float* W_v = (const float*)d_in[7];
    const float* b_v = (const float*)d_in[8];
    const float* W_o = (const float*)d_in[9];
    const float* b_o = (const float*)d_in[10];
    float* out = (float*)d_out;

    float *pp;
    __half *xh, *xkh, *xvh, *wqT, *wkT, *wvT, *woT, *qhp, *khp, *vhp, *vtp, *ah;
    cudaGetSymbolAddress((void**)&pp,  g_part);
    cudaGetSymbolAddress((void**)&xh,  g_xh);
    cudaGetSymbolAddress((void**)&xkh, g_xkh);
    cudaGetSymbolAddress((void**)&xvh, g_xvh);
    cudaGetSymbolAddress((void**)&wqT, g_wqT);
    cudaGetSymbolAddress((void**)&wkT, g_wkT);
    cudaGetSymbolAddress((void**)&wvT, g_wvT);
    cudaGetSymbolAddress((void**)&woT, g_woT);
    cudaGetSymbolAddress((void**)&qhp, g_qh);
    cudaGetSymbolAddress((void**)&khp, g_kh);
    cudaGetSymbolAddress((void**)&vhp, g_vh);
    cudaGetSymbolAddress((void**)&vtp, g_vt);
    cudaGetSymbolAddress((void**)&ah,  g_attnh);

    cudaFuncSetAttribute(attn_hmma, cudaFuncAttributeMaxDynamicSharedMemorySize, SMEM_DYN);

    const float scl2 = 0.12753102189093095f;   // log2(e)/sqrt(128)

    conv_h<<<(BSZ*DHH + 255)/256, 256>>>(query,  xh,  BSZ*DHH);
    conv_h<<<(BSZ*DHH + 255)/256, 256>>>(key,    xkh, BSZ*DHH);
    conv_h<<<(BSZ*DHH + 255)/256, 256>>>(values, xvh, BSZ*DHH);
    transpose_w<<<dim3(NQ/32,  DHH/32), 256>>>(W_q, wqT, DHH, NQ);
    transpose_w<<<dim3(DHH/32, DHH/32), 256>>>(W_k, wkT, DHH, DHH);
    transpose_w<<<dim3(DHH/32, DHH/32), 256>>>(W_v, wvT, DHH, DHH);
    transpose_w<<<dim3(DHH/32, NQ/32),  256>>>(W_o, woT, NQ, DHH);

    hgemm<1><<<dim3(NQ/128,  BSZ/128), 256>>>(xh,  wqT, b_q, qhp, BSZ, NQ,  DHH, scl2);
    hgemm<1><<<dim3(DHH/128, BSZ/128), 256>>>(xkh, wkT, b_k, khp, BSZ, DHH, DHH, 1.0f);
    hgemm<1><<<dim3(DHH/128, BSZ/128), 256>>>(xvh, wvT, b_v, vhp, BSZ, DHH, DHH, 1.0f);
    conv_vt_h<<<dim3(SS/64, DHH/4, BB), 256>>>(vhp, vtp);

    // attention: 256 q-rows per CTA, M=32 per warp
    attn_hmma<<<dim3(SS/QROWS, HH, BB), 256, SMEM_DYN>>>(qhp, khp, vtp, ah);

    hgemm_splitk<<<dim3(DHH/128, BSZ/128, OSPLIT), 256>>>(ah, woT, pp, BSZ, DHH, NQ);
    reduce_bias<<<(BSZ*DHH/4 + 255)/256, 256>>>(pp, b_o, out, BSZ*DHH, DHH);
}

// round 10
// speedup vs baseline: 9.8685x; 1.0536x over previous
#include <cuda_runtime.h>
#include <cuda_fp16.h>
#include <math.h>
#include <stdint.h>

#define BB 2
#define SS 2048
#define HH 32
#define DHH 128
#define NQ 4096
#define BSZ 4096
#define TK 64
#define NT 32
#define OSPLIT 8

// -------- scratch --------
__device__ float  g_part [OSPLIT*BSZ*DHH];
__device__ __half g_xh   [BSZ*DHH];
__device__ __half g_xkh  [BSZ*DHH];
__device__ __half g_xvh  [BSZ*DHH];
__device__ __half g_wqT  [NQ*DHH];
__device__ __half g_wkT  [DHH*DHH];
__device__ __half g_wvT  [DHH*DHH];
__device__ __half g_woT  [DHH*NQ];
__device__ __half g_qh   [BSZ*NQ];           // Q proj, log2e/sqrt(d) pre-scaled
__device__ __half g_kh   [BSZ*DHH];          // K proj fp16 [b][s][d]
__device__ __half g_vh   [BSZ*DHH];          // V proj fp16 [b][s][d]
__device__ __half g_attnh[BSZ*NQ];

// -------- helpers --------
__device__ __forceinline__ uint32_t smem_u32(const void* p){
    uint32_t a;
    asm("{ .reg .u64 t; cvta.to.shared.u64 t, %1; cvt.u32.u64 %0, t; }" : "=r"(a) : "l"(p));
    return a;
}
__device__ __forceinline__ void cp16(uint32_t dst, const void* src){
    asm volatile("cp.async.cg.shared.global [%0], [%1], 16;" :: "r"(dst), "l"(src));
}
#define CP_COMMIT() asm volatile("cp.async.commit_group;" ::: "memory")
#define CP_WAIT1()  asm volatile("cp.async.wait_group 1;" ::: "memory")
#define CP_WAIT0()  asm volatile("cp.async.wait_group 0;" ::: "memory")

__device__ __forceinline__ void mma16816(float* c, const uint32_t* a, const uint32_t* b){
    asm volatile("mma.sync.aligned.m16n8k16.row.col.f32.f16.f16.f32 "
        "{%0,%1,%2,%3}, {%4,%5,%6,%7}, {%8,%9}, {%0,%1,%2,%3};"
        : "+f"(c[0]), "+f"(c[1]), "+f"(c[2]), "+f"(c[3])
        : "r"(a[0]), "r"(a[1]), "r"(a[2]), "r"(a[3]), "r"(b[0]), "r"(b[1]));
}
__device__ __forceinline__ void ldsm4(uint32_t* r, uint32_t a){
    asm volatile("ldmatrix.sync.aligned.m8n8.x4.shared.b16 {%0,%1,%2,%3}, [%4];"
        : "=r"(r[0]), "=r"(r[1]), "=r"(r[2]), "=r"(r[3]) : "r"(a));
}
__device__ __forceinline__ void ldsm4t(uint32_t* r, uint32_t a){
    asm volatile("ldmatrix.sync.aligned.m8n8.x4.trans.shared.b16 {%0,%1,%2,%3}, [%4];"
        : "=r"(r[0]), "=r"(r[1]), "=r"(r[2]), "=r"(r[3]) : "r"(a));
}
__device__ __forceinline__ uint32_t packh2(float x, float y){
    __half2 h = __floats2half2_rn(x, y);
    return *reinterpret_cast<uint32_t*>(&h);
}
__device__ __forceinline__ uint32_t ex2x2(uint32_t h){
    uint32_t r;
    asm("ex2.approx.f16x2 %0, %1;" : "=r"(r) : "r"(h));
    return r;
}

// =======================================================================
// fp16 HMMA GEMM (full-K): C = (A @ Bt^T + bias) * scale
// =======================================================================
template<int OUT_HALF>
__global__ __launch_bounds__(256) void hgemm(
    const __half* __restrict__ A, const __half* __restrict__ Bt,
    const float* __restrict__ bias, void* __restrict__ Cv,
    int M, int N, int K, float scale)
{
    __shared__ __align__(16) __half As[2][128*40];
    __shared__ __align__(16) __half Bs[2][128*40];
    const int tid = threadIdx.x, lane = tid & 31, w = tid >> 5;
    const int wm = (w >> 2) * 64, wn = (w & 3) * 32;
    const int m0 = blockIdx.y * 128, n0 = blockIdx.x * 128;
    const int g = lane >> 2, q4 = lane & 3;
    const int arow = ((lane >> 3) & 1) * 8 + (lane & 7);
    const int akse = (lane >> 4) * 8;
    const int brow = ((lane >> 4) & 1) * 8 + (lane & 7);
    const int bkse = ((lane >> 3) & 1) * 8;

    float acc[4][4][4] = {};
    const int nk = K / 32;

    auto load = [&](int kb, int st){
        #pragma unroll
        for (int i = 0; i < 2; ++i) {
            int e = tid + 256*i, r = e >> 2, c = e & 3;
            cp16(smem_u32(&As[st][r*40 + c*8]), A  + (size_t)(m0 + r)*K + kb*32 + c*8);
            cp16(smem_u32(&Bs[st][r*40 + c*8]), Bt + (size_t)(n0 + r)*K + kb*32 + c*8);
        }
    };
    load(0, 0); CP_COMMIT();

    for (int kb = 0; kb < nk; ++kb) {
        if (kb + 1 < nk) { load(kb+1, (kb+1)&1); CP_COMMIT(); CP_WAIT1(); }
        else             { CP_WAIT0(); }
        __syncthreads();
        const int st = kb & 1;
        const uint32_t aB = smem_u32(&As[st][0]) + (wm + arow)*80 + akse*2;
        const uint32_t bB = smem_u32(&Bs[st][0]) + (wn + brow)*80 + bkse*2;
        #pragma unroll
        for (int ks = 0; ks < 2; ++ks) {
            uint32_t aF[4][4], bF[2][4];
            #pragma unroll
            for (int mi = 0; mi < 4; ++mi) ldsm4(aF[mi], aB + mi*16*80 + ks*32);
            #pragma unroll
            for (int np = 0; np < 2; ++np) ldsm4(bF[np], bB + np*16*80 + ks*32);
            #pragma unroll
            for (int mi = 0; mi < 4; ++mi)
                #pragma unroll
                for (int ni = 0; ni < 4; ++ni)
                    mma16816(acc[mi][ni], aF[mi], bF[ni>>1] + (ni&1)*2);
        }
        __syncthreads();
    }

    #pragma unroll
    for (int mi = 0; mi < 4; ++mi) {
        #pragma unroll
        for (int ni = 0; ni < 4; ++ni) {
            int row = m0 + wm + mi*16 + g;
            int col = n0 + wn + ni*8 + 2*q4;
            float b0 = bias[col], b1 = bias[col+1];
            float c0 = (acc[mi][ni][0] + b0)*scale, c1 = (acc[mi][ni][1] + b1)*scale;
            float c2 = (acc[mi][ni][2] + b0)*scale, c3 = (acc[mi][ni][3] + b1)*scale;
            if (OUT_HALF) {
                __half* C = (__half*)Cv;
                *reinterpret_cast<__half2*>(C + (size_t)row*N + col)     = __floats2half2_rn(c0, c1);
                *reinterpret_cast<__half2*>(C + (size_t)(row+8)*N + col) = __floats2half2_rn(c2, c3);
            } else {
                float* C = (float*)Cv;
                *reinterpret_cast<float2*>(C + (size_t)row*N + col)     = make_float2(c0, c1);
                *reinterpret_cast<float2*>(C + (size_t)(row+8)*N + col) = make_float2(c2, c3);
            }
        }
    }
}

// ---- split-K hgemm + reduce (O projection) ----
__global__ __launch_bounds__(256) void hgemm_splitk(
    const __half* __restrict__ A, const __half* __restrict__ Bt,
    float* __restrict__ part, int M, int N, int K)
{
    __shared__ __align__(16) __half As[2][128*40];
    __shared__ __align__(16) __half Bs[2][128*40];
    const int tid = threadIdx.x, lane = tid & 31, w = tid >> 5;
    const int wm = (w >> 2) * 64, wn = (w & 3) * 32;
    const int m0 = blockIdx.y * 128, n0 = blockIdx.x * 128;
    const int kc = blockIdx.z;
    const int g = lane >> 2, q4 = lane & 3;
    const int arow = ((lane >> 3) & 1) * 8 + (lane & 7);
    const int akse = (lane >> 4) * 8;
    const int brow = ((lane >> 4) & 1) * 8 + (lane & 7);
    const int bkse = ((lane >> 3) & 1) * 8;

    float acc[4][4][4] = {};
    const int nkpc = K / 32 / OSPLIT;
    const int kb0 = kc * nkpc;

    auto load = [&](int kb, int st){
        #pragma unroll
        for (int i = 0; i < 2; ++i) {
            int e = tid + 256*i, r = e >> 2, c = e & 3;
            cp16(smem_u32(&As[st][r*40 + c*8]), A  + (size_t)(m0 + r)*K + kb*32 + c*8);
            cp16(smem_u32(&Bs[st][r*40 + c*8]), Bt + (size_t)(n0 + r)*K + kb*32 + c*8);
        }
    };
    load(kb0, 0); CP_COMMIT();

    for (int i = 0; i < nkpc; ++i) {
        if (i + 1 < nkpc) { load(kb0+i+1, (i+1)&1); CP_COMMIT(); CP_WAIT1(); }
        else              { CP_WAIT0(); }
        __syncthreads();
        const int st = i & 1;
        const uint32_t aB = smem_u32(&As[st][0]) + (wm + arow)*80 + akse*2;
        const uint32_t bB = smem_u32(&Bs[st][0]) + (wn + brow)*80 + bkse*2;
        #pragma unroll
        for (int ks = 0; ks < 2; ++ks) {
            uint32_t aF[4][4], bF[2][4];
            #pragma unroll
            for (int mi = 0; mi < 4; ++mi) ldsm4(aF[mi], aB + mi*16*80 + ks*32);
            #pragma unroll
            for (int np = 0; np < 2; ++np) ldsm4(bF[np], bB + np*16*80 + ks*32);
            #pragma unroll
            for (int mi = 0; mi < 4; ++mi)
                #pragma unroll
                for (int ni = 0; ni < 4; ++ni)
                    mma16816(acc[mi][ni], aF[mi], bF[ni>>1] + (ni&1)*2);
        }
        __syncthreads();
    }

    float* P = part + (size_t)kc * M * N;
    #pragma unroll
    for (int mi = 0; mi < 4; ++mi)
        #pragma unroll
        for (int ni = 0; ni < 4; ++ni) {
            int row = m0 + wm + mi*16 + g;
            int col = n0 + wn + ni*8 + 2*q4;
            *reinterpret_cast<float2*>(P + (size_t)row*N + col)     = make_float2(acc[mi][ni][0], acc[mi][ni][1]);
            *reinterpret_cast<float2*>(P + (size_t)(row+8)*N + col) = make_float2(acc[mi][ni][2], acc[mi][ni][3]);
        }
}

__global__ void reduce_bias(const float* __restrict__ part, const float* __restrict__ bias,
                            float* __restrict__ out, int MN, int N)
{
    int i = (blockIdx.x * 256 + threadIdx.x) * 4;
    if (i >= MN) return;
    float4 s = *reinterpret_cast<const float4*>(part + i);
    #pragma unroll
    for (int kc = 1; kc < OSPLIT; ++kc) {
        float4 p = *reinterpret_cast<const float4*>(part + (size_t)kc*MN + i);
        s.x += p.x; s.y += p.y; s.z += p.z; s.w += p.w;
    }
    int c = i & (N - 1);
    s.x += bias[c]; s.y += bias[c+1]; s.z += bias[c+2]; s.w += bias[c+3];
    *reinterpret_cast<float4*>(out + i) = s;
}

// -------- fused converts (3 arrays in one launch) --------
__global__ void conv3_h(const float4* __restrict__ q, const float4* __restrict__ k,
                        const float4* __restrict__ v,
                        uint2* __restrict__ oq, uint2* __restrict__ ok,
                        uint2* __restrict__ ov, int n4)
{
    int i = blockIdx.x * 256 + threadIdx.x;
    if (i >= n4) return;
    float4 f;
    f = q[i]; oq[i] = make_uint2(packh2(f.x, f.y), packh2(f.z, f.w));
    f = k[i]; ok[i] = make_uint2(packh2(f.x, f.y), packh2(f.z, f.w));
    f = v[i]; ov[i] = make_uint2(packh2(f.x, f.y), packh2(f.z, f.w));
}

// -------- fused weight transposes (4 matrices in one launch) --------
__global__ void transpose_all(const float* __restrict__ Wq, const float* __restrict__ Wk,
                              const float* __restrict__ Wv, const float* __restrict__ Wo,
                              __half* __restrict__ wqT, __half* __restrict__ wkT,
                              __half* __restrict__ wvT, __half* __restrict__ woT)
{
    __shared__ float t[32][33];
    int id = blockIdx.x;
    const float* in; __half* out; int K, N, tile;
    if (id < 512)      { in = Wq; out = wqT; K = DHH; N = NQ;  tile = id; }
    else if (id < 528) { in = Wk; out = wkT; K = DHH; N = DHH; tile = id - 512; }
    else if (id < 544) { in = Wv; out = wvT; K = DHH; N = DHH; tile = id - 528; }
    else               { in = Wo; out = woT; K = NQ;  N = DHH; tile = id - 544; }
    int ntx = N / 32;
    int bx = (tile % ntx) * 32, by = (tile / ntx) * 32;
    int x = threadIdx.x & 31, y = threadIdx.x >> 5;
    #pragma unroll
    for (int i = 0; i < 4; ++i)
        t[y + 8*i][x] = in[(size_t)(by + y + 8*i)*N + bx + x];
    __syncthreads();
    #pragma unroll
    for (int i = 0; i < 4; ++i)
        out[(size_t)(bx + y + 8*i)*K + by + x] = __float2half_rn(t[x][y + 8*i]);
}

// =======================================================================
// HMMA flash attention — M=32/warp, V row-major + ldmatrix.trans
// =======================================================================
#define KROWB 272
#define KBYTES (64*KROWB)             // 17408
#define BUF    (2*KBYTES)             // K + V, 34816
#define QROWB  272
#define QROWS  256
#define QBYTES (QROWS*QROWB)          // 69632
#define SMEM_DYN (QBYTES + 3*BUF)     // 174080

__device__ __forceinline__ void load_tile(uint32_t buf, int b, int kt,
    const __half* kh, const __half* vh, int tid)
{
    const __half* ks = kh + ((size_t)b*SS + (size_t)kt*TK) * DHH;
    const __half* vs = vh + ((size_t)b*SS + (size_t)kt*TK) * DHH;
    #pragma unroll
    for (int t = 0; t < 4; ++t) {
        int e = tid + t*256, r = e >> 4, c = e & 15;
        cp16(buf + r*KROWB + c*16,          ks + (size_t)r*DHH + c*8);
        cp16(buf + KBYTES + r*KROWB + c*16, vs + (size_t)r*DHH + c*8);
    }
}

__global__ __launch_bounds__(256, 1) void attn_hmma(
    const __half* __restrict__ qh, const __half* __restrict__ kh,
    const __half* __restrict__ vh, __half* __restrict__ o2h)
{
    extern __shared__ __align__(16) char smraw[];
    const uint32_t smb = smem_u32(smraw);        // Q block
    const uint32_t kvb = smb + QBYTES;           // K/V stages
    const int qb = blockIdx.x, h = blockIdx.y, b = blockIdx.z;
    const int tid = threadIdx.x, w = tid >> 5, lane = tid & 31;
    const int g = lane >> 2, q4 = lane & 3;
    const int jrow = ((lane >> 4) & 1) * 8 + (lane & 7);
    const int ksel = ((lane >> 3) & 1) * 8;
    const int arow = ((lane >> 3) & 1) * 8 + (lane & 7);
    const int akse = (lane >> 4) * 8;
    const int vrow = lane & 15;                  // s within 16-chunk (trans ldsm)
    const int vcol8 = (lane >> 4) * 8;           // d offset within 16-group

    // stage Q (256 contiguous rows) + K/V tiles 0,1
    {
        const __half* qsrc = qh + ((size_t)b*SS + (size_t)h*64 + (size_t)qb*8) * NQ;
        #pragma unroll
        for (int t = 0; t < 16; ++t) {
            int e = tid + t*256, r = e >> 4, c = e & 15;
            cp16(smb + r*QROWB + c*16, qsrc + (size_t)r*DHH + c*8);
        }
    }
    load_tile(kvb, b, 0, kh, vh, tid);
    CP_COMMIT();
    load_tile(kvb + BUF, b, 1, kh, vh, tid);
    CP_COMMIT();

    float o[2][16][4];
    #pragma unroll
    for (int m = 0; m < 2; ++m)
        #pragma unroll
        for (int n = 0; n < 16; ++n)
            #pragma unroll
            for (int i = 0; i < 4; ++i) o[m][n][i] = 0.f;
    float rsum[2][4] = {};
    const uint32_t onesB[2] = {0x3C003C00u, 0x3C003C00u};
    const uint32_t Qb = smb + (w*32 + arow)*QROWB + akse*2;

    for (int kt = 0; kt < NT; ++kt) {
        if (kt + 1 < NT) { CP_WAIT1(); } else { CP_WAIT0(); }
        __syncthreads();
        if (kt + 2 < NT) {
            load_tile(kvb + (uint32_t)((kt+2)%3)*BUF, b, kt+2, kh, vh, tid);
            CP_COMMIT();
        }

        const uint32_t Kb = kvb + (uint32_t)(kt%3)*BUF + jrow*KROWB + ksel*2;
        const uint32_t Vb = kvb + (uint32_t)(kt%3)*BUF + KBYTES + vrow*KROWB + vcol8*2;

        // S = Q K^T for both m-tiles (K fragments shared)
        float s[2][8][4];
        #pragma unroll
        for (int m = 0; m < 2; ++m)
            #pragma unroll
            for (int j = 0; j < 8; ++j)
                #pragma unroll
                for (int i = 0; i < 4; ++i) s[m][j][i] = 0.f;
        #pragma unroll
        for (int ks = 0; ks < 8; ++ks) {
            uint32_t aF0[4], aF1[4];
            ldsm4(aF0, Qb + 32*ks);
            ldsm4(aF1, Qb + 16*QROWB + 32*ks);
            uint32_t bb[2][4];
            ldsm4(bb[0], Kb + 32*ks);
            #pragma unroll
            for (int jp = 0; jp < 4; ++jp) {
                if (jp < 3) ldsm4(bb[(jp+1)&1], Kb + (jp+1)*16*KROWB + 32*ks);
                mma16816(s[0][2*jp],   aF0, bb[jp&1]);
                mma16816(s[0][2*jp+1], aF0, bb[jp&1] + 2);
                mma16816(s[1][2*jp],   aF1, bb[jp&1]);
                mma16816(s[1][2*jp+1], aF1, bb[jp&1] + 2);
            }
        }

        // P = 2^S via fp16x2 MUFU (half the MUFU ops)
        uint32_t P[2][4][4];
        #pragma unroll
        for (int m = 0; m < 2; ++m)
            #pragma unroll
            for (int j = 0; j < 8; ++j) {
                P[m][j>>1][(j&1)*2]     = ex2x2(packh2(s[m][j][0], s[m][j][1]));
                P[m][j>>1][(j&1)*2 + 1] = ex2x2(packh2(s[m][j][2], s[m][j][3]));
            }

        // O += P V (V loaded row-major, ldsm.trans); rowsum += P @ ones
        #pragma unroll
        for (int ks = 0; ks < 4; ++ks) {
            const uint32_t Vk = Vb + ks*16*KROWB;
            uint32_t bb[2][4];
            ldsm4t(bb[0], Vk);
            #pragma unroll
            for (int np = 0; np < 8; ++np) {
                if (np < 7) ldsm4t(bb[(np+1)&1], Vk + (np+1)*32);
                mma16816(o[0][2*np],   P[0][ks], bb[np&1]);
                mma16816(o[0][2*np+1], P[0][ks], bb[np&1] + 2);
                mma16816(o[1][2*np],   P[1][ks], bb[np&1]);
                mma16816(o[1][2*np+1], P[1][ks], bb[np&1] + 2);
            }
            mma16816(rsum[0], P[0][ks], onesB);
            mma16816(rsum[1], P[1][ks], onesB);
        }
    }

    // epilogue: rows = qb*256 + w*32 + m*16 + {g, g+8}
    #pragma unroll
    for (int m = 0; m < 2; ++m) {
        const float inv0 = 1.0f / rsum[m][0], inv1 = 1.0f / rsum[m][2];
        const int lr = w*32 + m*16 + g;
        __half* dst0 = o2h + ((size_t)b*SS + (size_t)qb*QROWS + lr)     * NQ + (size_t)h * DHH;
        __half* dst1 = o2h + ((size_t)b*SS + (size_t)qb*QROWS + lr + 8) * NQ + (size_t)h * DHH;
        #pragma unroll
        for (int n = 0; n < 16; ++n) {
            int c = 8*n + 2*q4;
            *reinterpret_cast<__half2*>(dst0 + c) = __floats2half2_rn(o[m][n][0]*inv0, o[m][n][1]*inv0);
            *reinterpret_cast<__half2*>(dst1 + c) = __floats2half2_rn(o[m][n][2]*inv1, o[m][n][3]*inv1);
        }
    }
}

// ---------------------------------------------------------------------------
extern "C" void kernel_launch(void* const* d_in, const int* in_sizes, int n_in,
                              void* d_out, int out_size)
{
    const float* query  = (const float*)d_in[0];
    const float* key    = (const float*)d_in[1];
    const float* values = (const float*)d_in[2];
    const float* W_q = (const float*)d_in[3];
    const float* b_q = (const float*)d_in[4];
    const float* W_k = (const float*)d_in[5];
    const float* b_k = (const float*)d_in[6];
    const float* W_v = (const float*)d_in[7];
    const float* b_v = (const float*)d_in[8];
    const float* W_o = (const float*)d_in[9];
    const float* b_o = (const float*)d_in[10];
    float* out = (float*)d_out;

    float *pp;
    __half *xh, *xkh, *xvh, *wqT, *wkT, *wvT, *woT, *qhp, *khp, *vhp, *ah;
    cudaGetSymbolAddress((void**)&pp,  g_part);
    cudaGetSymbolAddress((void**)&xh,  g_xh);
    cudaGetSymbolAddress((void**)&xkh, g_xkh);
    cudaGetSymbolAddress((void**)&xvh, g_xvh);
    cudaGetSymbolAddress((void**)&wqT, g_wqT);
    cudaGetSymbolAddress((void**)&wkT, g_wkT);
    cudaGetSymbolAddress((void**)&wvT, g_wvT);
    cudaGetSymbolAddress((void**)&woT, g_woT);
    cudaGetSymbolAddress((void**)&qhp, g_qh);
    cudaGetSymbolAddress((void**)&khp, g_kh);
    cudaGetSymbolAddress((void**)&vhp, g_vh);
    cudaGetSymbolAddress((void**)&ah,  g_attnh);

    cudaFuncSetAttribute(attn_hmma, cudaFuncAttributeMaxDynamicSharedMemorySize, SMEM_DYN);

    const float scl2 = 0.12753102189093095f;   // log2(e)/sqrt(128)

    // launch 0: fused input converts
    conv3_h<<<(BSZ*DHH/4 + 255)/256, 256>>>(
        (const float4*)query, (const float4*)key, (const float4*)values,
        (uint2*)xh, (uint2*)xkh, (uint2*)xvh, BSZ*DHH/4);
    // launch 1: fused weight transposes
    transpose_all<<<1056, 256>>>(W_q, W_k, W_v, W_o, wqT, wkT, wvT, woT);

    // launches 2-4: projections
    hgemm<1><<<dim3(NQ/128,  BSZ/128), 256>>>(xh,  wqT, b_q, qhp, BSZ, NQ,  DHH, scl2);
    hgemm<1><<<dim3(DHH/128, BSZ/128), 256>>>(xkh, wkT, b_k, khp, BSZ, DHH, DHH, 1.0f);
    hgemm<1><<<dim3(DHH/128, BSZ/128), 256>>>(xvh, wvT, b_v, vhp, BSZ, DHH, DHH, 1.0f);

    // launch 5: attention  (ncu -s 5 -c 1 captures THIS)
    attn_hmma<<<dim3(SS/QROWS, HH, BB), 256, SMEM_DYN>>>(qhp, khp, vhp, ah);

    // launches 6-7: O projection
    hgemm_splitk<<<dim3(DHH/128, BSZ/128, OSPLIT), 256>>>(ah, woT, pp, BSZ, DHH, NQ);
    reduce_bias<<<(BSZ*DHH/4 + 255)/256, 256>>>(pp, b_o, out, BSZ*DHH, DHH);
}

// round 11
// speedup vs baseline: 10.0572x; 1.0191x over previous
#include <cuda_runtime.h>
#include <cuda_fp16.h>
#include <math.h>
#include <stdint.h>

#define BB 2
#define SS 2048
#define HH 32
#define DHH 128
#define NQ 4096
#define BSZ 4096
#define TK 64
#define NT 32
#define OSPLIT 8

// -------- scratch --------
__device__ float  g_part [OSPLIT*BSZ*DHH];
__device__ __half g_xh   [BSZ*DHH];
__device__ __half g_xkh  [BSZ*DHH];
__device__ __half g_xvh  [BSZ*DHH];
__device__ __half g_wqT  [NQ*DHH];
__device__ __half g_wkT  [DHH*DHH];
__device__ __half g_wvT  [DHH*DHH];
__device__ __half g_woT  [DHH*NQ];
__device__ __half g_qh   [BSZ*NQ];           // Q proj, log2e/sqrt(d) pre-scaled
__device__ __half g_kh   [BSZ*DHH];
__device__ __half g_vh   [BSZ*DHH];
__device__ __half g_attnh[BSZ*NQ];

// -------- helpers --------
__device__ __forceinline__ uint32_t smem_u32(const void* p){
    uint32_t a;
    asm("{ .reg .u64 t; cvta.to.shared.u64 t, %1; cvt.u32.u64 %0, t; }" : "=r"(a) : "l"(p));
    return a;
}
__device__ __forceinline__ void cp16(uint32_t dst, const void* src){
    asm volatile("cp.async.cg.shared.global [%0], [%1], 16;" :: "r"(dst), "l"(src));
}
#define CP_COMMIT() asm volatile("cp.async.commit_group;" ::: "memory")
#define CP_WAIT1()  asm volatile("cp.async.wait_group 1;" ::: "memory")
#define CP_WAIT0()  asm volatile("cp.async.wait_group 0;" ::: "memory")

__device__ __forceinline__ void mma16816(float* c, const uint32_t* a, const uint32_t* b){
    asm volatile("mma.sync.aligned.m16n8k16.row.col.f32.f16.f16.f32 "
        "{%0,%1,%2,%3}, {%4,%5,%6,%7}, {%8,%9}, {%0,%1,%2,%3};"
        : "+f"(c[0]), "+f"(c[1]), "+f"(c[2]), "+f"(c[3])
        : "r"(a[0]), "r"(a[1]), "r"(a[2]), "r"(a[3]), "r"(b[0]), "r"(b[1]));
}
__device__ __forceinline__ void ldsm4(uint32_t* r, uint32_t a){
    asm volatile("ldmatrix.sync.aligned.m8n8.x4.shared.b16 {%0,%1,%2,%3}, [%4];"
        : "=r"(r[0]), "=r"(r[1]), "=r"(r[2]), "=r"(r[3]) : "r"(a));
}
__device__ __forceinline__ void ldsm4t(uint32_t* r, uint32_t a){
    asm volatile("ldmatrix.sync.aligned.m8n8.x4.trans.shared.b16 {%0,%1,%2,%3}, [%4];"
        : "=r"(r[0]), "=r"(r[1]), "=r"(r[2]), "=r"(r[3]) : "r"(a));
}
__device__ __forceinline__ uint32_t packh2(float x, float y){
    __half2 h = __floats2half2_rn(x, y);
    return *reinterpret_cast<uint32_t*>(&h);
}
__device__ __forceinline__ uint32_t ex2x2(uint32_t h){
    uint32_t r;
    asm("ex2.approx.f16x2 %0, %1;" : "=r"(r) : "r"(h));
    return r;
}

// =======================================================================
// Fused prep: input converts (blocks 0..511) + weight transposes (512..1567)
// =======================================================================
__global__ __launch_bounds__(256) void prep_all(
    const float4* __restrict__ q, const float4* __restrict__ k, const float4* __restrict__ v,
    uint2* __restrict__ oq, uint2* __restrict__ ok, uint2* __restrict__ ov,
    const float* __restrict__ Wq, const float* __restrict__ Wk,
    const float* __restrict__ Wv, const float* __restrict__ Wo,
    __half* __restrict__ wqT, __half* __restrict__ wkT,
    __half* __restrict__ wvT, __half* __restrict__ woT)
{
    __shared__ float t[32][33];
    int id = blockIdx.x;
    if (id < 512) {
        int i = id * 256 + threadIdx.x;   // n4 = 131072, 512*256 exact
        float4 f;
        f = q[i]; oq[i] = make_uint2(packh2(f.x, f.y), packh2(f.z, f.w));
        f = k[i]; ok[i] = make_uint2(packh2(f.x, f.y), packh2(f.z, f.w));
        f = v[i]; ov[i] = make_uint2(packh2(f.x, f.y), packh2(f.z, f.w));
        return;
    }
    id -= 512;
    const float* in; __half* out; int K, N, tile;
    if (id < 512)      { in = Wq; out = wqT; K = DHH; N = NQ;  tile = id; }
    else if (id < 528) { in = Wk; out = wkT; K = DHH; N = DHH; tile = id - 512; }
    else if (id < 544) { in = Wv; out = wvT; K = DHH; N = DHH; tile = id - 528; }
    else               { in = Wo; out = woT; K = NQ;  N = DHH; tile = id - 544; }
    int ntx = N / 32;
    int bx = (tile % ntx) * 32, by = (tile / ntx) * 32;
    int x = threadIdx.x & 31, y = threadIdx.x >> 5;
    #pragma unroll
    for (int i = 0; i < 4; ++i)
        t[y + 8*i][x] = in[(size_t)(by + y + 8*i)*N + bx + x];
    __syncthreads();
    #pragma unroll
    for (int i = 0; i < 4; ++i)
        out[(size_t)(bx + y + 8*i)*K + by + x] = __float2half_rn(t[x][y + 8*i]);
}

// =======================================================================
// Fused Q/K/V projections: one launch, flat grid of 1088 CTAs.
//   blocks [0,1024)   : Q proj tiles (M=BSZ, N=NQ)
//   blocks [1024,1056): K proj tiles (M=BSZ, N=DHH)
//   blocks [1056,1088): V proj tiles
// K-dim fixed = 128 (nk=4). Output fp16 with per-region scale.
// =======================================================================
__global__ __launch_bounds__(256) void hgemm_qkv(
    const __half* __restrict__ xq, const __half* __restrict__ xk, const __half* __restrict__ xv,
    const __half* __restrict__ wqT, const __half* __restrict__ wkT, const __half* __restrict__ wvT,
    const float* __restrict__ b_q, const float* __restrict__ b_k, const float* __restrict__ b_v,
    __half* __restrict__ qh, __half* __restrict__ kh, __half* __restrict__ vh,
    float scl2)
{
    __shared__ __align__(16) __half As[2][128*40];
    __shared__ __align__(16) __half Bs[2][128*40];

    const int bid = blockIdx.x;
    const __half *A, *Bt; const float* bias; __half* C; int N, m0, n0; float scale;
    if (bid < 1024) {
        A = xq; Bt = wqT; bias = b_q; C = qh; N = NQ; scale = scl2;
        m0 = (bid >> 5) * 128; n0 = (bid & 31) * 128;
    } else if (bid < 1056) {
        A = xk; Bt = wkT; bias = b_k; C = kh; N = DHH; scale = 1.0f;
        m0 = (bid - 1024) * 128; n0 = 0;
    } else {
        A = xv; Bt = wvT; bias = b_v; C = vh; N = DHH; scale = 1.0f;
        m0 = (bid - 1056) * 128; n0 = 0;
    }

    const int tid = threadIdx.x, lane = tid & 31, w = tid >> 5;
    const int wm = (w >> 2) * 64, wn = (w & 3) * 32;
    const int g = lane >> 2, q4 = lane & 3;
    const int arow = ((lane >> 3) & 1) * 8 + (lane & 7);
    const int akse = (lane >> 4) * 8;
    const int brow = ((lane >> 4) & 1) * 8 + (lane & 7);
    const int bkse = ((lane >> 3) & 1) * 8;

    float acc[4][4][4] = {};

    auto load = [&](int kb, int st){
        #pragma unroll
        for (int i = 0; i < 2; ++i) {
            int e = tid + 256*i, r = e >> 2, c = e & 3;
            cp16(smem_u32(&As[st][r*40 + c*8]), A  + (size_t)(m0 + r)*DHH + kb*32 + c*8);
            cp16(smem_u32(&Bs[st][r*40 + c*8]), Bt + (size_t)(n0 + r)*DHH + kb*32 + c*8);
        }
    };
    load(0, 0); CP_COMMIT();

    #pragma unroll
    for (int kb = 0; kb < 4; ++kb) {
        if (kb + 1 < 4) { load(kb+1, (kb+1)&1); CP_COMMIT(); CP_WAIT1(); }
        else            { CP_WAIT0(); }
        __syncthreads();
        const int st = kb & 1;
        const uint32_t aB = smem_u32(&As[st][0]) + (wm + arow)*80 + akse*2;
        const uint32_t bB = smem_u32(&Bs[st][0]) + (wn + brow)*80 + bkse*2;
        #pragma unroll
        for (int ks = 0; ks < 2; ++ks) {
            uint32_t aF[4][4], bF[2][4];
            #pragma unroll
            for (int mi = 0; mi < 4; ++mi) ldsm4(aF[mi], aB + mi*16*80 + ks*32);
            #pragma unroll
            for (int np = 0; np < 2; ++np) ldsm4(bF[np], bB + np*16*80 + ks*32);
            #pragma unroll
            for (int mi = 0; mi < 4; ++mi)
                #pragma unroll
                for (int ni = 0; ni < 4; ++ni)
                    mma16816(acc[mi][ni], aF[mi], bF[ni>>1] + (ni&1)*2);
        }
        __syncthreads();
    }

    #pragma unroll
    for (int mi = 0; mi < 4; ++mi)
        #pragma unroll
        for (int ni = 0; ni < 4; ++ni) {
            int row = m0 + wm + mi*16 + g;
            int col = n0 + wn + ni*8 + 2*q4;
            float b0 = bias[col], b1 = bias[col+1];
            *reinterpret_cast<__half2*>(C + (size_t)row*N + col) =
                __floats2half2_rn((acc[mi][ni][0] + b0)*scale, (acc[mi][ni][1] + b1)*scale);
            *reinterpret_cast<__half2*>(C + (size_t)(row+8)*N + col) =
                __floats2half2_rn((acc[mi][ni][2] + b0)*scale, (acc[mi][ni][3] + b1)*scale);
        }
}

// ---- split-K hgemm + reduce (O projection) ----
__global__ __launch_bounds__(256) void hgemm_splitk(
    const __half* __restrict__ A, const __half* __restrict__ Bt,
    float* __restrict__ part, int M, int N, int K)
{
    __shared__ __align__(16) __half As[2][128*40];
    __shared__ __align__(16) __half Bs[2][128*40];
    const int tid = threadIdx.x, lane = tid & 31, w = tid >> 5;
    const int wm = (w >> 2) * 64, wn = (w & 3) * 32;
    const int m0 = blockIdx.y * 128, n0 = blockIdx.x * 128;
    const int kc = blockIdx.z;
    const int g = lane >> 2, q4 = lane & 3;
    const int arow = ((lane >> 3) & 1) * 8 + (lane & 7);
    const int akse = (lane >> 4) * 8;
    const int brow = ((lane >> 4) & 1) * 8 + (lane & 7);
    const int bkse = ((lane >> 3) & 1) * 8;

    float acc[4][4][4] = {};
    const int nkpc = K / 32 / OSPLIT;
    const int kb0 = kc * nkpc;

    auto load = [&](int kb, int st){
        #pragma unroll
        for (int i = 0; i < 2; ++i) {
            int e = tid + 256*i, r = e >> 2, c = e & 3;
            cp16(smem_u32(&As[st][r*40 + c*8]), A  + (size_t)(m0 + r)*K + kb*32 + c*8);
            cp16(smem_u32(&Bs[st][r*40 + c*8]), Bt + (size_t)(n0 + r)*K + kb*32 + c*8);
        }
    };
    load(kb0, 0); CP_COMMIT();

    for (int i = 0; i < nkpc; ++i) {
        if (i + 1 < nkpc) { load(kb0+i+1, (i+1)&1); CP_COMMIT(); CP_WAIT1(); }
        else              { CP_WAIT0(); }
        __syncthreads();
        const int st = i & 1;
        const uint32_t aB = smem_u32(&As[st][0]) + (wm + arow)*80 + akse*2;
        const uint32_t bB = smem_u32(&Bs[st][0]) + (wn + brow)*80 + bkse*2;
        #pragma unroll
        for (int ks = 0; ks < 2; ++ks) {
            uint32_t aF[4][4], bF[2][4];
            #pragma unroll
            for (int mi = 0; mi < 4; ++mi) ldsm4(aF[mi], aB + mi*16*80 + ks*32);
            #pragma unroll
            for (int np = 0; np < 2; ++np) ldsm4(bF[np], bB + np*16*80 + ks*32);
            #pragma unroll
            for (int mi = 0; mi < 4; ++mi)
                #pragma unroll
                for (int ni = 0; ni < 4; ++ni)
                    mma16816(acc[mi][ni], aF[mi], bF[ni>>1] + (ni&1)*2);
        }
        __syncthreads();
    }

    float* P = part + (size_t)kc * M * N;
    #pragma unroll
    for (int mi = 0; mi < 4; ++mi)
        #pragma unroll
        for (int ni = 0; ni < 4; ++ni) {
            int row = m0 + wm + mi*16 + g;
            int col = n0 + wn + ni*8 + 2*q4;
            *reinterpret_cast<float2*>(P + (size_t)row*N + col)     = make_float2(acc[mi][ni][0], acc[mi][ni][1]);
            *reinterpret_cast<float2*>(P + (size_t)(row+8)*N + col) = make_float2(acc[mi][ni][2], acc[mi][ni][3]);
        }
}

__global__ void reduce_bias(const float* __restrict__ part, const float* __restrict__ bias,
                            float* __restrict__ out, int MN, int N)
{
    int i = (blockIdx.x * 256 + threadIdx.x) * 4;
    if (i >= MN) return;
    float4 s = *reinterpret_cast<const float4*>(part + i);
    #pragma unroll
    for (int kc = 1; kc < OSPLIT; ++kc) {
        float4 p = *reinterpret_cast<const float4*>(part + (size_t)kc*MN + i);
        s.x += p.x; s.y += p.y; s.z += p.z; s.w += p.w;
    }
    int c = i & (N - 1);
    s.x += bias[c]; s.y += bias[c+1]; s.z += bias[c+2]; s.w += bias[c+3];
    *reinterpret_cast<float4*>(out + i) = s;
}

// =======================================================================
// HMMA flash attention — M=32/warp, V row-major + ldmatrix.trans
// =======================================================================
#define KROWB 272
#define KBYTES (64*KROWB)
#define BUF    (2*KBYTES)
#define QROWB  272
#define QROWS  256
#define QBYTES (QROWS*QROWB)
#define SMEM_DYN (QBYTES + 3*BUF)     // 174080

__device__ __forceinline__ void load_tile(uint32_t buf, int b, int kt,
    const __half* kh, const __half* vh, int tid)
{
    const __half* ks = kh + ((size_t)b*SS + (size_t)kt*TK) * DHH;
    const __half* vs = vh + ((size_t)b*SS + (size_t)kt*TK) * DHH;
    #pragma unroll
    for (int t = 0; t < 4; ++t) {
        int e = tid + t*256, r = e >> 4, c = e & 15;
        cp16(buf + r*KROWB + c*16,          ks + (size_t)r*DHH + c*8);
        cp16(buf + KBYTES + r*KROWB + c*16, vs + (size_t)r*DHH + c*8);
    }
}

__global__ __launch_bounds__(256, 1) void attn_hmma(
    const __half* __restrict__ qh, const __half* __restrict__ kh,
    const __half* __restrict__ vh, __half* __restrict__ o2h)
{
    extern __shared__ __align__(16) char smraw[];
    const uint32_t smb = smem_u32(smraw);
    const uint32_t kvb = smb + QBYTES;
    const int qb = blockIdx.x, h = blockIdx.y, b = blockIdx.z;
    const int tid = threadIdx.x, w = tid >> 5, lane = tid & 31;
    const int g = lane >> 2, q4 = lane & 3;
    const int jrow = ((lane >> 4) & 1) * 8 + (lane & 7);
    const int ksel = ((lane >> 3) & 1) * 8;
    const int arow = ((lane >> 3) & 1) * 8 + (lane & 7);
    const int akse = (lane >> 4) * 8;
    const int vrow = lane & 15;
    const int vcol8 = (lane >> 4) * 8;

    {
        const __half* qsrc = qh + ((size_t)b*SS + (size_t)h*64 + (size_t)qb*8) * NQ;
        #pragma unroll
        for (int t = 0; t < 16; ++t) {
            int e = tid + t*256, r = e >> 4, c = e & 15;
            cp16(smb + r*QROWB + c*16, qsrc + (size_t)r*DHH + c*8);
        }
    }
    load_tile(kvb, b, 0, kh, vh, tid);
    CP_COMMIT();
    load_tile(kvb + BUF, b, 1, kh, vh, tid);
    CP_COMMIT();

    float o[2][16][4];
    #pragma unroll
    for (int m = 0; m < 2; ++m)
        #pragma unroll
        for (int n = 0; n < 16; ++n)
            #pragma unroll
            for (int i = 0; i < 4; ++i) o[m][n][i] = 0.f;
    float rsum[2][4] = {};
    const uint32_t onesB[2] = {0x3C003C00u, 0x3C003C00u};
    const uint32_t Qb = smb + (w*32 + arow)*QROWB + akse*2;

    for (int kt = 0; kt < NT; ++kt) {
        if (kt + 1 < NT) { CP_WAIT1(); } else { CP_WAIT0(); }
        __syncthreads();
        if (kt + 2 < NT) {
            load_tile(kvb + (uint32_t)((kt+2)%3)*BUF, b, kt+2, kh, vh, tid);
            CP_COMMIT();
        }

        const uint32_t Kb = kvb + (uint32_t)(kt%3)*BUF + jrow*KROWB + ksel*2;
        const uint32_t Vb = kvb + (uint32_t)(kt%3)*BUF + KBYTES + vrow*KROWB + vcol8*2;

        float s[2][8][4];
        #pragma unroll
        for (int m = 0; m < 2; ++m)
            #pragma unroll
            for (int j = 0; j < 8; ++j)
                #pragma unroll
                for (int i = 0; i < 4; ++i) s[m][j][i] = 0.f;
        #pragma unroll
        for (int ks = 0; ks < 8; ++ks) {
            uint32_t aF0[4], aF1[4];
            ldsm4(aF0, Qb + 32*ks);
            ldsm4(aF1, Qb + 16*QROWB + 32*ks);
            uint32_t bb[2][4];
            ldsm4(bb[0], Kb + 32*ks);
            #pragma unroll
            for (int jp = 0; jp < 4; ++jp) {
                if (jp < 3) ldsm4(bb[(jp+1)&1], Kb + (jp+1)*16*KROWB + 32*ks);
                mma16816(s[0][2*jp],   aF0, bb[jp&1]);
                mma16816(s[0][2*jp+1], aF0, bb[jp&1] + 2);
                mma16816(s[1][2*jp],   aF1, bb[jp&1]);
                mma16816(s[1][2*jp+1], aF1, bb[jp&1] + 2);
            }
        }

        uint32_t P[2][4][4];
        #pragma unroll
        for (int m = 0; m < 2; ++m)
            #pragma unroll
            for (int j = 0; j < 8; ++j) {
                P[m][j>>1][(j&1)*2]     = ex2x2(packh2(s[m][j][0], s[m][j][1]));
                P[m][j>>1][(j&1)*2 + 1] = ex2x2(packh2(s[m][j][2], s[m][j][3]));
            }

        #pragma unroll
        for (int ks = 0; ks < 4; ++ks) {
            const uint32_t Vk = Vb + ks*16*KROWB;
            uint32_t bb[2][4];
            ldsm4t(bb[0], Vk);
            #pragma unroll
            for (int np = 0; np < 8; ++np) {
                if (np < 7) ldsm4t(bb[(np+1)&1], Vk + (np+1)*32);
                mma16816(o[0][2*np],   P[0][ks], bb[np&1]);
                mma16816(o[0][2*np+1], P[0][ks], bb[np&1] + 2);
                mma16816(o[1][2*np],   P[1][ks], bb[np&1]);
                mma16816(o[1][2*np+1], P[1][ks], bb[np&1] + 2);
            }
            mma16816(rsum[0], P[0][ks], onesB);
            mma16816(rsum[1], P[1][ks], onesB);
        }
    }

    #pragma unroll
    for (int m = 0; m < 2; ++m) {
        const float inv0 = 1.0f / rsum[m][0], inv1 = 1.0f / rsum[m][2];
        const int lr = w*32 + m*16 + g;
        __half* dst0 = o2h + ((size_t)b*SS + (size_t)qb*QROWS + lr)     * NQ + (size_t)h * DHH;
        __half* dst1 = o2h + ((size_t)b*SS + (size_t)qb*QROWS + lr + 8) * NQ + (size_t)h * DHH;
        #pragma unroll
        for (int n = 0; n < 16; ++n) {
            int c = 8*n + 2*q4;
            *reinterpret_cast<__half2*>(dst0 + c) = __floats2half2_rn(o[m][n][0]*inv0, o[m][n][1]*inv0);
            *reinterpret_cast<__half2*>(dst1 + c) = __floats2half2_rn(o[m][n][2]*inv1, o[m][n][3]*inv1);
        }
    }
}

// ---------------------------------------------------------------------------
extern "C" void kernel_launch(void* const* d_in, const int* in_sizes, int n_in,
                              void* d_out, int out_size)
{
    const float* query  = (const float*)d_in[0];
    const float* key    = (const float*)d_in[1];
    const float* values = (const float*)d_in[2];
    const float* W_q = (const float*)d_in[3];
    const float* b_q = (const float*)d_in[4];
    const float* W_k = (const float*)d_in[5];
    const float* b_k = (const float*)d_in[6];
    const float* W_v = (const float*)d_in[7];
    const float* b_v = (const float*)d_in[8];
    const float* W_o = (const float*)d_in[9];
    const float* b_o = (const float*)d_in[10];
    float* out = (float*)d_out;

    float *pp;
    __half *xh, *xkh, *xvh, *wqT, *wkT, *wvT, *woT, *qhp, *khp, *vhp, *ah;
    cudaGetSymbolAddress((void**)&pp,  g_part);
    cudaGetSymbolAddress((void**)&xh,  g_xh);
    cudaGetSymbolAddress((void**)&xkh, g_xkh);
    cudaGetSymbolAddress((void**)&xvh, g_xvh);
    cudaGetSymbolAddress((void**)&wqT, g_wqT);
    cudaGetSymbolAddress((void**)&wkT, g_wkT);
    cudaGetSymbolAddress((void**)&wvT, g_wvT);
    cudaGetSymbolAddress((void**)&woT, g_woT);
    cudaGetSymbolAddress((void**)&qhp, g_qh);
    cudaGetSymbolAddress((void**)&khp, g_kh);
    cudaGetSymbolAddress((void**)&vhp, g_vh);
    cudaGetSymbolAddress((void**)&ah,  g_attnh);

    cudaFuncSetAttribute(attn_hmma, cudaFuncAttributeMaxDynamicSharedMemorySize, SMEM_DYN);

    const float scl2 = 0.12753102189093095f;   // log2(e)/sqrt(128)

    // launch 0: fused converts + weight transposes
    prep_all<<<1568, 256>>>(
        (const float4*)query, (const float4*)key, (const float4*)values,
        (uint2*)xh, (uint2*)xkh, (uint2*)xvh,
        W_q, W_k, W_v, W_o, wqT, wkT, wvT, woT);

    // launch 1: all three projections in one grid
    hgemm_qkv<<<1088, 256>>>(xh, xkh, xvh, wqT, wkT, wvT,
                             b_q, b_k, b_v, qhp, khp, vhp, scl2);

    // launch 2: attention
    attn_hmma<<<dim3(SS/QROWS, HH, BB), 256, SMEM_DYN>>>(qhp, khp, vhp, ah);

    // launches 3-4: O projection
    hgemm_splitk<<<dim3(DHH/128, BSZ/128, OSPLIT), 256>>>(ah, woT, pp, BSZ, DHH, NQ);
    reduce_bias<<<(BSZ*DHH/4 + 255)/256, 256>>>(pp, b_o, out, BSZ*DHH, DHH);
}

// round 12
// speedup vs baseline: 11.0886x; 1.1026x over previous
#include <cuda_runtime.h>
#include <cuda_fp16.h>
#include <math.h>
#include <stdint.h>

#define BB 2
#define SS 2048
#define HH 32
#define DHH 128
#define NQ 4096
#define BSZ 4096
#define TK 64
#define NT 32
#define OSPLIT 8

// -------- scratch --------
__device__ float  g_part [OSPLIT*BSZ*DHH];
__device__ __half g_xh   [BSZ*DHH];
__device__ __half g_xkh  [BSZ*DHH];
__device__ __half g_xvh  [BSZ*DHH];
__device__ __half g_wqT  [NQ*DHH];
__device__ __half g_wkT  [DHH*DHH];
__device__ __half g_wvT  [DHH*DHH];
__device__ __half g_woT  [DHH*NQ];
__device__ __half g_qh   [BSZ*NQ];           // Q proj, log2e/sqrt(d) pre-scaled
__device__ __half g_kh   [BSZ*DHH];
__device__ __half g_vh   [BSZ*DHH];
__device__ __half g_attnh[BSZ*NQ];

// -------- helpers --------
__device__ __forceinline__ uint32_t smem_u32(const void* p){
    uint32_t a;
    asm("{ .reg .u64 t; cvta.to.shared.u64 t, %1; cvt.u32.u64 %0, t; }" : "=r"(a) : "l"(p));
    return a;
}
__device__ __forceinline__ void cp16(uint32_t dst, const void* src){
    asm volatile("cp.async.cg.shared.global [%0], [%1], 16;" :: "r"(dst), "l"(src));
}
#define CP_COMMIT() asm volatile("cp.async.commit_group;" ::: "memory")
#define CP_WAIT1()  asm volatile("cp.async.wait_group 1;" ::: "memory")
#define CP_WAIT0()  asm volatile("cp.async.wait_group 0;" ::: "memory")

__device__ __forceinline__ void mma16816(float* c, const uint32_t* a, const uint32_t* b){
    asm volatile("mma.sync.aligned.m16n8k16.row.col.f32.f16.f16.f32 "
        "{%0,%1,%2,%3}, {%4,%5,%6,%7}, {%8,%9}, {%0,%1,%2,%3};"
        : "+f"(c[0]), "+f"(c[1]), "+f"(c[2]), "+f"(c[3])
        : "r"(a[0]), "r"(a[1]), "r"(a[2]), "r"(a[3]), "r"(b[0]), "r"(b[1]));
}
__device__ __forceinline__ void ldsm4(uint32_t* r, uint32_t a){
    asm volatile("ldmatrix.sync.aligned.m8n8.x4.shared.b16 {%0,%1,%2,%3}, [%4];"
        : "=r"(r[0]), "=r"(r[1]), "=r"(r[2]), "=r"(r[3]) : "r"(a));
}
__device__ __forceinline__ void ldsm4t(uint32_t* r, uint32_t a){
    asm volatile("ldmatrix.sync.aligned.m8n8.x4.trans.shared.b16 {%0,%1,%2,%3}, [%4];"
        : "=r"(r[0]), "=r"(r[1]), "=r"(r[2]), "=r"(r[3]) : "r"(a));
}
__device__ __forceinline__ uint32_t packh2(float x, float y){
    __half2 h = __floats2half2_rn(x, y);
    return *reinterpret_cast<uint32_t*>(&h);
}
__device__ __forceinline__ uint32_t ex2x2(uint32_t h){
    uint32_t r;
    asm("ex2.approx.f16x2 %0, %1;" : "=r"(r) : "r"(h));
    return r;
}

// =======================================================================
// Fused prep: input converts (blocks 0..511) + weight transposes (512..1567)
// =======================================================================
__global__ __launch_bounds__(256) void prep_all(
    const float4* __restrict__ q, const float4* __restrict__ k, const float4* __restrict__ v,
    uint2* __restrict__ oq, uint2* __restrict__ ok, uint2* __restrict__ ov,
    const float* __restrict__ Wq, const float* __restrict__ Wk,
    const float* __restrict__ Wv, const float* __restrict__ Wo,
    __half* __restrict__ wqT, __half* __restrict__ wkT,
    __half* __restrict__ wvT, __half* __restrict__ woT)
{
    __shared__ float t[32][33];
    int id = blockIdx.x;
    if (id < 512) {
        int i = id * 256 + threadIdx.x;
        float4 f;
        f = q[i]; oq[i] = make_uint2(packh2(f.x, f.y), packh2(f.z, f.w));
        f = k[i]; ok[i] = make_uint2(packh2(f.x, f.y), packh2(f.z, f.w));
        f = v[i]; ov[i] = make_uint2(packh2(f.x, f.y), packh2(f.z, f.w));
        return;
    }
    id -= 512;
    const float* in; __half* out; int K, N, tile;
    if (id < 512)      { in = Wq; out = wqT; K = DHH; N = NQ;  tile = id; }
    else if (id < 528) { in = Wk; out = wkT; K = DHH; N = DHH; tile = id - 512; }
    else if (id < 544) { in = Wv; out = wvT; K = DHH; N = DHH; tile = id - 528; }
    else               { in = Wo; out = woT; K = NQ;  N = DHH; tile = id - 544; }
    int ntx = N / 32;
    int bx = (tile % ntx) * 32, by = (tile / ntx) * 32;
    int x = threadIdx.x & 31, y = threadIdx.x >> 5;
    #pragma unroll
    for (int i = 0; i < 4; ++i)
        t[y + 8*i][x] = in[(size_t)(by + y + 8*i)*N + bx + x];
    __syncthreads();
    #pragma unroll
    for (int i = 0; i < 4; ++i)
        out[(size_t)(bx + y + 8*i)*K + by + x] = __float2half_rn(t[x][y + 8*i]);
}

// =======================================================================
// Fused Q/K/V projections: one launch, flat grid of 1088 CTAs.
// =======================================================================
__global__ __launch_bounds__(256) void hgemm_qkv(
    const __half* __restrict__ xq, const __half* __restrict__ xk, const __half* __restrict__ xv,
    const __half* __restrict__ wqT, const __half* __restrict__ wkT, const __half* __restrict__ wvT,
    const float* __restrict__ b_q, const float* __restrict__ b_k, const float* __restrict__ b_v,
    __half* __restrict__ qh, __half* __restrict__ kh, __half* __restrict__ vh,
    float scl2)
{
    __shared__ __align__(16) __half As[2][128*40];
    __shared__ __align__(16) __half Bs[2][128*40];

    const int bid = blockIdx.x;
    const __half *A, *Bt; const float* bias; __half* C; int N, m0, n0; float scale;
    if (bid < 1024) {
        A = xq; Bt = wqT; bias = b_q; C = qh; N = NQ; scale = scl2;
        m0 = (bid >> 5) * 128; n0 = (bid & 31) * 128;
    } else if (bid < 1056) {
        A = xk; Bt = wkT; bias = b_k; C = kh; N = DHH; scale = 1.0f;
        m0 = (bid - 1024) * 128; n0 = 0;
    } else {
        A = xv; Bt = wvT; bias = b_v; C = vh; N = DHH; scale = 1.0f;
        m0 = (bid - 1056) * 128; n0 = 0;
    }

    const int tid = threadIdx.x, lane = tid & 31, w = tid >> 5;
    const int wm = (w >> 2) * 64, wn = (w & 3) * 32;
    const int g = lane >> 2, q4 = lane & 3;
    const int arow = ((lane >> 3) & 1) * 8 + (lane & 7);
    const int akse = (lane >> 4) * 8;
    const int brow = ((lane >> 4) & 1) * 8 + (lane & 7);
    const int bkse = ((lane >> 3) & 1) * 8;

    float acc[4][4][4] = {};

    auto load = [&](int kb, int st){
        #pragma unroll
        for (int i = 0; i < 2; ++i) {
            int e = tid + 256*i, r = e >> 2, c = e & 3;
            cp16(smem_u32(&As[st][r*40 + c*8]), A  + (size_t)(m0 + r)*DHH + kb*32 + c*8);
            cp16(smem_u32(&Bs[st][r*40 + c*8]), Bt + (size_t)(n0 + r)*DHH + kb*32 + c*8);
        }
    };
    load(0, 0); CP_COMMIT();

    #pragma unroll
    for (int kb = 0; kb < 4; ++kb) {
        if (kb + 1 < 4) { load(kb+1, (kb+1)&1); CP_COMMIT(); CP_WAIT1(); }
        else            { CP_WAIT0(); }
        __syncthreads();
        const int st = kb & 1;
        const uint32_t aB = smem_u32(&As[st][0]) + (wm + arow)*80 + akse*2;
        const uint32_t bB = smem_u32(&Bs[st][0]) + (wn + brow)*80 + bkse*2;
        #pragma unroll
        for (int ks = 0; ks < 2; ++ks) {
            uint32_t aF[4][4], bF[2][4];
            #pragma unroll
            for (int mi = 0; mi < 4; ++mi) ldsm4(aF[mi], aB + mi*16*80 + ks*32);
            #pragma unroll
            for (int np = 0; np < 2; ++np) ldsm4(bF[np], bB + np*16*80 + ks*32);
            #pragma unroll
            for (int mi = 0; mi < 4; ++mi)
                #pragma unroll
                for (int ni = 0; ni < 4; ++ni)
                    mma16816(acc[mi][ni], aF[mi], bF[ni>>1] + (ni&1)*2);
        }
        __syncthreads();
    }

    #pragma unroll
    for (int mi = 0; mi < 4; ++mi)
        #pragma unroll
        for (int ni = 0; ni < 4; ++ni) {
            int row = m0 + wm + mi*16 + g;
            int col = n0 + wn + ni*8 + 2*q4;
            float b0 = bias[col], b1 = bias[col+1];
            *reinterpret_cast<__half2*>(C + (size_t)row*N + col) =
                __floats2half2_rn((acc[mi][ni][0] + b0)*scale, (acc[mi][ni][1] + b1)*scale);
            *reinterpret_cast<__half2*>(C + (size_t)(row+8)*N + col) =
                __floats2half2_rn((acc[mi][ni][2] + b0)*scale, (acc[mi][ni][3] + b1)*scale);
        }
}

// ---- split-K hgemm + reduce (O projection) ----
__global__ __launch_bounds__(256) void hgemm_splitk(
    const __half* __restrict__ A, const __half* __restrict__ Bt,
    float* __restrict__ part, int M, int N, int K)
{
    __shared__ __align__(16) __half As[2][128*40];
    __shared__ __align__(16) __half Bs[2][128*40];
    const int tid = threadIdx.x, lane = tid & 31, w = tid >> 5;
    const int wm = (w >> 2) * 64, wn = (w & 3) * 32;
    const int m0 = blockIdx.y * 128, n0 = blockIdx.x * 128;
    const int kc = blockIdx.z;
    const int g = lane >> 2, q4 = lane & 3;
    const int arow = ((lane >> 3) & 1) * 8 + (lane & 7);
    const int akse = (lane >> 4) * 8;
    const int brow = ((lane >> 4) & 1) * 8 + (lane & 7);
    const int bkse = ((lane >> 3) & 1) * 8;

    float acc[4][4][4] = {};
    const int nkpc = K / 32 / OSPLIT;
    const int kb0 = kc * nkpc;

    auto load = [&](int kb, int st){
        #pragma unroll
        for (int i = 0; i < 2; ++i) {
            int e = tid + 256*i, r = e >> 2, c = e & 3;
            cp16(smem_u32(&As[st][r*40 + c*8]), A  + (size_t)(m0 + r)*K + kb*32 + c*8);
            cp16(smem_u32(&Bs[st][r*40 + c*8]), Bt + (size_t)(n0 + r)*K + kb*32 + c*8);
        }
    };
    load(kb0, 0); CP_COMMIT();

    for (int i = 0; i < nkpc; ++i) {
        if (i + 1 < nkpc) { load(kb0+i+1, (i+1)&1); CP_COMMIT(); CP_WAIT1(); }
        else              { CP_WAIT0(); }
        __syncthreads();
        const int st = i & 1;
        const uint32_t aB = smem_u32(&As[st][0]) + (wm + arow)*80 + akse*2;
        const uint32_t bB = smem_u32(&Bs[st][0]) + (wn + brow)*80 + bkse*2;
        #pragma unroll
        for (int ks = 0; ks < 2; ++ks) {
            uint32_t aF[4][4], bF[2][4];
            #pragma unroll
            for (int mi = 0; mi < 4; ++mi) ldsm4(aF[mi], aB + mi*16*80 + ks*32);
            #pragma unroll
            for (int np = 0; np < 2; ++np) ldsm4(bF[np], bB + np*16*80 + ks*32);
            #pragma unroll
            for (int mi = 0; mi < 4; ++mi)
                #pragma unroll
                for (int ni = 0; ni < 4; ++ni)
                    mma16816(acc[mi][ni], aF[mi], bF[ni>>1] + (ni&1)*2);
        }
        __syncthreads();
    }

    float* P = part + (size_t)kc * M * N;
    #pragma unroll
    for (int mi = 0; mi < 4; ++mi)
        #pragma unroll
        for (int ni = 0; ni < 4; ++ni) {
            int row = m0 + wm + mi*16 + g;
            int col = n0 + wn + ni*8 + 2*q4;
            *reinterpret_cast<float2*>(P + (size_t)row*N + col)     = make_float2(acc[mi][ni][0], acc[mi][ni][1]);
            *reinterpret_cast<float2*>(P + (size_t)(row+8)*N + col) = make_float2(acc[mi][ni][2], acc[mi][ni][3]);
        }
}

__global__ void reduce_bias(const float* __restrict__ part, const float* __restrict__ bias,
                            float* __restrict__ out, int MN, int N)
{
    int i = (blockIdx.x * 256 + threadIdx.x) * 4;
    if (i >= MN) return;
    float4 s = *reinterpret_cast<const float4*>(part + i);
    #pragma unroll
    for (int kc = 1; kc < OSPLIT; ++kc) {
        float4 p = *reinterpret_cast<const float4*>(part + (size_t)kc*MN + i);
        s.x += p.x; s.y += p.y; s.z += p.z; s.w += p.w;
    }
    int c = i & (N - 1);
    s.x += bias[c]; s.y += bias[c+1]; s.z += bias[c+2]; s.w += bias[c+3];
    *reinterpret_cast<float4*>(out + i) = s;
}

// =======================================================================
// HMMA flash attention — 4 warps/CTA, M=32/warp, 128 q-rows/CTA,
// 2-stage K/V pipeline, 2 CTAs/SM co-residency to hide softmax bubbles.
// =======================================================================
#define KROWB 272
#define KBYTES (64*KROWB)
#define BUF    (2*KBYTES)             // K+V one stage: 34816
#define QROWB  272
#define QROWS  128
#define QBYTES (QROWS*QROWB)          // 34816
#define SMEM_DYN (QBYTES + 2*BUF)     // 104448 -> 2 CTAs/SM

__device__ __forceinline__ void load_tile(uint32_t buf, int b, int kt,
    const __half* kh, const __half* vh, int tid)
{
    const __half* ks = kh + ((size_t)b*SS + (size_t)kt*TK) * DHH;
    const __half* vs = vh + ((size_t)b*SS + (size_t)kt*TK) * DHH;
    #pragma unroll
    for (int t = 0; t < 8; ++t) {
        int e = tid + t*128, r = e >> 4, c = e & 15;
        cp16(buf + r*KROWB + c*16,          ks + (size_t)r*DHH + c*8);
        cp16(buf + KBYTES + r*KROWB + c*16, vs + (size_t)r*DHH + c*8);
    }
}

__global__ __launch_bounds__(128, 2) void attn_hmma(
    const __half* __restrict__ qh, const __half* __restrict__ kh,
    const __half* __restrict__ vh, __half* __restrict__ o2h)
{
    extern __shared__ __align__(16) char smraw[];
    const uint32_t smb = smem_u32(smraw);        // Q block (128 rows)
    const uint32_t kvb = smb + QBYTES;           // 2 K/V stages
    const int qb = blockIdx.x, h = blockIdx.y, b = blockIdx.z;
    const int tid = threadIdx.x, w = tid >> 5, lane = tid & 31;
    const int g = lane >> 2, q4 = lane & 3;
    const int jrow = ((lane >> 4) & 1) * 8 + (lane & 7);
    const int ksel = ((lane >> 3) & 1) * 8;
    const int arow = ((lane >> 3) & 1) * 8 + (lane & 7);
    const int akse = (lane >> 4) * 8;
    const int vrow = lane & 15;
    const int vcol8 = (lane >> 4) * 8;

    // stage Q (128 contiguous rows: qh layout rows b*S + h*64 + qb*4 .. +127)
    {
        const __half* qsrc = qh + ((size_t)b*SS + (size_t)h*64 + (size_t)qb*4) * NQ;
        #pragma unroll
        for (int t = 0; t < 16; ++t) {
            int e = tid + t*128, r = e >> 4, c = e & 15;
            cp16(smb + r*QROWB + c*16, qsrc + (size_t)r*DHH + c*8);
        }
    }
    load_tile(kvb, b, 0, kh, vh, tid);
    CP_COMMIT();
    load_tile(kvb + BUF, b, 1, kh, vh, tid);
    CP_COMMIT();

    float o[2][16][4];
    #pragma unroll
    for (int m = 0; m < 2; ++m)
        #pragma unroll
        for (int n = 0; n < 16; ++n)
            #pragma unroll
            for (int i = 0; i < 4; ++i) o[m][n][i] = 0.f;
    float rsum[2][4] = {};
    const uint32_t onesB[2] = {0x3C003C00u, 0x3C003C00u};
    const uint32_t Qb = smb + (w*32 + arow)*QROWB + akse*2;

    for (int kt = 0; kt < NT; ++kt) {
        if (kt + 1 < NT) { CP_WAIT1(); } else { CP_WAIT0(); }
        __syncthreads();                     // tile kt visible to all warps

        const uint32_t Kb = kvb + (uint32_t)(kt&1)*BUF + jrow*KROWB + ksel*2;
        const uint32_t Vb = kvb + (uint32_t)(kt&1)*BUF + KBYTES + vrow*KROWB + vcol8*2;

        // S = Q K^T for both m-tiles (K fragments shared)
        float s[2][8][4];
        #pragma unroll
        for (int m = 0; m < 2; ++m)
            #pragma unroll
            for (int j = 0; j < 8; ++j)
                #pragma unroll
                for (int i = 0; i < 4; ++i) s[m][j][i] = 0.f;
        #pragma unroll
        for (int ks = 0; ks < 8; ++ks) {
            uint32_t aF0[4], aF1[4];
            ldsm4(aF0, Qb + 32*ks);
            ldsm4(aF1, Qb + 16*QROWB + 32*ks);
            uint32_t bb[2][4];
            ldsm4(bb[0], Kb + 32*ks);
            #pragma unroll
            for (int jp = 0; jp < 4; ++jp) {
                if (jp < 3) ldsm4(bb[(jp+1)&1], Kb + (jp+1)*16*KROWB + 32*ks);
                mma16816(s[0][2*jp],   aF0, bb[jp&1]);
                mma16816(s[0][2*jp+1], aF0, bb[jp&1] + 2);
                mma16816(s[1][2*jp],   aF1, bb[jp&1]);
                mma16816(s[1][2*jp+1], aF1, bb[jp&1] + 2);
            }
        }

        // P = 2^S (fp16x2 MUFU)
        uint32_t P[2][4][4];
        #pragma unroll
        for (int m = 0; m < 2; ++m)
            #pragma unroll
            for (int j = 0; j < 8; ++j) {
                P[m][j>>1][(j&1)*2]     = ex2x2(packh2(s[m][j][0], s[m][j][1]));
                P[m][j>>1][(j&1)*2 + 1] = ex2x2(packh2(s[m][j][2], s[m][j][3]));
            }

        // O += P V ; rowsum += P @ ones
        #pragma unroll
        for (int ks = 0; ks < 4; ++ks) {
            const uint32_t Vk = Vb + ks*16*KROWB;
            uint32_t bb[2][4];
            ldsm4t(bb[0], Vk);
            #pragma unroll
            for (int np = 0; np < 8; ++np) {
                if (np < 7) ldsm4t(bb[(np+1)&1], Vk + (np+1)*32);
                mma16816(o[0][2*np],   P[0][ks], bb[np&1]);
                mma16816(o[0][2*np+1], P[0][ks], bb[np&1] + 2);
                mma16816(o[1][2*np],   P[1][ks], bb[np&1]);
                mma16816(o[1][2*np+1], P[1][ks], bb[np&1] + 2);
            }
            mma16816(rsum[0], P[0][ks], onesB);
            mma16816(rsum[1], P[1][ks], onesB);
        }

        __syncthreads();                     // all warps done reading stage kt&1
        if (kt + 2 < NT) {
            load_tile(kvb + (uint32_t)(kt&1)*BUF, b, kt+2, kh, vh, tid);
            CP_COMMIT();
        }
    }

    // epilogue: rows = qb*128 + w*32 + m*16 + {g, g+8}
    #pragma unroll
    for (int m = 0; m < 2; ++m) {
        const float inv0 = 1.0f / rsum[m][0], inv1 = 1.0f / rsum[m][2];
        const int lr = w*32 + m*16 + g;
        __half* dst0 = o2h + ((size_t)b*SS + (size_t)qb*QROWS + lr)     * NQ + (size_t)h * DHH;
        __half* dst1 = o2h + ((size_t)b*SS + (size_t)qb*QROWS + lr + 8) * NQ + (size_t)h * DHH;
        #pragma unroll
        for (int n = 0; n < 16; ++n) {
            int c = 8*n + 2*q4;
            *reinterpret_cast<__half2*>(dst0 + c) = __floats2half2_rn(o[m][n][0]*inv0, o[m][n][1]*inv0);
            *reinterpret_cast<__half2*>(dst1 + c) = __floats2half2_rn(o[m][n][2]*inv1, o[m][n][3]*inv1);
        }
    }
}

// ---------------------------------------------------------------------------
extern "C" void kernel_launch(void* const* d_in, const int* in_sizes, int n_in,
                              void* d_out, int out_size)
{
    const float* query  = (const float*)d_in[0];
    const float* key    = (const float*)d_in[1];
    const float* values = (const float*)d_in[2];
    const float* W_q = (const float*)d_in[3];
    const float* b_q = (const float*)d_in[4];
    const float* W_k = (const float*)d_in[5];
    const float* b_k = (const float*)d_in[6];
    const float* W_v = (const float*)d_in[7];
    const float* b_v = (const float*)d_in[8];
    const float* W_o = (const float*)d_in[9];
    const float* b_o = (const float*)d_in[10];
    float* out = (float*)d_out;

    float *pp;
    __half *xh, *xkh, *xvh, *wqT, *wkT, *wvT, *woT, *qhp, *khp, *vhp, *ah;
    cudaGetSymbolAddress((void**)&pp,  g_part);
    cudaGetSymbolAddress((void**)&xh,  g_xh);
    cudaGetSymbolAddress((void**)&xkh, g_xkh);
    cudaGetSymbolAddress((void**)&xvh, g_xvh);
    cudaGetSymbolAddress((void**)&wqT, g_wqT);
    cudaGetSymbolAddress((void**)&wkT, g_wkT);
    cudaGetSymbolAddress((void**)&wvT, g_wvT);
    cudaGetSymbolAddress((void**)&woT, g_woT);
    cudaGetSymbolAddress((void**)&qhp, g_qh);
    cudaGetSymbolAddress((void**)&khp, g_kh);
    cudaGetSymbolAddress((void**)&vhp, g_vh);
    cudaGetSymbolAddress((void**)&ah,  g_attnh);

    cudaFuncSetAttribute(attn_hmma, cudaFuncAttributeMaxDynamicSharedMemorySize, SMEM_DYN);

    const float scl2 = 0.12753102189093095f;   // log2(e)/sqrt(128)

    // launch 0: fused converts + weight transposes
    prep_all<<<1568, 256>>>(
        (const float4*)query, (const float4*)key, (const float4*)values,
        (uint2*)xh, (uint2*)xkh, (uint2*)xvh,
        W_q, W_k, W_v, W_o, wqT, wkT, wvT, woT);

    // launch 1: all three projections in one grid
    hgemm_qkv<<<1088, 256>>>(xh, xkh, xvh, wqT, wkT, wvT,
                             b_q, b_k, b_v, qhp, khp, vhp, scl2);

    // launch 2: attention — 1024 CTAs of 128 threads, 2 CTAs/SM
    attn_hmma<<<dim3(SS/QROWS, HH, BB), 128, SMEM_DYN>>>(qhp, khp, vhp, ah);

    // launches 3-4: O projection
    hgemm_splitk<<<dim3(DHH/128, BSZ/128, OSPLIT), 256>>>(ah, woT, pp, BSZ, DHH, NQ);
    reduce_bias<<<(BSZ*DHH/4 + 255)/256, 256>>>(pp, b_o, out, BSZ*DHH, DHH);
}

// round 13
// speedup vs baseline: 11.2082x; 1.0108x over previous
#include <cuda_runtime.h>
#include <cuda_fp16.h>
#include <math.h>
#include <stdint.h>

#define BB 2
#define SS 2048
#define HH 32
#define DHH 128
#define NQ 4096
#define BSZ 4096
#define TK 64
#define NT 32
#define OSPLIT 16

// -------- scratch --------
__device__ float  g_part [OSPLIT*BSZ*DHH];
__device__ __half g_xh   [BSZ*DHH];
__device__ __half g_xkh  [BSZ*DHH];
__device__ __half g_xvh  [BSZ*DHH];
__device__ __half g_wqT  [NQ*DHH];
__device__ __half g_wkT  [DHH*DHH];
__device__ __half g_wvT  [DHH*DHH];
__device__ __half g_woT  [DHH*NQ];
__device__ __half g_qh   [BSZ*NQ];           // Q proj, log2e/sqrt(d) pre-scaled
__device__ __half g_kh   [BSZ*DHH];
__device__ __half g_vh   [BSZ*DHH];
__device__ __half g_attnh[BSZ*NQ];

// -------- helpers --------
__device__ __forceinline__ uint32_t smem_u32(const void* p){
    uint32_t a;
    asm("{ .reg .u64 t; cvta.to.shared.u64 t, %1; cvt.u32.u64 %0, t; }" : "=r"(a) : "l"(p));
    return a;
}
__device__ __forceinline__ void cp16(uint32_t dst, const void* src){
    asm volatile("cp.async.cg.shared.global [%0], [%1], 16;" :: "r"(dst), "l"(src));
}
#define CP_COMMIT() asm volatile("cp.async.commit_group;" ::: "memory")
#define CP_WAIT1()  asm volatile("cp.async.wait_group 1;" ::: "memory")
#define CP_WAIT0()  asm volatile("cp.async.wait_group 0;" ::: "memory")

__device__ __forceinline__ void mma16816(float* c, const uint32_t* a, const uint32_t* b){
    asm volatile("mma.sync.aligned.m16n8k16.row.col.f32.f16.f16.f32 "
        "{%0,%1,%2,%3}, {%4,%5,%6,%7}, {%8,%9}, {%0,%1,%2,%3};"
        : "+f"(c[0]), "+f"(c[1]), "+f"(c[2]), "+f"(c[3])
        : "r"(a[0]), "r"(a[1]), "r"(a[2]), "r"(a[3]), "r"(b[0]), "r"(b[1]));
}
__device__ __forceinline__ void ldsm4(uint32_t* r, uint32_t a){
    asm volatile("ldmatrix.sync.aligned.m8n8.x4.shared.b16 {%0,%1,%2,%3}, [%4];"
        : "=r"(r[0]), "=r"(r[1]), "=r"(r[2]), "=r"(r[3]) : "r"(a));
}
__device__ __forceinline__ void ldsm4t(uint32_t* r, uint32_t a){
    asm volatile("ldmatrix.sync.aligned.m8n8.x4.trans.shared.b16 {%0,%1,%2,%3}, [%4];"
        : "=r"(r[0]), "=r"(r[1]), "=r"(r[2]), "=r"(r[3]) : "r"(a));
}
__device__ __forceinline__ uint32_t packh2(float x, float y){
    __half2 h = __floats2half2_rn(x, y);
    return *reinterpret_cast<uint32_t*>(&h);
}
__device__ __forceinline__ uint32_t ex2x2(uint32_t h){
    uint32_t r;
    asm("ex2.approx.f16x2 %0, %1;" : "=r"(r) : "r"(h));
    return r;
}
__device__ __forceinline__ float sumh2(uint32_t h){
    __half2 v = *reinterpret_cast<__half2*>(&h);
    float2 f = __half22float2(v);
    return f.x + f.y;
}

// =======================================================================
// Fused prep: input converts (blocks 0..511) + weight transposes (512..1567)
// =======================================================================
__global__ __launch_bounds__(256) void prep_all(
    const float4* __restrict__ q, const float4* __restrict__ k, const float4* __restrict__ v,
    uint2* __restrict__ oq, uint2* __restrict__ ok, uint2* __restrict__ ov,
    const float* __restrict__ Wq, const float* __restrict__ Wk,
    const float* __restrict__ Wv, const float* __restrict__ Wo,
    __half* __restrict__ wqT, __half* __restrict__ wkT,
    __half* __restrict__ wvT, __half* __restrict__ woT)
{
    __shared__ float t[32][33];
    int id = blockIdx.x;
    if (id < 512) {
        int i = id * 256 + threadIdx.x;
        float4 f;
        f = q[i]; oq[i] = make_uint2(packh2(f.x, f.y), packh2(f.z, f.w));
        f = k[i]; ok[i] = make_uint2(packh2(f.x, f.y), packh2(f.z, f.w));
        f = v[i]; ov[i] = make_uint2(packh2(f.x, f.y), packh2(f.z, f.w));
        return;
    }
    id -= 512;
    const float* in; __half* out; int K, N, tile;
    if (id < 512)      { in = Wq; out = wqT; K = DHH; N = NQ;  tile = id; }
    else if (id < 528) { in = Wk; out = wkT; K = DHH; N = DHH; tile = id - 512; }
    else if (id < 544) { in = Wv; out = wvT; K = DHH; N = DHH; tile = id - 528; }
    else               { in = Wo; out = woT; K = NQ;  N = DHH; tile = id - 544; }
    int ntx = N / 32;
    int bx = (tile % ntx) * 32, by = (tile / ntx) * 32;
    int x = threadIdx.x & 31, y = threadIdx.x >> 5;
    #pragma unroll
    for (int i = 0; i < 4; ++i)
        t[y + 8*i][x] = in[(size_t)(by + y + 8*i)*N + bx + x];
    __syncthreads();
    #pragma unroll
    for (int i = 0; i < 4; ++i)
        out[(size_t)(bx + y + 8*i)*K + by + x] = __float2half_rn(t[x][y + 8*i]);
}

// =======================================================================
// Fused Q/K/V projections: one launch, flat grid of 1088 CTAs.
// =======================================================================
__global__ __launch_bounds__(256) void hgemm_qkv(
    const __half* __restrict__ xq, const __half* __restrict__ xk, const __half* __restrict__ xv,
    const __half* __restrict__ wqT, const __half* __restrict__ wkT, const __half* __restrict__ wvT,
    const float* __restrict__ b_q, const float* __restrict__ b_k, const float* __restrict__ b_v,
    __half* __restrict__ qh, __half* __restrict__ kh, __half* __restrict__ vh,
    float scl2)
{
    __shared__ __align__(16) __half As[2][128*40];
    __shared__ __align__(16) __half Bs[2][128*40];

    const int bid = blockIdx.x;
    const __half *A, *Bt; const float* bias; __half* C; int N, m0, n0; float scale;
    if (bid < 1024) {
        A = xq; Bt = wqT; bias = b_q; C = qh; N = NQ; scale = scl2;
        m0 = (bid >> 5) * 128; n0 = (bid & 31) * 128;
    } else if (bid < 1056) {
        A = xk; Bt = wkT; bias = b_k; C = kh; N = DHH; scale = 1.0f;
        m0 = (bid - 1024) * 128; n0 = 0;
    } else {
        A = xv; Bt = wvT; bias = b_v; C = vh; N = DHH; scale = 1.0f;
        m0 = (bid - 1056) * 128; n0 = 0;
    }

    const int tid = threadIdx.x, lane = tid & 31, w = tid >> 5;
    const int wm = (w >> 2) * 64, wn = (w & 3) * 32;
    const int g = lane >> 2, q4 = lane & 3;
    const int arow = ((lane >> 3) & 1) * 8 + (lane & 7);
    const int akse = (lane >> 4) * 8;
    const int brow = ((lane >> 4) & 1) * 8 + (lane & 7);
    const int bkse = ((lane >> 3) & 1) * 8;

    float acc[4][4][4] = {};

    auto load = [&](int kb, int st){
        #pragma unroll
        for (int i = 0; i < 2; ++i) {
            int e = tid + 256*i, r = e >> 2, c = e & 3;
            cp16(smem_u32(&As[st][r*40 + c*8]), A  + (size_t)(m0 + r)*DHH + kb*32 + c*8);
            cp16(smem_u32(&Bs[st][r*40 + c*8]), Bt + (size_t)(n0 + r)*DHH + kb*32 + c*8);
        }
    };
    load(0, 0); CP_COMMIT();

    #pragma unroll
    for (int kb = 0; kb < 4; ++kb) {
        if (kb + 1 < 4) { load(kb+1, (kb+1)&1); CP_COMMIT(); CP_WAIT1(); }
        else            { CP_WAIT0(); }
        __syncthreads();
        const int st = kb & 1;
        const uint32_t aB = smem_u32(&As[st][0]) + (wm + arow)*80 + akse*2;
        const uint32_t bB = smem_u32(&Bs[st][0]) + (wn + brow)*80 + bkse*2;
        #pragma unroll
        for (int ks = 0; ks < 2; ++ks) {
            uint32_t aF[4][4], bF[2][4];
            #pragma unroll
            for (int mi = 0; mi < 4; ++mi) ldsm4(aF[mi], aB + mi*16*80 + ks*32);
            #pragma unroll
            for (int np = 0; np < 2; ++np) ldsm4(bF[np], bB + np*16*80 + ks*32);
            #pragma unroll
            for (int mi = 0; mi < 4; ++mi)
                #pragma unroll
                for (int ni = 0; ni < 4; ++ni)
                    mma16816(acc[mi][ni], aF[mi], bF[ni>>1] + (ni&1)*2);
        }
        __syncthreads();
    }

    #pragma unroll
    for (int mi = 0; mi < 4; ++mi)
        #pragma unroll
        for (int ni = 0; ni < 4; ++ni) {
            int row = m0 + wm + mi*16 + g;
            int col = n0 + wn + ni*8 + 2*q4;
            float b0 = bias[col], b1 = bias[col+1];
            *reinterpret_cast<__half2*>(C + (size_t)row*N + col) =
                __floats2half2_rn((acc[mi][ni][0] + b0)*scale, (acc[mi][ni][1] + b1)*scale);
            *reinterpret_cast<__half2*>(C + (size_t)(row+8)*N + col) =
                __floats2half2_rn((acc[mi][ni][2] + b0)*scale, (acc[mi][ni][3] + b1)*scale);
        }
}

// ---- split-K hgemm + reduce (O projection), OSPLIT=16 ----
__global__ __launch_bounds__(256) void hgemm_splitk(
    const __half* __restrict__ A, const __half* __restrict__ Bt,
    float* __restrict__ part, int M, int N, int K)
{
    __shared__ __align__(16) __half As[2][128*40];
    __shared__ __align__(16) __half Bs[2][128*40];
    const int tid = threadIdx.x, lane = tid & 31, w = tid >> 5;
    const int wm = (w >> 2) * 64, wn = (w & 3) * 32;
    const int m0 = blockIdx.y * 128, n0 = blockIdx.x * 128;
    const int kc = blockIdx.z;
    const int g = lane >> 2, q4 = lane & 3;
    const int arow = ((lane >> 3) & 1) * 8 + (lane & 7);
    const int akse = (lane >> 4) * 8;
    const int brow = ((lane >> 4) & 1) * 8 + (lane & 7);
    const int bkse = ((lane >> 3) & 1) * 8;

    float acc[4][4][4] = {};
    const int nkpc = K / 32 / OSPLIT;
    const int kb0 = kc * nkpc;

    auto load = [&](int kb, int st){
        #pragma unroll
        for (int i = 0; i < 2; ++i) {
            int e = tid + 256*i, r = e >> 2, c = e & 3;
            cp16(smem_u32(&As[st][r*40 + c*8]), A  + (size_t)(m0 + r)*K + kb*32 + c*8);
            cp16(smem_u32(&Bs[st][r*40 + c*8]), Bt + (size_t)(n0 + r)*K + kb*32 + c*8);
        }
    };
    load(kb0, 0); CP_COMMIT();

    for (int i = 0; i < nkpc; ++i) {
        if (i + 1 < nkpc) { load(kb0+i+1, (i+1)&1); CP_COMMIT(); CP_WAIT1(); }
        else              { CP_WAIT0(); }
        __syncthreads();
        const int st = i & 1;
        const uint32_t aB = smem_u32(&As[st][0]) + (wm + arow)*80 + akse*2;
        const uint32_t bB = smem_u32(&Bs[st][0]) + (wn + brow)*80 + bkse*2;
        #pragma unroll
        for (int ks = 0; ks < 2; ++ks) {
            uint32_t aF[4][4], bF[2][4];
            #pragma unroll
            for (int mi = 0; mi < 4; ++mi) ldsm4(aF[mi], aB + mi*16*80 + ks*32);
            #pragma unroll
            for (int np = 0; np < 2; ++np) ldsm4(bF[np], bB + np*16*80 + ks*32);
            #pragma unroll
            for (int mi = 0; mi < 4; ++mi)
                #pragma unroll
                for (int ni = 0; ni < 4; ++ni)
                    mma16816(acc[mi][ni], aF[mi], bF[ni>>1] + (ni&1)*2);
        }
        __syncthreads();
    }

    float* P = part + (size_t)kc * M * N;
    #pragma unroll
    for (int mi = 0; mi < 4; ++mi)
        #pragma unroll
        for (int ni = 0; ni < 4; ++ni) {
            int row = m0 + wm + mi*16 + g;
            int col = n0 + wn + ni*8 + 2*q4;
            *reinterpret_cast<float2*>(P + (size_t)row*N + col)     = make_float2(acc[mi][ni][0], acc[mi][ni][1]);
            *reinterpret_cast<float2*>(P + (size_t)(row+8)*N + col) = make_float2(acc[mi][ni][2], acc[mi][ni][3]);
        }
}

__global__ void reduce_bias(const float* __restrict__ part, const float* __restrict__ bias,
                            float* __restrict__ out, int MN, int N)
{
    int i = (blockIdx.x * 256 + threadIdx.x) * 4;
    if (i >= MN) return;
    float4 s = *reinterpret_cast<const float4*>(part + i);
    #pragma unroll
    for (int kc = 1; kc < OSPLIT; ++kc) {
        float4 p = *reinterpret_cast<const float4*>(part + (size_t)kc*MN + i);
        s.x += p.x; s.y += p.y; s.z += p.z; s.w += p.w;
    }
    int c = i & (N - 1);
    s.x += bias[c]; s.y += bias[c+1]; s.z += bias[c+2]; s.w += bias[c+3];
    *reinterpret_cast<float4*>(out + i) = s;
}

// =======================================================================
// HMMA flash attention — 4 warps/CTA, M=32/warp, 2 CTAs/SM,
// rowsum moved off the tensor pipe (fp32 FADD on idle FMA pipe).
// =======================================================================
#define KROWB 272
#define KBYTES (64*KROWB)
#define BUF    (2*KBYTES)             // K+V one stage: 34816
#define QROWB  272
#define QROWS  128
#define QBYTES (QROWS*QROWB)          // 34816
#define SMEM_DYN (QBYTES + 2*BUF)     // 104448 -> 2 CTAs/SM

__device__ __forceinline__ void load_tile(uint32_t buf, int b, int kt,
    const __half* kh, const __half* vh, int tid)
{
    const __half* ks = kh + ((size_t)b*SS + (size_t)kt*TK) * DHH;
    const __half* vs = vh + ((size_t)b*SS + (size_t)kt*TK) * DHH;
    #pragma unroll
    for (int t = 0; t < 8; ++t) {
        int e = tid + t*128, r = e >> 4, c = e & 15;
        cp16(buf + r*KROWB + c*16,          ks + (size_t)r*DHH + c*8);
        cp16(buf + KBYTES + r*KROWB + c*16, vs + (size_t)r*DHH + c*8);
    }
}

__global__ __launch_bounds__(128, 2) void attn_hmma(
    const __half* __restrict__ qh, const __half* __restrict__ kh,
    const __half* __restrict__ vh, __half* __restrict__ o2h)
{
    extern __shared__ __align__(16) char smraw[];
    const uint32_t smb = smem_u32(smraw);
    const uint32_t kvb = smb + QBYTES;
    const int qb = blockIdx.x, h = blockIdx.y, b = blockIdx.z;
    const int tid = threadIdx.x, w = tid >> 5, lane = tid & 31;
    const int g = lane >> 2, q4 = lane & 3;
    const int jrow = ((lane >> 4) & 1) * 8 + (lane & 7);
    const int ksel = ((lane >> 3) & 1) * 8;
    const int arow = ((lane >> 3) & 1) * 8 + (lane & 7);
    const int akse = (lane >> 4) * 8;
    const int vrow = lane & 15;
    const int vcol8 = (lane >> 4) * 8;

    {
        const __half* qsrc = qh + ((size_t)b*SS + (size_t)h*64 + (size_t)qb*4) * NQ;
        #pragma unroll
        for (int t = 0; t < 16; ++t) {
            int e = tid + t*128, r = e >> 4, c = e & 15;
            cp16(smb + r*QROWB + c*16, qsrc + (size_t)r*DHH + c*8);
        }
    }
    load_tile(kvb, b, 0, kh, vh, tid);
    CP_COMMIT();
    load_tile(kvb + BUF, b, 1, kh, vh, tid);
    CP_COMMIT();

    float o[2][16][4];
    #pragma unroll
    for (int m = 0; m < 2; ++m)
        #pragma unroll
        for (int n = 0; n < 16; ++n)
            #pragma unroll
            for (int i = 0; i < 4; ++i) o[m][n][i] = 0.f;
    float rs[2][2] = {};                       // [m][row g / g+8], per-lane partial
    const uint32_t Qb = smb + (w*32 + arow)*QROWB + akse*2;

    for (int kt = 0; kt < NT; ++kt) {
        if (kt + 1 < NT) { CP_WAIT1(); } else { CP_WAIT0(); }
        __syncthreads();

        const uint32_t Kb = kvb + (uint32_t)(kt&1)*BUF + jrow*KROWB + ksel*2;
        const uint32_t Vb = kvb + (uint32_t)(kt&1)*BUF + KBYTES + vrow*KROWB + vcol8*2;

        // S = Q K^T for both m-tiles (K fragments shared)
        float s[2][8][4];
        #pragma unroll
        for (int m = 0; m < 2; ++m)
            #pragma unroll
            for (int j = 0; j < 8; ++j)
                #pragma unroll
                for (int i = 0; i < 4; ++i) s[m][j][i] = 0.f;
        #pragma unroll
        for (int ks = 0; ks < 8; ++ks) {
            uint32_t aF0[4], aF1[4];
            ldsm4(aF0, Qb + 32*ks);
            ldsm4(aF1, Qb + 16*QROWB + 32*ks);
            uint32_t bb[2][4];
            ldsm4(bb[0], Kb + 32*ks);
            #pragma unroll
            for (int jp = 0; jp < 4; ++jp) {
                if (jp < 3) ldsm4(bb[(jp+1)&1], Kb + (jp+1)*16*KROWB + 32*ks);
                mma16816(s[0][2*jp],   aF0, bb[jp&1]);
                mma16816(s[0][2*jp+1], aF0, bb[jp&1] + 2);
                mma16816(s[1][2*jp],   aF1, bb[jp&1]);
                mma16816(s[1][2*jp+1], aF1, bb[jp&1] + 2);
            }
        }

        // P = 2^S (fp16x2 MUFU); rowsum accumulated in fp32 on FMA pipe
        uint32_t P[2][4][4];
        #pragma unroll
        for (int m = 0; m < 2; ++m)
            #pragma unroll
            for (int j = 0; j < 8; ++j) {
                uint32_t p0 = ex2x2(packh2(s[m][j][0], s[m][j][1]));  // row g
                uint32_t p1 = ex2x2(packh2(s[m][j][2], s[m][j][3]));  // row g+8
                P[m][j>>1][(j&1)*2]     = p0;
                P[m][j>>1][(j&1)*2 + 1] = p1;
                rs[m][0] += sumh2(p0);
                rs[m][1] += sumh2(p1);
            }

        // O += P V (no more rowsum MMAs on the tensor pipe)
        #pragma unroll
        for (int ks = 0; ks < 4; ++ks) {
            const uint32_t Vk = Vb + ks*16*KROWB;
            uint32_t bb[2][4];
            ldsm4t(bb[0], Vk);
            #pragma unroll
            for (int np = 0; np < 8; ++np) {
                if (np < 7) ldsm4t(bb[(np+1)&1], Vk + (np+1)*32);
                mma16816(o[0][2*np],   P[0][ks], bb[np&1]);
                mma16816(o[0][2*np+1], P[0][ks], bb[np&1] + 2);
                mma16816(o[1][2*np],   P[1][ks], bb[np&1]);
                mma16816(o[1][2*np+1], P[1][ks], bb[np&1] + 2);
            }
        }

        __syncthreads();
        if (kt + 2 < NT) {
            load_tile(kvb + (uint32_t)(kt&1)*BUF, b, kt+2, kh, vh, tid);
            CP_COMMIT();
        }
    }

    // cross-lane rowsum reduce (4 lanes per row share q4 bits 0..1)
    #pragma unroll
    for (int m = 0; m < 2; ++m)
        #pragma unroll
        for (int r = 0; r < 2; ++r) {
            rs[m][r] += __shfl_xor_sync(0xffffffffu, rs[m][r], 1);
            rs[m][r] += __shfl_xor_sync(0xffffffffu, rs[m][r], 2);
        }

    // epilogue: rows = qb*128 + w*32 + m*16 + {g, g+8}
    #pragma unroll
    for (int m = 0; m < 2; ++m) {
        const float inv0 = 1.0f / rs[m][0], inv1 = 1.0f / rs[m][1];
        const int lr = w*32 + m*16 + g;
        __half* dst0 = o2h + ((size_t)b*SS + (size_t)qb*QROWS + lr)     * NQ + (size_t)h * DHH;
        __half* dst1 = o2h + ((size_t)b*SS + (size_t)qb*QROWS + lr + 8) * NQ + (size_t)h * DHH;
        #pragma unroll
        for (int n = 0; n < 16; ++n) {
            int c = 8*n + 2*q4;
            *reinterpret_cast<__half2*>(dst0 + c) = __floats2half2_rn(o[m][n][0]*inv0, o[m][n][1]*inv0);
            *reinterpret_cast<__half2*>(dst1 + c) = __floats2half2_rn(o[m][n][2]*inv1, o[m][n][3]*inv1);
        }
    }
}

// ---------------------------------------------------------------------------
extern "C" void kernel_launch(void* const* d_in, const int* in_sizes, int n_in,
                              void* d_out, int out_size)
{
    const float* query  = (const float*)d_in[0];
    const float* key    = (const float*)d_in[1];
    const float* values = (const float*)d_in[2];
    const float* W_q = (const float*)d_in[3];
    const float* b_q = (const float*)d_in[4];
    const float* W_k = (const float*)d_in[5];
    const float* b_k = (const float*)d_in[6];
    const float* W_v = (const float*)d_in[7];
    const float* b_v = (const float*)d_in[8];
    const float* W_o = (const float*)d_in[9];
    const float* b_o = (const float*)d_in[10];
    float* out = (float*)d_out;

    float *pp;
    __half *xh, *xkh, *xvh, *wqT, *wkT, *wvT, *woT, *qhp, *khp, *vhp, *ah;
    cudaGetSymbolAddress((void**)&pp,  g_part);
    cudaGetSymbolAddress((void**)&xh,  g_xh);
    cudaGetSymbolAddress((void**)&xkh, g_xkh);
    cudaGetSymbolAddress((void**)&xvh, g_xvh);
    cudaGetSymbolAddress((void**)&wqT, g_wqT);
    cudaGetSymbolAddress((void**)&wkT, g_wkT);
    cudaGetSymbolAddress((void**)&wvT, g_wvT);
    cudaGetSymbolAddress((void**)&woT, g_woT);
    cudaGetSymbolAddress((void**)&qhp, g_qh);
    cudaGetSymbolAddress((void**)&khp, g_kh);
    cudaGetSymbolAddress((void**)&vhp, g_vh);
    cudaGetSymbolAddress((void**)&ah,  g_attnh);

    cudaFuncSetAttribute(attn_hmma, cudaFuncAttributeMaxDynamicSharedMemorySize, SMEM_DYN);

    const float scl2 = 0.12753102189093095f;   // log2(e)/sqrt(128)

    // launch 0: fused converts + weight transposes
    prep_all<<<1568, 256>>>(
        (const float4*)query, (const float4*)key, (const float4*)values,
        (uint2*)xh, (uint2*)xkh, (uint2*)xvh,
        W_q, W_k, W_v, W_o, wqT, wkT, wvT, woT);

    // launch 1: all three projections in one grid
    hgemm_qkv<<<1088, 256>>>(xh, xkh, xvh, wqT, wkT, wvT,
                             b_q, b_k, b_v, qhp, khp, vhp, scl2);

    // launch 2: attention — 1024 CTAs of 128 threads, 2 CTAs/SM
    attn_hmma<<<dim3(SS/QROWS, HH, BB), 128, SMEM_DYN>>>(qhp, khp, vhp, ah);

    // launches 3-4: O projection (OSPLIT=16 for occupancy)
    hgemm_splitk<<<dim3(DHH/128, BSZ/128, OSPLIT), 256>>>(ah, woT, pp, BSZ, DHH, NQ);
    reduce_bias<<<(BSZ*DHH/4 + 255)/256, 256>>>(pp, b_o, out, BSZ*DHH, DHH);
}